// round 3
// baseline (speedup 1.0000x reference)
#include <cuda_runtime.h>
#include <math.h>

#define NNODES 50000
#define NEDGE  800000
#define NTOT   (NEDGE + NNODES)
#define DIN    1024
#define HID    128
#define C1     256   // HEADS*HID
#define NC     4

// ---------------- scratch (device globals; no allocation allowed) ----------------
__device__ float g_hpre[(size_t)NNODES * HID];    // relu(x@W_pre+b)        25.6 MB
__device__ float g_h1[(size_t)NNODES * C1];       // hpre@W1                51.2 MB
__device__ float g_h1out[(size_t)NNODES * C1];    // after GAT1 + ELU       51.2 MB
__device__ float g_asrc1[NNODES * 2];
__device__ float g_adst1[NNODES * 2];
__device__ float g_h2[NNODES * NC];
__device__ float g_asrc2[NNODES];
__device__ float g_adst2[NNODES];
__device__ int   g_cnt[NNODES];                   // counts, then scatter cursor
__device__ int   g_off[NNODES + 1];
__device__ int   g_esrc[NTOT];                    // CSR (by dst): src node ids

__device__ __forceinline__ int clampN(int v) {
    return v < 0 ? 0 : (v >= NNODES ? NNODES - 1 : v);
}

// ---------------- CSR build ----------------
__global__ void k_init_counts() {
    int i = blockIdx.x * blockDim.x + threadIdx.x;
    if (i < NNODES) g_cnt[i] = 1;   // self-loop pre-count
}

// edge_index is int32 ([2,E] row-major: src row then dst row)
__global__ void k_count(const int* __restrict__ ei) {
    int e = blockIdx.x * blockDim.x + threadIdx.x;
    if (e < NEDGE) {
        int dst = clampN(ei[NEDGE + e]);
        atomicAdd(&g_cnt[dst], 1);
    }
}

// single-block scan over 50000 counts -> exclusive offsets; zeroes g_cnt (cursor)
__global__ void k_scan() {
    __shared__ int wsum[32];
    __shared__ int running;
    int tid = threadIdx.x, lane = tid & 31, w = tid >> 5;
    if (tid == 0) running = 0;
    __syncthreads();
    for (int base = 0; base < NNODES; base += 1024) {
        int i = base + tid;
        int v = (i < NNODES) ? g_cnt[i] : 0;
        if (i < NNODES) g_cnt[i] = 0;
        int x = v;
        #pragma unroll
        for (int o = 1; o < 32; o <<= 1) {
            int t = __shfl_up_sync(0xffffffffu, x, o);
            if (lane >= o) x += t;
        }
        if (lane == 31) wsum[w] = x;
        __syncthreads();
        if (w == 0) {
            int s = wsum[lane];
            #pragma unroll
            for (int o = 1; o < 32; o <<= 1) {
                int t = __shfl_up_sync(0xffffffffu, s, o);
                if (lane >= o) s += t;
            }
            wsum[lane] = s;
        }
        __syncthreads();
        int warpPrefix = (w > 0) ? wsum[w - 1] : 0;
        int total = wsum[31];
        int r = running;
        if (i < NNODES) g_off[i] = r + warpPrefix + (x - v);
        __syncthreads();
        if (tid == 0) running += total;
        __syncthreads();
    }
    if (threadIdx.x == 0) g_off[NNODES] = running;
}

__global__ void k_scatter(const int* __restrict__ ei) {
    int e = blockIdx.x * blockDim.x + threadIdx.x;
    if (e >= NTOT) return;
    int src, dst;
    if (e < NEDGE) { src = clampN(ei[e]); dst = clampN(ei[NEDGE + e]); }
    else           { src = e - NEDGE; dst = src; }
    int pos = g_off[dst] + atomicAdd(&g_cnt[dst], 1);
    g_esrc[pos] = src;
}

// ---------------- SGEMM 128x128x8, fp32, optional bias+relu ----------------
// C[M,N] = A[M,K] @ B[K,N]; N must be multiple of 128 (128 or 256 here)
__device__ __forceinline__ void sgemm_tile(
    const float* __restrict__ A, const float* __restrict__ B,
    const float* __restrict__ bias, float* __restrict__ C,
    int M, int N, int K, int doRelu)
{
    __shared__ float As[8][128];
    __shared__ float Bs[8][128];
    int tid = threadIdx.x;
    int colBase = blockIdx.x * 128;
    int rowBase = blockIdx.y * 128;
    int aRow = tid >> 1, aCol = (tid & 1) * 4;
    int bRow = tid >> 5, bCol = (tid & 31) * 4;
    int ty = tid >> 4, tx = tid & 15;

    float acc[8][8];
    #pragma unroll
    for (int m = 0; m < 8; m++)
        #pragma unroll
        for (int n = 0; n < 8; n++) acc[m][n] = 0.f;

    const float* Ap = A + (size_t)(rowBase + aRow) * K + aCol;
    const float* Bp = B + (size_t)bRow * N + colBase + bCol;
    bool aValid = (rowBase + aRow) < M;

    for (int k0 = 0; k0 < K; k0 += 8) {
        float4 av = aValid ? *(const float4*)Ap : make_float4(0.f, 0.f, 0.f, 0.f);
        As[aCol + 0][aRow] = av.x;
        As[aCol + 1][aRow] = av.y;
        As[aCol + 2][aRow] = av.z;
        As[aCol + 3][aRow] = av.w;
        *(float4*)&Bs[bRow][bCol] = *(const float4*)Bp;
        __syncthreads();
        #pragma unroll
        for (int k = 0; k < 8; k++) {
            float4 a0 = *(const float4*)&As[k][ty * 8];
            float4 a1 = *(const float4*)&As[k][ty * 8 + 4];
            float4 b0 = *(const float4*)&Bs[k][tx * 8];
            float4 b1 = *(const float4*)&Bs[k][tx * 8 + 4];
            float ra[8] = {a0.x, a0.y, a0.z, a0.w, a1.x, a1.y, a1.z, a1.w};
            float rb[8] = {b0.x, b0.y, b0.z, b0.w, b1.x, b1.y, b1.z, b1.w};
            #pragma unroll
            for (int m = 0; m < 8; m++)
                #pragma unroll
                for (int n = 0; n < 8; n++)
                    acc[m][n] += ra[m] * rb[n];
        }
        __syncthreads();
        Ap += 8;
        Bp += 8 * N;
    }

    #pragma unroll
    for (int m = 0; m < 8; m++) {
        int r = rowBase + ty * 8 + m;
        if (r < M) {
            #pragma unroll
            for (int n = 0; n < 8; n += 4) {
                int c = colBase + tx * 8 + n;
                float4 v;
                v.x = acc[m][n + 0]; v.y = acc[m][n + 1];
                v.z = acc[m][n + 2]; v.w = acc[m][n + 3];
                if (bias) {
                    v.x += bias[c + 0]; v.y += bias[c + 1];
                    v.z += bias[c + 2]; v.w += bias[c + 3];
                }
                if (doRelu) {
                    v.x = fmaxf(v.x, 0.f); v.y = fmaxf(v.y, 0.f);
                    v.z = fmaxf(v.z, 0.f); v.w = fmaxf(v.w, 0.f);
                }
                *(float4*)&C[(size_t)r * N + c] = v;
            }
        }
    }
}

// wrappers bind scratch symbols in DEVICE code (no host symbol-address API)
__global__ void __launch_bounds__(256, 2)
k_gemm_pre(const float* __restrict__ x, const float* __restrict__ W_pre,
           const float* __restrict__ b_pre)
{
    sgemm_tile(x, W_pre, b_pre, g_hpre, NNODES, HID, DIN, 1);
}

__global__ void __launch_bounds__(256, 2)
k_gemm_h1(const float* __restrict__ W1)
{
    sgemm_tile(g_hpre, W1, nullptr, g_h1, NNODES, C1, HID, 0);
}

// ---------------- alpha for layer 1: per-node dots with a_src1/a_dst1 ----------------
// a_src1/a_dst1 are [2,128] row-major -> flat index == channel index of h1 row.
__global__ void k_alpha1(const float* __restrict__ a_src1, const float* __restrict__ a_dst1) {
    int node = blockIdx.x * 8 + (threadIdx.x >> 5);
    int lane = threadIdx.x & 31;
    const float* hrow = &g_h1[(size_t)node * C1];
    float s0 = 0.f, s1 = 0.f, d0 = 0.f, d1 = 0.f;
    #pragma unroll
    for (int k = 0; k < 8; k++) {
        int c = lane + 32 * k;
        float v = hrow[c];
        float as = a_src1[c], ad = a_dst1[c];
        if (k < 4) { s0 += v * as; d0 += v * ad; }
        else       { s1 += v * as; d1 += v * ad; }
    }
    #pragma unroll
    for (int o = 16; o; o >>= 1) {
        s0 += __shfl_xor_sync(0xffffffffu, s0, o);
        s1 += __shfl_xor_sync(0xffffffffu, s1, o);
        d0 += __shfl_xor_sync(0xffffffffu, d0, o);
        d1 += __shfl_xor_sync(0xffffffffu, d1, o);
    }
    if (lane == 0) {
        g_asrc1[node * 2 + 0] = s0; g_asrc1[node * 2 + 1] = s1;
        g_adst1[node * 2 + 0] = d0; g_adst1[node * 2 + 1] = d1;
    }
}

__device__ __forceinline__ float lrelu(float e) { return e > 0.f ? e : 0.2f * e; }

// ---------------- GAT1 aggregation: one warp per dst node, 2-pass softmax ----------------
__global__ void k_agg1(const float* __restrict__ b1) {
    int node = blockIdx.x * 8 + (threadIdx.x >> 5);
    int lane = threadIdx.x & 31;
    int beg = g_off[node], end = g_off[node + 1];
    float ad0 = g_adst1[node * 2 + 0], ad1 = g_adst1[node * 2 + 1];

    // pass 1: max over incoming edges per head
    float m0 = -1e30f, m1 = -1e30f;
    for (int j = beg + lane; j < end; j += 32) {
        int s = g_esrc[j];
        m0 = fmaxf(m0, lrelu(g_asrc1[s * 2 + 0] + ad0));
        m1 = fmaxf(m1, lrelu(g_asrc1[s * 2 + 1] + ad1));
    }
    #pragma unroll
    for (int o = 16; o; o >>= 1) {
        m0 = fmaxf(m0, __shfl_xor_sync(0xffffffffu, m0, o));
        m1 = fmaxf(m1, __shfl_xor_sync(0xffffffffu, m1, o));
    }

    // pass 2: exp-sum + weighted feature accumulation (whole warp per edge)
    float acc[8];
    #pragma unroll
    for (int k = 0; k < 8; k++) acc[k] = 0.f;
    float s0 = 0.f, s1 = 0.f;
    for (int j = beg; j < end; j++) {
        int s = g_esrc[j];
        float p0 = expf(lrelu(g_asrc1[s * 2 + 0] + ad0) - m0);
        float p1 = expf(lrelu(g_asrc1[s * 2 + 1] + ad1) - m1);
        s0 += p0; s1 += p1;
        const float* hrow = &g_h1[(size_t)s * C1];
        #pragma unroll
        for (int k = 0; k < 8; k++) {
            float v = hrow[lane + 32 * k];
            acc[k] += v * (k < 4 ? p0 : p1);
        }
    }
    float inv0 = 1.f / (s0 + 1e-16f), inv1 = 1.f / (s1 + 1e-16f);
    float* orow = &g_h1out[(size_t)node * C1];
    #pragma unroll
    for (int k = 0; k < 8; k++) {
        int c = lane + 32 * k;
        float o = acc[k] * (k < 4 ? inv0 : inv1) + b1[c];
        orow[c] = (o > 0.f) ? o : expm1f(o);   // ELU
    }
}

// ---------------- layer 2 feature transform + alpha (fused, warp per node) ----------------
__global__ void k_gemm2(const float* __restrict__ W2, const float* __restrict__ a_src2,
                        const float* __restrict__ a_dst2) {
    __shared__ float sW[C1 * NC];
    __shared__ float sa[NC], sd[NC];
    int tid = threadIdx.x;
    *(float4*)&sW[tid * 4] = *(const float4*)&W2[tid * 4];
    if (tid < NC) { sa[tid] = a_src2[tid]; sd[tid] = a_dst2[tid]; }
    __syncthreads();

    int node = blockIdx.x * 8 + (tid >> 5);
    int lane = tid & 31;
    const float* hrow = &g_h1out[(size_t)node * C1];
    float a0 = 0.f, a1 = 0.f, a2 = 0.f, a3 = 0.f;
    #pragma unroll
    for (int k = 0; k < 8; k++) {
        int c = lane + 32 * k;
        float v = hrow[c];
        a0 += v * sW[c * 4 + 0];
        a1 += v * sW[c * 4 + 1];
        a2 += v * sW[c * 4 + 2];
        a3 += v * sW[c * 4 + 3];
    }
    #pragma unroll
    for (int o = 16; o; o >>= 1) {
        a0 += __shfl_xor_sync(0xffffffffu, a0, o);
        a1 += __shfl_xor_sync(0xffffffffu, a1, o);
        a2 += __shfl_xor_sync(0xffffffffu, a2, o);
        a3 += __shfl_xor_sync(0xffffffffu, a3, o);
    }
    if (lane == 0) {
        g_h2[node * 4 + 0] = a0; g_h2[node * 4 + 1] = a1;
        g_h2[node * 4 + 2] = a2; g_h2[node * 4 + 3] = a3;
        g_asrc2[node] = a0 * sa[0] + a1 * sa[1] + a2 * sa[2] + a3 * sa[3];
        g_adst2[node] = a0 * sd[0] + a1 * sd[1] + a2 * sd[2] + a3 * sd[3];
    }
}

// ---------------- GAT2 aggregation (heads=1, C=4), warp per node ----------------
__global__ void k_agg2(const float* __restrict__ b2, float* __restrict__ out) {
    int node = blockIdx.x * 8 + (threadIdx.x >> 5);
    int lane = threadIdx.x & 31;
    int beg = g_off[node], end = g_off[node + 1];
    float ad = g_adst2[node];

    float m = -1e30f;
    for (int j = beg + lane; j < end; j += 32)
        m = fmaxf(m, lrelu(g_asrc2[g_esrc[j]] + ad));
    #pragma unroll
    for (int o = 16; o; o >>= 1)
        m = fmaxf(m, __shfl_xor_sync(0xffffffffu, m, o));

    float ss = 0.f, c0 = 0.f, c1 = 0.f, c2 = 0.f, c3 = 0.f;
    for (int j = beg + lane; j < end; j += 32) {
        int s = g_esrc[j];
        float p = expf(lrelu(g_asrc2[s] + ad) - m);
        ss += p;
        c0 += g_h2[s * 4 + 0] * p;
        c1 += g_h2[s * 4 + 1] * p;
        c2 += g_h2[s * 4 + 2] * p;
        c3 += g_h2[s * 4 + 3] * p;
    }
    #pragma unroll
    for (int o = 16; o; o >>= 1) {
        ss += __shfl_xor_sync(0xffffffffu, ss, o);
        c0 += __shfl_xor_sync(0xffffffffu, c0, o);
        c1 += __shfl_xor_sync(0xffffffffu, c1, o);
        c2 += __shfl_xor_sync(0xffffffffu, c2, o);
        c3 += __shfl_xor_sync(0xffffffffu, c3, o);
    }
    if (lane == 0) {
        float inv = 1.f / (ss + 1e-16f);
        out[node * 4 + 0] = c0 * inv + b2[0];
        out[node * 4 + 1] = c1 * inv + b2[1];
        out[node * 4 + 2] = c2 * inv + b2[2];
        out[node * 4 + 3] = c3 * inv + b2[3];
    }
}

// ---------------- launch ----------------
extern "C" void kernel_launch(void* const* d_in, const int* in_sizes, int n_in,
                              void* d_out, int out_size) {
    const float* x      = (const float*)d_in[0];
    const int*   ei     = (const int*)d_in[1];     // int32 (JAX default: x64 disabled)
    const float* W_pre  = (const float*)d_in[2];
    const float* b_pre  = (const float*)d_in[3];
    const float* W1     = (const float*)d_in[4];
    const float* a_src1 = (const float*)d_in[5];
    const float* a_dst1 = (const float*)d_in[6];
    const float* b1     = (const float*)d_in[7];
    const float* W2     = (const float*)d_in[8];
    const float* a_src2 = (const float*)d_in[9];
    const float* a_dst2 = (const float*)d_in[10];
    const float* b2     = (const float*)d_in[11];
    float* out = (float*)d_out;

    // CSR build (self-loops included)
    k_init_counts<<<(NNODES + 255) / 256, 256>>>();
    k_count<<<(NEDGE + 255) / 256, 256>>>(ei);
    k_scan<<<1, 1024>>>();
    k_scatter<<<(NTOT + 255) / 256, 256>>>(ei);

    // h_pre = relu(x @ W_pre + b_pre)   [50000,1024]@[1024,128]
    {
        dim3 grid(1, (NNODES + 127) / 128);
        k_gemm_pre<<<grid, 256>>>(x, W_pre, b_pre);
    }
    // h1 = h_pre @ W1                   [50000,128]@[128,256]
    {
        dim3 grid(2, (NNODES + 127) / 128);
        k_gemm_h1<<<grid, 256>>>(W1);
    }
    k_alpha1<<<NNODES / 8, 256>>>(a_src1, a_dst1);
    k_agg1<<<NNODES / 8, 256>>>(b1);
    k_gemm2<<<NNODES / 8, 256>>>(W2, a_src2, a_dst2);
    k_agg2<<<NNODES / 8, 256>>>(b2, out);
}

// round 4
// speedup vs baseline: 1.9270x; 1.9270x over previous
#include <cuda_runtime.h>
#include <cuda_bf16.h>
#include <math.h>
#include <stdint.h>

#define NNODES 50000
#define NEDGE  800000
#define NTOT   (NEDGE + NNODES)
#define DIN    1024
#define HID    128
#define C1     256   // HEADS*HID
#define NC     4

// ---------------- scratch (device globals; no allocation allowed) ----------------
__device__ float g_hpre[(size_t)NNODES * HID];    // relu(x@W_pre+b)        25.6 MB
__device__ float g_h1[(size_t)NNODES * C1];       // hpre@W1                51.2 MB
__device__ float g_h1out[(size_t)NNODES * C1];    // after GAT1 + ELU       51.2 MB
__device__ float g_asrc1[NNODES * 2];
__device__ float g_adst1[NNODES * 2];
__device__ float g_h2[NNODES * NC];
__device__ float g_asrc2[NNODES];
__device__ float g_adst2[NNODES];
__device__ int   g_cnt[NNODES];                   // counts, then scatter cursor
__device__ int   g_off[NNODES + 1];
__device__ int   g_esrc[NTOT];                    // CSR (by dst): src node ids

__device__ __forceinline__ int clampN(int v) {
    return v < 0 ? 0 : (v >= NNODES ? NNODES - 1 : v);
}

// ---------------- CSR build ----------------
__global__ void k_init_counts() {
    int i = blockIdx.x * blockDim.x + threadIdx.x;
    if (i < NNODES) g_cnt[i] = 1;   // self-loop pre-count
}

__global__ void k_count(const int* __restrict__ ei) {
    int e = blockIdx.x * blockDim.x + threadIdx.x;
    if (e < NEDGE) {
        int dst = clampN(ei[NEDGE + e]);
        atomicAdd(&g_cnt[dst], 1);
    }
}

__global__ void k_scan() {
    __shared__ int wsum[32];
    __shared__ int running;
    int tid = threadIdx.x, lane = tid & 31, w = tid >> 5;
    if (tid == 0) running = 0;
    __syncthreads();
    for (int base = 0; base < NNODES; base += 1024) {
        int i = base + tid;
        int v = (i < NNODES) ? g_cnt[i] : 0;
        if (i < NNODES) g_cnt[i] = 0;
        int x = v;
        #pragma unroll
        for (int o = 1; o < 32; o <<= 1) {
            int t = __shfl_up_sync(0xffffffffu, x, o);
            if (lane >= o) x += t;
        }
        if (lane == 31) wsum[w] = x;
        __syncthreads();
        if (w == 0) {
            int s = wsum[lane];
            #pragma unroll
            for (int o = 1; o < 32; o <<= 1) {
                int t = __shfl_up_sync(0xffffffffu, s, o);
                if (lane >= o) s += t;
            }
            wsum[lane] = s;
        }
        __syncthreads();
        int warpPrefix = (w > 0) ? wsum[w - 1] : 0;
        int total = wsum[31];
        int r = running;
        if (i < NNODES) g_off[i] = r + warpPrefix + (x - v);
        __syncthreads();
        if (tid == 0) running += total;
        __syncthreads();
    }
    if (threadIdx.x == 0) g_off[NNODES] = running;
}

__global__ void k_scatter(const int* __restrict__ ei) {
    int e = blockIdx.x * blockDim.x + threadIdx.x;
    if (e >= NTOT) return;
    int src, dst;
    if (e < NEDGE) { src = clampN(ei[e]); dst = clampN(ei[NEDGE + e]); }
    else           { src = e - NEDGE; dst = src; }
    int pos = g_off[dst] + atomicAdd(&g_cnt[dst], 1);
    g_esrc[pos] = src;
}

// ============== split-bf16 tensor-core GEMM =================================
// C[M,N] = A[M,K] @ B[K,N] in ~fp32 precision via 3-term bf16 mma:
//   A = Ah + Al, B = Bh + Bl (bf16 splits); C += Ah*Bh + Ah*Bl + Al*Bh
// CTA 128x128x32, 8 warps (4x2), warp tile 32x64, mma.m16n8k16.

__device__ __forceinline__ uint32_t packbf(float v0, float v1) {
    // bf16x2: low half = v0, high half = v1
    uint32_t r;
    asm("cvt.rn.bf16x2.f32 %0, %1, %2;" : "=r"(r) : "f"(v1), "f"(v0));
    return r;
}
__device__ __forceinline__ float bflowf(uint32_t p)  { return __uint_as_float(p << 16); }
__device__ __forceinline__ float bfhighf(uint32_t p) { return __uint_as_float(p & 0xffff0000u); }

__device__ __forceinline__ void ldsm4(uint32_t addr, uint32_t* r) {
    asm volatile("ldmatrix.sync.aligned.m8n8.x4.shared.b16 {%0,%1,%2,%3},[%4];"
        : "=r"(r[0]), "=r"(r[1]), "=r"(r[2]), "=r"(r[3]) : "r"(addr));
}
__device__ __forceinline__ void ldsm4t(uint32_t addr, uint32_t* r) {
    asm volatile("ldmatrix.sync.aligned.m8n8.x4.trans.shared.b16 {%0,%1,%2,%3},[%4];"
        : "=r"(r[0]), "=r"(r[1]), "=r"(r[2]), "=r"(r[3]) : "r"(addr));
}
__device__ __forceinline__ void mma16816(float* c, const uint32_t* a, const uint32_t* b) {
    asm volatile(
        "mma.sync.aligned.m16n8k16.row.col.f32.bf16.bf16.f32 "
        "{%0,%1,%2,%3},{%4,%5,%6,%7},{%8,%9},{%0,%1,%2,%3};"
        : "+f"(c[0]), "+f"(c[1]), "+f"(c[2]), "+f"(c[3])
        : "r"(a[0]), "r"(a[1]), "r"(a[2]), "r"(a[3]), "r"(b[0]), "r"(b[1]));
}

// convert 8 floats (2x float4) -> 4 u32 hi + 4 u32 lo
__device__ __forceinline__ void cvt_chunk(float4 x, float4 y, uint32_t* h, uint32_t* l) {
    h[0] = packbf(x.x, x.y); h[1] = packbf(x.z, x.w);
    h[2] = packbf(y.x, y.y); h[3] = packbf(y.z, y.w);
    l[0] = packbf(x.x - bflowf(h[0]), x.y - bfhighf(h[0]));
    l[1] = packbf(x.z - bflowf(h[1]), x.w - bfhighf(h[1]));
    l[2] = packbf(y.x - bflowf(h[2]), y.y - bfhighf(h[2]));
    l[3] = packbf(y.z - bflowf(h[3]), y.w - bfhighf(h[3]));
}

__device__ __forceinline__ void gemm_bf16s(
    const float* __restrict__ A, const float* __restrict__ B,
    const float* __restrict__ bias, float* __restrict__ C,
    int M, int N, int K, int doRelu)
{
    // smem: A planes 128 rows x 64B; B planes 32 rows x 256B (each 8KB)
    __shared__ __align__(16) uint32_t sAh[2048], sAl[2048], sBh[2048], sBl[2048];
    const uint32_t aHi = (uint32_t)__cvta_generic_to_shared(sAh);
    const uint32_t aLo = (uint32_t)__cvta_generic_to_shared(sAl);
    const uint32_t bHi = (uint32_t)__cvta_generic_to_shared(sBh);
    const uint32_t bLo = (uint32_t)__cvta_generic_to_shared(sBl);

    const int tid = threadIdx.x;
    const int lane = tid & 31;
    const int warp = tid >> 5;
    const int warpM = (warp & 3) * 32;   // 4 m-groups
    const int warpN = (warp >> 2) * 64;  // 2 n-groups
    const int rowBase = blockIdx.y * 128;
    const int colBase = blockIdx.x * 128;

    // A staging role: row m = tid>>1, k-half = (tid&1)*16 (chunks (tid&1)*2, +1)
    const int am = tid >> 1;
    const int akoff = (tid & 1) * 16;
    // B staging role: row k = tid>>3, n-offset = (tid&7)*16 (chunks (tid&7)*2, +1)
    const int bk = tid >> 3;
    const int bnoff = (tid & 7) * 16;

    float acc[2][8][4];
    #pragma unroll
    for (int mi = 0; mi < 2; mi++)
        #pragma unroll
        for (int j = 0; j < 8; j++)
            #pragma unroll
            for (int q = 0; q < 4; q++) acc[mi][j][q] = 0.f;

    const int niter = K >> 5;

    float4 ra[4], rb[4];
    // ---- load tile 0 ----
    {
        int gm = rowBase + am;
        if (gm < M) {
            const float4* p = (const float4*)(A + (size_t)gm * K + akoff);
            ra[0] = p[0]; ra[1] = p[1]; ra[2] = p[2]; ra[3] = p[3];
        } else {
            ra[0] = ra[1] = ra[2] = ra[3] = make_float4(0.f, 0.f, 0.f, 0.f);
        }
        const float4* p = (const float4*)(B + (size_t)bk * N + colBase + bnoff);
        rb[0] = p[0]; rb[1] = p[1]; rb[2] = p[2]; rb[3] = p[3];
    }

    for (int it = 0; it < niter; it++) {
        // ---- convert + store current tile to smem ----
        {
            uint32_t h[4], l[4];
            #pragma unroll
            for (int cc = 0; cc < 2; cc++) {
                int c = (tid & 1) * 2 + cc;
                cvt_chunk(ra[cc * 2], ra[cc * 2 + 1], h, l);
                int p = c ^ ((am >> 1) & 3);
                int off = am * 16 + p * 4;          // u32 units
                *(uint4*)&sAh[off] = make_uint4(h[0], h[1], h[2], h[3]);
                *(uint4*)&sAl[off] = make_uint4(l[0], l[1], l[2], l[3]);
            }
            #pragma unroll
            for (int cc = 0; cc < 2; cc++) {
                int c = (tid & 7) * 2 + cc;
                cvt_chunk(rb[cc * 2], rb[cc * 2 + 1], h, l);
                int p = c ^ (bk & 7);
                int off = bk * 64 + p * 4;          // u32 units
                *(uint4*)&sBh[off] = make_uint4(h[0], h[1], h[2], h[3]);
                *(uint4*)&sBl[off] = make_uint4(l[0], l[1], l[2], l[3]);
            }
        }
        __syncthreads();

        // ---- prefetch next tile into registers ----
        if (it + 1 < niter) {
            int kt = (it + 1) * 32;
            int gm = rowBase + am;
            if (gm < M) {
                const float4* p = (const float4*)(A + (size_t)gm * K + kt + akoff);
                ra[0] = p[0]; ra[1] = p[1]; ra[2] = p[2]; ra[3] = p[3];
            }
            const float4* p = (const float4*)(B + (size_t)(kt + bk) * N + colBase + bnoff);
            rb[0] = p[0]; rb[1] = p[1]; rb[2] = p[2]; rb[3] = p[3];
        }

        // ---- mma over the two k16 steps ----
        #pragma unroll
        for (int s = 0; s < 2; s++) {
            uint32_t Ah[2][4], Al[2][4];
            #pragma unroll
            for (int mi = 0; mi < 2; mi++) {
                int m0 = warpM + mi * 16 + (lane & 15);
                int c = 2 * s + (lane >> 4);
                int p = c ^ ((m0 >> 1) & 3);
                uint32_t off = (uint32_t)(m0 * 64 + p * 16);
                ldsm4(aHi + off, Ah[mi]);
                ldsm4(aLo + off, Al[mi]);
            }
            uint32_t Bh[4][4], Bl[4][4];
            #pragma unroll
            for (int nb = 0; nb < 4; nb++) {
                int k = s * 16 + (lane & 15);
                int nc = (warpN >> 3) + nb * 2 + (lane >> 4);
                int p = nc ^ (k & 7);
                uint32_t off = (uint32_t)(k * 256 + p * 16);
                ldsm4t(bHi + off, Bh[nb]);
                ldsm4t(bLo + off, Bl[nb]);
            }
            #pragma unroll
            for (int mi = 0; mi < 2; mi++)
                #pragma unroll
                for (int nb = 0; nb < 4; nb++)
                    #pragma unroll
                    for (int h = 0; h < 2; h++) {
                        float* c = acc[mi][nb * 2 + h];
                        mma16816(c, Ah[mi], &Bh[nb][h * 2]);
                        mma16816(c, Ah[mi], &Bl[nb][h * 2]);
                        mma16816(c, Al[mi], &Bh[nb][h * 2]);
                    }
        }
        __syncthreads();
    }

    // ---- epilogue ----
    #pragma unroll
    for (int mi = 0; mi < 2; mi++) {
        #pragma unroll
        for (int j = 0; j < 8; j++) {
            float* c = acc[mi][j];
            int gm = rowBase + warpM + mi * 16 + (lane >> 2);
            int gn = colBase + warpN + j * 8 + (lane & 3) * 2;
            float b0 = 0.f, b1 = 0.f;
            if (bias) { b0 = bias[gn]; b1 = bias[gn + 1]; }
            float v0 = c[0] + b0, v1 = c[1] + b1, v2 = c[2] + b0, v3 = c[3] + b1;
            if (doRelu) {
                v0 = fmaxf(v0, 0.f); v1 = fmaxf(v1, 0.f);
                v2 = fmaxf(v2, 0.f); v3 = fmaxf(v3, 0.f);
            }
            if (gm < M)     *(float2*)&C[(size_t)gm * N + gn]       = make_float2(v0, v1);
            if (gm + 8 < M) *(float2*)&C[(size_t)(gm + 8) * N + gn] = make_float2(v2, v3);
        }
    }
}

__global__ void __launch_bounds__(256, 1)
k_gemm_pre(const float* __restrict__ x, const float* __restrict__ W_pre,
           const float* __restrict__ b_pre)
{
    gemm_bf16s(x, W_pre, b_pre, g_hpre, NNODES, HID, DIN, 1);
}

__global__ void __launch_bounds__(256, 1)
k_gemm_h1(const float* __restrict__ W1)
{
    gemm_bf16s(g_hpre, W1, nullptr, g_h1, NNODES, C1, HID, 0);
}

// ---------------- alpha for layer 1 ----------------
__global__ void k_alpha1(const float* __restrict__ a_src1, const float* __restrict__ a_dst1) {
    int node = blockIdx.x * 8 + (threadIdx.x >> 5);
    int lane = threadIdx.x & 31;
    const float* hrow = &g_h1[(size_t)node * C1];
    float s0 = 0.f, s1 = 0.f, d0 = 0.f, d1 = 0.f;
    #pragma unroll
    for (int k = 0; k < 8; k++) {
        int c = lane + 32 * k;
        float v = hrow[c];
        float as = a_src1[c], ad = a_dst1[c];
        if (k < 4) { s0 += v * as; d0 += v * ad; }
        else       { s1 += v * as; d1 += v * ad; }
    }
    #pragma unroll
    for (int o = 16; o; o >>= 1) {
        s0 += __shfl_xor_sync(0xffffffffu, s0, o);
        s1 += __shfl_xor_sync(0xffffffffu, s1, o);
        d0 += __shfl_xor_sync(0xffffffffu, d0, o);
        d1 += __shfl_xor_sync(0xffffffffu, d1, o);
    }
    if (lane == 0) {
        g_asrc1[node * 2 + 0] = s0; g_asrc1[node * 2 + 1] = s1;
        g_adst1[node * 2 + 0] = d0; g_adst1[node * 2 + 1] = d1;
    }
}

__device__ __forceinline__ float lrelu(float e) { return e > 0.f ? e : 0.2f * e; }

// ---------------- GAT1 aggregation ----------------
__global__ void k_agg1(const float* __restrict__ b1) {
    int node = blockIdx.x * 8 + (threadIdx.x >> 5);
    int lane = threadIdx.x & 31;
    int beg = g_off[node], end = g_off[node + 1];
    float ad0 = g_adst1[node * 2 + 0], ad1 = g_adst1[node * 2 + 1];

    float m0 = -1e30f, m1 = -1e30f;
    for (int j = beg + lane; j < end; j += 32) {
        int s = g_esrc[j];
        m0 = fmaxf(m0, lrelu(g_asrc1[s * 2 + 0] + ad0));
        m1 = fmaxf(m1, lrelu(g_asrc1[s * 2 + 1] + ad1));
    }
    #pragma unroll
    for (int o = 16; o; o >>= 1) {
        m0 = fmaxf(m0, __shfl_xor_sync(0xffffffffu, m0, o));
        m1 = fmaxf(m1, __shfl_xor_sync(0xffffffffu, m1, o));
    }

    float acc[8];
    #pragma unroll
    for (int k = 0; k < 8; k++) acc[k] = 0.f;
    float s0 = 0.f, s1 = 0.f;
    for (int j = beg; j < end; j++) {
        int s = g_esrc[j];
        float p0 = expf(lrelu(g_asrc1[s * 2 + 0] + ad0) - m0);
        float p1 = expf(lrelu(g_asrc1[s * 2 + 1] + ad1) - m1);
        s0 += p0; s1 += p1;
        const float* hrow = &g_h1[(size_t)s * C1];
        #pragma unroll
        for (int k = 0; k < 8; k++) {
            float v = hrow[lane + 32 * k];
            acc[k] += v * (k < 4 ? p0 : p1);
        }
    }
    float inv0 = 1.f / (s0 + 1e-16f), inv1 = 1.f / (s1 + 1e-16f);
    float* orow = &g_h1out[(size_t)node * C1];
    #pragma unroll
    for (int k = 0; k < 8; k++) {
        int c = lane + 32 * k;
        float o = acc[k] * (k < 4 ? inv0 : inv1) + b1[c];
        orow[c] = (o > 0.f) ? o : expm1f(o);   // ELU
    }
}

// ---------------- layer 2 transform + alpha ----------------
__global__ void k_gemm2(const float* __restrict__ W2, const float* __restrict__ a_src2,
                        const float* __restrict__ a_dst2) {
    __shared__ float sW[C1 * NC];
    __shared__ float sa[NC], sd[NC];
    int tid = threadIdx.x;
    *(float4*)&sW[tid * 4] = *(const float4*)&W2[tid * 4];
    if (tid < NC) { sa[tid] = a_src2[tid]; sd[tid] = a_dst2[tid]; }
    __syncthreads();

    int node = blockIdx.x * 8 + (tid >> 5);
    int lane = tid & 31;
    const float* hrow = &g_h1out[(size_t)node * C1];
    float a0 = 0.f, a1 = 0.f, a2 = 0.f, a3 = 0.f;
    #pragma unroll
    for (int k = 0; k < 8; k++) {
        int c = lane + 32 * k;
        float v = hrow[c];
        a0 += v * sW[c * 4 + 0];
        a1 += v * sW[c * 4 + 1];
        a2 += v * sW[c * 4 + 2];
        a3 += v * sW[c * 4 + 3];
    }
    #pragma unroll
    for (int o = 16; o; o >>= 1) {
        a0 += __shfl_xor_sync(0xffffffffu, a0, o);
        a1 += __shfl_xor_sync(0xffffffffu, a1, o);
        a2 += __shfl_xor_sync(0xffffffffu, a2, o);
        a3 += __shfl_xor_sync(0xffffffffu, a3, o);
    }
    if (lane == 0) {
        g_h2[node * 4 + 0] = a0; g_h2[node * 4 + 1] = a1;
        g_h2[node * 4 + 2] = a2; g_h2[node * 4 + 3] = a3;
        g_asrc2[node] = a0 * sa[0] + a1 * sa[1] + a2 * sa[2] + a3 * sa[3];
        g_adst2[node] = a0 * sd[0] + a1 * sd[1] + a2 * sd[2] + a3 * sd[3];
    }
}

// ---------------- GAT2 aggregation ----------------
__global__ void k_agg2(const float* __restrict__ b2, float* __restrict__ out) {
    int node = blockIdx.x * 8 + (threadIdx.x >> 5);
    int lane = threadIdx.x & 31;
    int beg = g_off[node], end = g_off[node + 1];
    float ad = g_adst2[node];

    float m = -1e30f;
    for (int j = beg + lane; j < end; j += 32)
        m = fmaxf(m, lrelu(g_asrc2[g_esrc[j]] + ad));
    #pragma unroll
    for (int o = 16; o; o >>= 1)
        m = fmaxf(m, __shfl_xor_sync(0xffffffffu, m, o));

    float ss = 0.f, c0 = 0.f, c1 = 0.f, c2 = 0.f, c3 = 0.f;
    for (int j = beg + lane; j < end; j += 32) {
        int s = g_esrc[j];
        float p = expf(lrelu(g_asrc2[s] + ad) - m);
        ss += p;
        c0 += g_h2[s * 4 + 0] * p;
        c1 += g_h2[s * 4 + 1] * p;
        c2 += g_h2[s * 4 + 2] * p;
        c3 += g_h2[s * 4 + 3] * p;
    }
    #pragma unroll
    for (int o = 16; o; o >>= 1) {
        ss += __shfl_xor_sync(0xffffffffu, ss, o);
        c0 += __shfl_xor_sync(0xffffffffu, c0, o);
        c1 += __shfl_xor_sync(0xffffffffu, c1, o);
        c2 += __shfl_xor_sync(0xffffffffu, c2, o);
        c3 += __shfl_xor_sync(0xffffffffu, c3, o);
    }
    if (lane == 0) {
        float inv = 1.f / (ss + 1e-16f);
        out[node * 4 + 0] = c0 * inv + b2[0];
        out[node * 4 + 1] = c1 * inv + b2[1];
        out[node * 4 + 2] = c2 * inv + b2[2];
        out[node * 4 + 3] = c3 * inv + b2[3];
    }
}

// ---------------- launch ----------------
extern "C" void kernel_launch(void* const* d_in, const int* in_sizes, int n_in,
                              void* d_out, int out_size) {
    const float* x      = (const float*)d_in[0];
    const int*   ei     = (const int*)d_in[1];     // int32 (JAX default: x64 disabled)
    const float* W_pre  = (const float*)d_in[2];
    const float* b_pre  = (const float*)d_in[3];
    const float* W1     = (const float*)d_in[4];
    const float* a_src1 = (const float*)d_in[5];
    const float* a_dst1 = (const float*)d_in[6];
    const float* b1     = (const float*)d_in[7];
    const float* W2     = (const float*)d_in[8];
    const float* a_src2 = (const float*)d_in[9];
    const float* a_dst2 = (const float*)d_in[10];
    const float* b2     = (const float*)d_in[11];
    float* out = (float*)d_out;

    // CSR build (self-loops included)
    k_init_counts<<<(NNODES + 255) / 256, 256>>>();
    k_count<<<(NEDGE + 255) / 256, 256>>>(ei);
    k_scan<<<1, 1024>>>();
    k_scatter<<<(NTOT + 255) / 256, 256>>>(ei);

    // h_pre = relu(x @ W_pre + b_pre)   [50000,1024]@[1024,128]
    {
        dim3 grid(1, (NNODES + 127) / 128);
        k_gemm_pre<<<grid, 256>>>(x, W_pre, b_pre);
    }
    // h1 = h_pre @ W1                   [50000,128]@[128,256]
    {
        dim3 grid(2, (NNODES + 127) / 128);
        k_gemm_h1<<<grid, 256>>>(W1);
    }
    k_alpha1<<<NNODES / 8, 256>>>(a_src1, a_dst1);
    k_agg1<<<NNODES / 8, 256>>>(b1);
    k_gemm2<<<NNODES / 8, 256>>>(W2, a_src2, a_dst2);
    k_agg2<<<NNODES / 8, 256>>>(b2, out);
}

// round 7
// speedup vs baseline: 2.2229x; 1.1536x over previous
#include <cuda_runtime.h>
#include <cuda_bf16.h>
#include <math.h>
#include <stdint.h>

#define NNODES 50000
#define NEDGE  800000
#define NTOT   (NEDGE + NNODES)
#define DIN    1024
#define HID    128
#define C1     256   // HEADS*HID
#define NC     4

// ---------------- scratch (device globals; no allocation allowed) ----------------
__device__ float g_hpre[(size_t)NNODES * HID];
__device__ float g_h1[(size_t)NNODES * C1];
__device__ float g_h1out[(size_t)NNODES * C1];
__device__ float g_asrc1[NNODES * 2];
__device__ float g_adst1[NNODES * 2];
__device__ float g_h2[NNODES * NC];
__device__ float g_asrc2[NNODES];
__device__ float g_adst2[NNODES];
__device__ int   g_cnt[NNODES];
__device__ int   g_off[NNODES + 1];
__device__ int   g_esrc[NTOT];
__device__ int   g_bsum[256];
// pre-split bf16 weight planes ([K][N] row-major, same layout as fp32 weights)
__device__ __align__(16) __nv_bfloat16 g_WpH[DIN * HID];
__device__ __align__(16) __nv_bfloat16 g_WpL[DIN * HID];
__device__ __align__(16) __nv_bfloat16 g_W1H[HID * C1];
__device__ __align__(16) __nv_bfloat16 g_W1L[HID * C1];

__device__ __forceinline__ int clampN(int v) {
    return v < 0 ? 0 : (v >= NNODES ? NNODES - 1 : v);
}

// ---------------- CSR build ----------------
__global__ void k_init_counts() {
    int i = blockIdx.x * blockDim.x + threadIdx.x;
    if (i < NNODES) g_cnt[i] = 1;   // self-loop pre-count
}

__global__ void k_count(const int* __restrict__ ei) {
    int e = blockIdx.x * blockDim.x + threadIdx.x;
    if (e < NEDGE) {
        int dst = clampN(ei[NEDGE + e]);
        atomicAdd(&g_cnt[dst], 1);
    }
}

// parallel scan: A) per-block scan + partials, B) scan partials, C) add offsets
__global__ void k_scanA() {
    __shared__ int wsum[8];
    int i = blockIdx.x * 256 + threadIdx.x;
    int lane = threadIdx.x & 31, w = threadIdx.x >> 5;
    int v = (i < NNODES) ? g_cnt[i] : 0;
    if (i < NNODES) g_cnt[i] = 0;
    int x = v;
    #pragma unroll
    for (int o = 1; o < 32; o <<= 1) {
        int t = __shfl_up_sync(0xffffffffu, x, o);
        if (lane >= o) x += t;
    }
    if (lane == 31) wsum[w] = x;
    __syncthreads();
    if (w == 0 && lane < 8) {
        int s = wsum[lane];
        #pragma unroll
        for (int o = 1; o < 8; o <<= 1) {
            int t = __shfl_up_sync(0xffu, s, o);
            if (lane >= o) s += t;
        }
        wsum[lane] = s;
    }
    __syncthreads();
    int pre = (w > 0) ? wsum[w - 1] : 0;
    if (i < NNODES) g_off[i] = pre + x - v;
    if (threadIdx.x == 255) g_bsum[blockIdx.x] = pre + x;
}

__global__ void k_scanB(int nblk) {
    __shared__ int wsum[8];
    int t = threadIdx.x;
    int lane = t & 31, w = t >> 5;
    int v = (t < nblk) ? g_bsum[t] : 0;
    int x = v;
    #pragma unroll
    for (int o = 1; o < 32; o <<= 1) {
        int q = __shfl_up_sync(0xffffffffu, x, o);
        if (lane >= o) x += q;
    }
    if (lane == 31) wsum[w] = x;
    __syncthreads();
    if (w == 0 && lane < 8) {
        int s = wsum[lane];
        #pragma unroll
        for (int o = 1; o < 8; o <<= 1) {
            int q = __shfl_up_sync(0xffu, s, o);
            if (lane >= o) s += q;
        }
        wsum[lane] = s;
    }
    __syncthreads();
    int pre = (w > 0) ? wsum[w - 1] : 0;
    if (t < nblk) g_bsum[t] = pre + x - v;
    if (t == 255) g_off[NNODES] = pre + x;
}

__global__ void k_scanC() {
    int i = blockIdx.x * 256 + threadIdx.x;
    if (i < NNODES) g_off[i] += g_bsum[blockIdx.x];
}

__global__ void k_scatter(const int* __restrict__ ei) {
    int e = blockIdx.x * blockDim.x + threadIdx.x;
    if (e >= NTOT) return;
    int src, dst;
    if (e < NEDGE) { src = clampN(ei[e]); dst = clampN(ei[NEDGE + e]); }
    else           { src = e - NEDGE; dst = src; }
    int pos = g_off[dst] + atomicAdd(&g_cnt[dst], 1);
    g_esrc[pos] = src;
}

// ================= bf16 split helpers =================
__device__ __forceinline__ uint32_t packbf(float v0, float v1) {
    uint32_t r;
    asm("cvt.rn.bf16x2.f32 %0, %1, %2;" : "=r"(r) : "f"(v1), "f"(v0));
    return r;
}
__device__ __forceinline__ float bflowf(uint32_t p)  { return __uint_as_float(p << 16); }
__device__ __forceinline__ float bfhighf(uint32_t p) { return __uint_as_float(p & 0xffff0000u); }

__device__ __forceinline__ void cvt_chunk(float4 x, float4 y, uint32_t* h, uint32_t* l) {
    h[0] = packbf(x.x, x.y); h[1] = packbf(x.z, x.w);
    h[2] = packbf(y.x, y.y); h[3] = packbf(y.z, y.w);
    l[0] = packbf(x.x - bflowf(h[0]), x.y - bfhighf(h[0]));
    l[1] = packbf(x.z - bflowf(h[1]), x.w - bfhighf(h[1]));
    l[2] = packbf(y.x - bflowf(h[2]), y.y - bfhighf(h[2]));
    l[3] = packbf(y.z - bflowf(h[3]), y.w - bfhighf(h[3]));
}

// weight split (once per run) — output symbols bound in DEVICE code
// (passing __device__ arrays as host-side kernel args passes the host shadow
//  symbol, which on GB300/ATS silently writes host memory — round-6 bug)
__global__ void k_prepWpre(const float* __restrict__ W) {
    int i = blockIdx.x * blockDim.x + threadIdx.x;
    if (i < DIN * HID) {
        float v = W[i];
        __nv_bfloat16 h = __float2bfloat16(v);
        g_WpH[i] = h;
        g_WpL[i] = __float2bfloat16(v - __bfloat162float(h));
    }
}
__global__ void k_prepW1(const float* __restrict__ W) {
    int i = blockIdx.x * blockDim.x + threadIdx.x;
    if (i < HID * C1) {
        float v = W[i];
        __nv_bfloat16 h = __float2bfloat16(v);
        g_W1H[i] = h;
        g_W1L[i] = __float2bfloat16(v - __bfloat162float(h));
    }
}

// ================= mma.sync split-bf16 GEMM, double-buffered =================
__device__ __forceinline__ void ldsm4(uint32_t addr, uint32_t* r) {
    asm volatile("ldmatrix.sync.aligned.m8n8.x4.shared.b16 {%0,%1,%2,%3},[%4];"
        : "=r"(r[0]), "=r"(r[1]), "=r"(r[2]), "=r"(r[3]) : "r"(addr));
}
__device__ __forceinline__ void ldsm4t(uint32_t addr, uint32_t* r) {
    asm volatile("ldmatrix.sync.aligned.m8n8.x4.trans.shared.b16 {%0,%1,%2,%3},[%4];"
        : "=r"(r[0]), "=r"(r[1]), "=r"(r[2]), "=r"(r[3]) : "r"(addr));
}
__device__ __forceinline__ void mma16816(float* c, const uint32_t* a, const uint32_t* b) {
    asm volatile(
        "mma.sync.aligned.m16n8k16.row.col.f32.bf16.bf16.f32 "
        "{%0,%1,%2,%3},{%4,%5,%6,%7},{%8,%9},{%0,%1,%2,%3};"
        : "+f"(c[0]), "+f"(c[1]), "+f"(c[2]), "+f"(c[3])
        : "r"(a[0]), "r"(a[1]), "r"(a[2]), "r"(a[3]), "r"(b[0]), "r"(b[1]));
}

// smem plan per buffer (32KB): A_hi 8K | A_lo 8K | B_hi 8K | B_lo 8K; 2 buffers
#define GB_BUF 32768
#define GB_AHI 0
#define GB_ALO 8192
#define GB_BHI 16384
#define GB_BLO 24576
#define GB_SMEM (2 * GB_BUF)

// A: fp32 [M][K]; Bh/Bl: bf16 [K][N] row-major. N multiple of 128, K multiple of 32.
__device__ __forceinline__ void gemm_bf16s(
    const float* __restrict__ A,
    const __nv_bfloat16* __restrict__ Bh, const __nv_bfloat16* __restrict__ Bl,
    const float* __restrict__ bias, float* __restrict__ C,
    int M, int N, int K, int doRelu)
{
    extern __shared__ __align__(16) char dsm[];
    const uint32_t sb = (uint32_t)__cvta_generic_to_shared(dsm);

    const int tid = threadIdx.x;
    const int lane = tid & 31;
    const int warp = tid >> 5;
    const int warpM = (warp & 3) * 32;
    const int warpN = (warp >> 2) * 64;
    const int rowBase = blockIdx.y * 128;
    const int colBase = blockIdx.x * 128;

    // staging roles
    const int am = tid >> 1;             // A row
    const int akoff = (tid & 1) * 16;    // A k-offset (16 floats)
    const int bk = tid >> 3;             // B k-row
    const int bnoff = (tid & 7) * 16;    // B n-offset (16 bf16)
    const int gm = rowBase + am;
    const bool aValid = gm < M;

    float acc[2][8][4];
    #pragma unroll
    for (int mi = 0; mi < 2; mi++)
        #pragma unroll
        for (int j = 0; j < 8; j++)
            #pragma unroll
            for (int q = 0; q < 4; q++) acc[mi][j][q] = 0.f;

    const int niter = K >> 5;
    float4 ra[4];
    uint4 rbh[2], rbl[2];

    // ---- prefetch tile 0 ----
    {
        if (aValid) {
            const float4* p = (const float4*)(A + (size_t)gm * K + akoff);
            ra[0] = p[0]; ra[1] = p[1]; ra[2] = p[2]; ra[3] = p[3];
        } else {
            ra[0] = ra[1] = ra[2] = ra[3] = make_float4(0.f, 0.f, 0.f, 0.f);
        }
        const uint4* ph = (const uint4*)(Bh + (size_t)bk * N + colBase + bnoff);
        const uint4* pl = (const uint4*)(Bl + (size_t)bk * N + colBase + bnoff);
        rbh[0] = ph[0]; rbh[1] = ph[1];
        rbl[0] = pl[0]; rbl[1] = pl[1];
    }
    // ---- store tile 0 to buffer 0 ----
    {
        uint32_t h[4], l[4];
        #pragma unroll
        for (int cc = 0; cc < 2; cc++) {
            int c = (tid & 1) * 2 + cc;
            cvt_chunk(ra[cc * 2], ra[cc * 2 + 1], h, l);
            int p = c ^ ((am >> 1) & 3);
            int off = am * 64 + p * 16;
            *(uint4*)(dsm + GB_AHI + off) = make_uint4(h[0], h[1], h[2], h[3]);
            *(uint4*)(dsm + GB_ALO + off) = make_uint4(l[0], l[1], l[2], l[3]);
        }
        #pragma unroll
        for (int cc = 0; cc < 2; cc++) {
            int c = (tid & 7) * 2 + cc;
            int p = c ^ (bk & 7);
            int off = bk * 256 + p * 16;
            *(uint4*)(dsm + GB_BHI + off) = rbh[cc];
            *(uint4*)(dsm + GB_BLO + off) = rbl[cc];
        }
    }
    __syncthreads();

    for (int it = 0; it < niter; it++) {
        const uint32_t bufA_h = sb + (it & 1) * GB_BUF + GB_AHI;
        const uint32_t bufA_l = sb + (it & 1) * GB_BUF + GB_ALO;
        const uint32_t bufB_h = sb + (it & 1) * GB_BUF + GB_BHI;
        const uint32_t bufB_l = sb + (it & 1) * GB_BUF + GB_BLO;

        // prefetch next tile into registers
        if (it + 1 < niter) {
            int kt = (it + 1) * 32;
            if (aValid) {
                const float4* p = (const float4*)(A + (size_t)gm * K + kt + akoff);
                ra[0] = p[0]; ra[1] = p[1]; ra[2] = p[2]; ra[3] = p[3];
            }
            const uint4* ph = (const uint4*)(Bh + (size_t)(kt + bk) * N + colBase + bnoff);
            const uint4* pl = (const uint4*)(Bl + (size_t)(kt + bk) * N + colBase + bnoff);
            rbh[0] = ph[0]; rbh[1] = ph[1];
            rbl[0] = pl[0]; rbl[1] = pl[1];
        }

        // mma over current buffer
        #pragma unroll
        for (int s = 0; s < 2; s++) {
            uint32_t Ah[2][4], Al[2][4];
            #pragma unroll
            for (int mi = 0; mi < 2; mi++) {
                int m0 = warpM + mi * 16 + (lane & 15);
                int c = 2 * s + (lane >> 4);
                int p = c ^ ((m0 >> 1) & 3);
                uint32_t off = (uint32_t)(m0 * 64 + p * 16);
                ldsm4(bufA_h + off, Ah[mi]);
                ldsm4(bufA_l + off, Al[mi]);
            }
            uint32_t Bhf[4][4], Blf[4][4];
            #pragma unroll
            for (int nb = 0; nb < 4; nb++) {
                int k = s * 16 + (lane & 15);
                int nc = (warpN >> 3) + nb * 2 + (lane >> 4);
                int p = nc ^ (k & 7);
                uint32_t off = (uint32_t)(k * 256 + p * 16);
                ldsm4t(bufB_h + off, Bhf[nb]);
                ldsm4t(bufB_l + off, Blf[nb]);
            }
            #pragma unroll
            for (int mi = 0; mi < 2; mi++)
                #pragma unroll
                for (int nb = 0; nb < 4; nb++)
                    #pragma unroll
                    for (int h = 0; h < 2; h++) {
                        float* c = acc[mi][nb * 2 + h];
                        mma16816(c, Ah[mi], &Bhf[nb][h * 2]);
                        mma16816(c, Ah[mi], &Blf[nb][h * 2]);
                        mma16816(c, Al[mi], &Bhf[nb][h * 2]);
                    }
        }

        // store next tile into the other buffer (overlaps with other warps' mma)
        if (it + 1 < niter) {
            char* nb = dsm + ((it + 1) & 1) * GB_BUF;
            uint32_t h[4], l[4];
            #pragma unroll
            for (int cc = 0; cc < 2; cc++) {
                int c = (tid & 1) * 2 + cc;
                cvt_chunk(ra[cc * 2], ra[cc * 2 + 1], h, l);
                int p = c ^ ((am >> 1) & 3);
                int off = am * 64 + p * 16;
                *(uint4*)(nb + GB_AHI + off) = make_uint4(h[0], h[1], h[2], h[3]);
                *(uint4*)(nb + GB_ALO + off) = make_uint4(l[0], l[1], l[2], l[3]);
            }
            #pragma unroll
            for (int cc = 0; cc < 2; cc++) {
                int c = (tid & 7) * 2 + cc;
                int p = c ^ (bk & 7);
                int off = bk * 256 + p * 16;
                *(uint4*)(nb + GB_BHI + off) = rbh[cc];
                *(uint4*)(nb + GB_BLO + off) = rbl[cc];
            }
        }
        __syncthreads();
    }

    // ---- epilogue ----
    #pragma unroll
    for (int mi = 0; mi < 2; mi++) {
        #pragma unroll
        for (int j = 0; j < 8; j++) {
            float* c = acc[mi][j];
            int gmr = rowBase + warpM + mi * 16 + (lane >> 2);
            int gn = colBase + warpN + j * 8 + (lane & 3) * 2;
            float b0 = 0.f, b1 = 0.f;
            if (bias) { b0 = bias[gn]; b1 = bias[gn + 1]; }
            float v0 = c[0] + b0, v1 = c[1] + b1, v2 = c[2] + b0, v3 = c[3] + b1;
            if (doRelu) {
                v0 = fmaxf(v0, 0.f); v1 = fmaxf(v1, 0.f);
                v2 = fmaxf(v2, 0.f); v3 = fmaxf(v3, 0.f);
            }
            if (gmr < M)     *(float2*)&C[(size_t)gmr * N + gn]       = make_float2(v0, v1);
            if (gmr + 8 < M) *(float2*)&C[(size_t)(gmr + 8) * N + gn] = make_float2(v2, v3);
        }
    }
}

__global__ void __launch_bounds__(256)
k_gemm_pre(const float* __restrict__ x, const float* __restrict__ b_pre)
{
    gemm_bf16s(x, g_WpH, g_WpL, b_pre, g_hpre, NNODES, HID, DIN, 1);
}

__global__ void __launch_bounds__(256)
k_gemm_h1()
{
    gemm_bf16s(g_hpre, g_W1H, g_W1L, nullptr, g_h1, NNODES, C1, HID, 0);
}

// ---------------- alpha for layer 1 ----------------
__global__ void k_alpha1(const float* __restrict__ a_src1, const float* __restrict__ a_dst1) {
    int node = blockIdx.x * 8 + (threadIdx.x >> 5);
    int lane = threadIdx.x & 31;
    const float* hrow = &g_h1[(size_t)node * C1];
    float s0 = 0.f, s1 = 0.f, d0 = 0.f, d1 = 0.f;
    #pragma unroll
    for (int k = 0; k < 8; k++) {
        int c = lane + 32 * k;
        float v = hrow[c];
        float as = a_src1[c], ad = a_dst1[c];
        if (k < 4) { s0 += v * as; d0 += v * ad; }
        else       { s1 += v * as; d1 += v * ad; }
    }
    #pragma unroll
    for (int o = 16; o; o >>= 1) {
        s0 += __shfl_xor_sync(0xffffffffu, s0, o);
        s1 += __shfl_xor_sync(0xffffffffu, s1, o);
        d0 += __shfl_xor_sync(0xffffffffu, d0, o);
        d1 += __shfl_xor_sync(0xffffffffu, d1, o);
    }
    if (lane == 0) {
        g_asrc1[node * 2 + 0] = s0; g_asrc1[node * 2 + 1] = s1;
        g_adst1[node * 2 + 0] = d0; g_adst1[node * 2 + 1] = d1;
    }
}

__device__ __forceinline__ float lrelu(float e) { return e > 0.f ? e : 0.2f * e; }

// ---------------- GAT1 aggregation ----------------
__global__ void k_agg1(const float* __restrict__ b1) {
    int node = blockIdx.x * 8 + (threadIdx.x >> 5);
    int lane = threadIdx.x & 31;
    int beg = g_off[node], end = g_off[node + 1];
    float ad0 = g_adst1[node * 2 + 0], ad1 = g_adst1[node * 2 + 1];

    float m0 = -1e30f, m1 = -1e30f;
    for (int j = beg + lane; j < end; j += 32) {
        int s = g_esrc[j];
        m0 = fmaxf(m0, lrelu(g_asrc1[s * 2 + 0] + ad0));
        m1 = fmaxf(m1, lrelu(g_asrc1[s * 2 + 1] + ad1));
    }
    #pragma unroll
    for (int o = 16; o; o >>= 1) {
        m0 = fmaxf(m0, __shfl_xor_sync(0xffffffffu, m0, o));
        m1 = fmaxf(m1, __shfl_xor_sync(0xffffffffu, m1, o));
    }

    float acc[8];
    #pragma unroll
    for (int k = 0; k < 8; k++) acc[k] = 0.f;
    float s0 = 0.f, s1 = 0.f;
    for (int j = beg; j < end; j++) {
        int s = g_esrc[j];
        float p0 = expf(lrelu(g_asrc1[s * 2 + 0] + ad0) - m0);
        float p1 = expf(lrelu(g_asrc1[s * 2 + 1] + ad1) - m1);
        s0 += p0; s1 += p1;
        const float* hrow = &g_h1[(size_t)s * C1];
        #pragma unroll
        for (int k = 0; k < 8; k++) {
            float v = hrow[lane + 32 * k];
            acc[k] += v * (k < 4 ? p0 : p1);
        }
    }
    float inv0 = 1.f / (s0 + 1e-16f), inv1 = 1.f / (s1 + 1e-16f);
    float* orow = &g_h1out[(size_t)node * C1];
    #pragma unroll
    for (int k = 0; k < 8; k++) {
        int c = lane + 32 * k;
        float o = acc[k] * (k < 4 ? inv0 : inv1) + b1[c];
        orow[c] = (o > 0.f) ? o : expm1f(o);   // ELU
    }
}

// ---------------- layer 2 transform + alpha ----------------
__global__ void k_gemm2(const float* __restrict__ W2, const float* __restrict__ a_src2,
                        const float* __restrict__ a_dst2) {
    __shared__ float sW[C1 * NC];
    __shared__ float sa[NC], sd[NC];
    int tid = threadIdx.x;
    *(float4*)&sW[tid * 4] = *(const float4*)&W2[tid * 4];
    if (tid < NC) { sa[tid] = a_src2[tid]; sd[tid] = a_dst2[tid]; }
    __syncthreads();

    int node = blockIdx.x * 8 + (tid >> 5);
    int lane = tid & 31;
    const float* hrow = &g_h1out[(size_t)node * C1];
    float a0 = 0.f, a1 = 0.f, a2 = 0.f, a3 = 0.f;
    #pragma unroll
    for (int k = 0; k < 8; k++) {
        int c = lane + 32 * k;
        float v = hrow[c];
        a0 += v * sW[c * 4 + 0];
        a1 += v * sW[c * 4 + 1];
        a2 += v * sW[c * 4 + 2];
        a3 += v * sW[c * 4 + 3];
    }
    #pragma unroll
    for (int o = 16; o; o >>= 1) {
        a0 += __shfl_xor_sync(0xffffffffu, a0, o);
        a1 += __shfl_xor_sync(0xffffffffu, a1, o);
        a2 += __shfl_xor_sync(0xffffffffu, a2, o);
        a3 += __shfl_xor_sync(0xffffffffu, a3, o);
    }
    if (lane == 0) {
        g_h2[node * 4 + 0] = a0; g_h2[node * 4 + 1] = a1;
        g_h2[node * 4 + 2] = a2; g_h2[node * 4 + 3] = a3;
        g_asrc2[node] = a0 * sa[0] + a1 * sa[1] + a2 * sa[2] + a3 * sa[3];
        g_adst2[node] = a0 * sd[0] + a1 * sd[1] + a2 * sd[2] + a3 * sd[3];
    }
}

// ---------------- GAT2 aggregation ----------------
__global__ void k_agg2(const float* __restrict__ b2, float* __restrict__ out) {
    int node = blockIdx.x * 8 + (threadIdx.x >> 5);
    int lane = threadIdx.x & 31;
    int beg = g_off[node], end = g_off[node + 1];
    float ad = g_adst2[node];

    float m = -1e30f;
    for (int j = beg + lane; j < end; j += 32)
        m = fmaxf(m, lrelu(g_asrc2[g_esrc[j]] + ad));
    #pragma unroll
    for (int o = 16; o; o >>= 1)
        m = fmaxf(m, __shfl_xor_sync(0xffffffffu, m, o));

    float ss = 0.f, c0 = 0.f, c1 = 0.f, c2 = 0.f, c3 = 0.f;
    for (int j = beg + lane; j < end; j += 32) {
        int s = g_esrc[j];
        float p = expf(lrelu(g_asrc2[s] + ad) - m);
        ss += p;
        c0 += g_h2[s * 4 + 0] * p;
        c1 += g_h2[s * 4 + 1] * p;
        c2 += g_h2[s * 4 + 2] * p;
        c3 += g_h2[s * 4 + 3] * p;
    }
    #pragma unroll
    for (int o = 16; o; o >>= 1) {
        ss += __shfl_xor_sync(0xffffffffu, ss, o);
        c0 += __shfl_xor_sync(0xffffffffu, c0, o);
        c1 += __shfl_xor_sync(0xffffffffu, c1, o);
        c2 += __shfl_xor_sync(0xffffffffu, c2, o);
        c3 += __shfl_xor_sync(0xffffffffu, c3, o);
    }
    if (lane == 0) {
        float inv = 1.f / (ss + 1e-16f);
        out[node * 4 + 0] = c0 * inv + b2[0];
        out[node * 4 + 1] = c1 * inv + b2[1];
        out[node * 4 + 2] = c2 * inv + b2[2];
        out[node * 4 + 3] = c3 * inv + b2[3];
    }
}

// ---------------- launch ----------------
extern "C" void kernel_launch(void* const* d_in, const int* in_sizes, int n_in,
                              void* d_out, int out_size) {
    const float* x      = (const float*)d_in[0];
    const int*   ei     = (const int*)d_in[1];
    const float* W_pre  = (const float*)d_in[2];
    const float* b_pre  = (const float*)d_in[3];
    const float* W1     = (const float*)d_in[4];
    const float* a_src1 = (const float*)d_in[5];
    const float* a_dst1 = (const float*)d_in[6];
    const float* b1     = (const float*)d_in[7];
    const float* W2     = (const float*)d_in[8];
    const float* a_src2 = (const float*)d_in[9];
    const float* a_dst2 = (const float*)d_in[10];
    const float* b2     = (const float*)d_in[11];
    float* out = (float*)d_out;

    cudaFuncSetAttribute(k_gemm_pre, cudaFuncAttributeMaxDynamicSharedMemorySize, GB_SMEM);
    cudaFuncSetAttribute(k_gemm_h1,  cudaFuncAttributeMaxDynamicSharedMemorySize, GB_SMEM);

    const int NB = (NNODES + 255) / 256;   // 196

    // CSR build (self-loops included)
    k_init_counts<<<NB, 256>>>();
    k_count<<<(NEDGE + 255) / 256, 256>>>(ei);
    k_scanA<<<NB, 256>>>();
    k_scanB<<<1, 256>>>(NB);
    k_scanC<<<NB, 256>>>();
    k_scatter<<<(NTOT + 255) / 256, 256>>>(ei);

    // split weights to bf16 hi/lo planes (symbols bound in device code)
    k_prepWpre<<<(DIN * HID + 255) / 256, 256>>>(W_pre);
    k_prepW1<<<(HID * C1 + 255) / 256, 256>>>(W1);

    // h_pre = relu(x @ W_pre + b_pre)
    {
        dim3 grid(1, (NNODES + 127) / 128);
        k_gemm_pre<<<grid, 256, GB_SMEM>>>(x, b_pre);
    }
    // h1 = h_pre @ W1
    {
        dim3 grid(2, (NNODES + 127) / 128);
        k_gemm_h1<<<grid, 256, GB_SMEM>>>();
    }
    k_alpha1<<<NNODES / 8, 256>>>(a_src1, a_dst1);
    k_agg1<<<NNODES / 8, 256>>>(b1);
    k_gemm2<<<NNODES / 8, 256>>>(W2, a_src2, a_dst2);
    k_agg2<<<NNODES / 8, 256>>>(b2, out);
}

// round 8
// speedup vs baseline: 2.4009x; 1.0801x over previous
#include <cuda_runtime.h>
#include <cuda_bf16.h>
#include <math.h>
#include <stdint.h>

#define NNODES 50000
#define NEDGE  800000
#define NTOT   (NEDGE + NNODES)
#define DIN    1024
#define HID    128
#define C1     256   // HEADS*HID
#define NC     4

// ---------------- scratch (device globals; no allocation allowed) ----------------
__device__ float g_hpre[(size_t)NNODES * HID];
__device__ float g_h1[(size_t)NNODES * C1];
__device__ float g_h1out[(size_t)NNODES * C1];
__device__ float g_asrc1[NNODES * 2];
__device__ float g_adst1[NNODES * 2];
__device__ float g_h2[NNODES * NC];
__device__ float g_asrc2[NNODES];
__device__ float g_adst2[NNODES];
__device__ int   g_cnt[NNODES];     // invariant: zero at kernel_launch entry
__device__ int   g_off[NNODES + 1];
__device__ int   g_esrc[NTOT];
__device__ int   g_bsum[256];
// pre-split bf16 weight planes ([K][N] row-major, same layout as fp32 weights)
__device__ __align__(16) __nv_bfloat16 g_WpH[DIN * HID];
__device__ __align__(16) __nv_bfloat16 g_WpL[DIN * HID];
__device__ __align__(16) __nv_bfloat16 g_W1H[HID * C1];
__device__ __align__(16) __nv_bfloat16 g_W1L[HID * C1];

__device__ __forceinline__ int clampN(int v) {
    return v < 0 ? 0 : (v >= NNODES ? NNODES - 1 : v);
}

// ---------------- CSR build ----------------
// g_cnt is zero on entry (device zero-init on first run; k_agg1 re-zeroes it).
__global__ void k_count(const int* __restrict__ ei) {
    int e = blockIdx.x * blockDim.x + threadIdx.x;
    if (e < NEDGE) {
        int dst = clampN(ei[NEDGE + e]);
        atomicAdd(&g_cnt[dst], 1);
    }
}

// parallel scan: A) per-block scan (+1 self-loop) + partials, B) scan partials, C) add
__global__ void k_scanA() {
    __shared__ int wsum[8];
    int i = blockIdx.x * 256 + threadIdx.x;
    int lane = threadIdx.x & 31, w = threadIdx.x >> 5;
    int v = (i < NNODES) ? (g_cnt[i] + 1) : 0;   // +1 = self-loop
    if (i < NNODES) g_cnt[i] = 0;                // becomes scatter cursor
    int x = v;
    #pragma unroll
    for (int o = 1; o < 32; o <<= 1) {
        int t = __shfl_up_sync(0xffffffffu, x, o);
        if (lane >= o) x += t;
    }
    if (lane == 31) wsum[w] = x;
    __syncthreads();
    if (w == 0 && lane < 8) {
        int s = wsum[lane];
        #pragma unroll
        for (int o = 1; o < 8; o <<= 1) {
            int t = __shfl_up_sync(0xffu, s, o);
            if (lane >= o) s += t;
        }
        wsum[lane] = s;
    }
    __syncthreads();
    int pre = (w > 0) ? wsum[w - 1] : 0;
    if (i < NNODES) g_off[i] = pre + x - v;
    if (threadIdx.x == 255) g_bsum[blockIdx.x] = pre + x;
}

__global__ void k_scanB(int nblk) {
    __shared__ int wsum[8];
    int t = threadIdx.x;
    int lane = t & 31, w = t >> 5;
    int v = (t < nblk) ? g_bsum[t] : 0;
    int x = v;
    #pragma unroll
    for (int o = 1; o < 32; o <<= 1) {
        int q = __shfl_up_sync(0xffffffffu, x, o);
        if (lane >= o) x += q;
    }
    if (lane == 31) wsum[w] = x;
    __syncthreads();
    if (w == 0 && lane < 8) {
        int s = wsum[lane];
        #pragma unroll
        for (int o = 1; o < 8; o <<= 1) {
            int q = __shfl_up_sync(0xffu, s, o);
            if (lane >= o) s += q;
        }
        wsum[lane] = s;
    }
    __syncthreads();
    int pre = (w > 0) ? wsum[w - 1] : 0;
    if (t < nblk) g_bsum[t] = pre + x - v;
    if (t == 255) g_off[NNODES] = pre + x;
}

__global__ void k_scanC() {
    int i = blockIdx.x * 256 + threadIdx.x;
    if (i < NNODES) g_off[i] += g_bsum[blockIdx.x];
}

__global__ void k_scatter(const int* __restrict__ ei) {
    int e = blockIdx.x * blockDim.x + threadIdx.x;
    if (e >= NTOT) return;
    int src, dst;
    if (e < NEDGE) { src = clampN(ei[e]); dst = clampN(ei[NEDGE + e]); }
    else           { src = e - NEDGE; dst = src; }
    int pos = g_off[dst] + atomicAdd(&g_cnt[dst], 1);
    g_esrc[pos] = src;
}

// ================= bf16 split helpers =================
__device__ __forceinline__ uint32_t packbf(float v0, float v1) {
    uint32_t r;
    asm("cvt.rn.bf16x2.f32 %0, %1, %2;" : "=r"(r) : "f"(v1), "f"(v0));
    return r;
}
__device__ __forceinline__ float bflowf(uint32_t p)  { return __uint_as_float(p << 16); }
__device__ __forceinline__ float bfhighf(uint32_t p) { return __uint_as_float(p & 0xffff0000u); }

__device__ __forceinline__ void cvt_chunk(float4 x, float4 y, uint32_t* h, uint32_t* l) {
    h[0] = packbf(x.x, x.y); h[1] = packbf(x.z, x.w);
    h[2] = packbf(y.x, y.y); h[3] = packbf(y.z, y.w);
    l[0] = packbf(x.x - bflowf(h[0]), x.y - bfhighf(h[0]));
    l[1] = packbf(x.z - bflowf(h[1]), x.w - bfhighf(h[1]));
    l[2] = packbf(y.x - bflowf(h[2]), y.y - bfhighf(h[2]));
    l[3] = packbf(y.z - bflowf(h[3]), y.w - bfhighf(h[3]));
}

// weight split (once per run) — output symbols bound in DEVICE code
__global__ void k_prepW(const float* __restrict__ Wp, const float* __restrict__ W1) {
    int i = blockIdx.x * blockDim.x + threadIdx.x;
    if (i < DIN * HID) {
        float v = Wp[i];
        __nv_bfloat16 h = __float2bfloat16(v);
        g_WpH[i] = h;
        g_WpL[i] = __float2bfloat16(v - __bfloat162float(h));
    } else {
        int j = i - DIN * HID;
        if (j < HID * C1) {
            float v = W1[j];
            __nv_bfloat16 h = __float2bfloat16(v);
            g_W1H[j] = h;
            g_W1L[j] = __float2bfloat16(v - __bfloat162float(h));
        }
    }
}

// ================= mma.sync split-bf16 GEMM, double-buffered =================
__device__ __forceinline__ void ldsm4(uint32_t addr, uint32_t* r) {
    asm volatile("ldmatrix.sync.aligned.m8n8.x4.shared.b16 {%0,%1,%2,%3},[%4];"
        : "=r"(r[0]), "=r"(r[1]), "=r"(r[2]), "=r"(r[3]) : "r"(addr));
}
__device__ __forceinline__ void ldsm4t(uint32_t addr, uint32_t* r) {
    asm volatile("ldmatrix.sync.aligned.m8n8.x4.trans.shared.b16 {%0,%1,%2,%3},[%4];"
        : "=r"(r[0]), "=r"(r[1]), "=r"(r[2]), "=r"(r[3]) : "r"(addr));
}
__device__ __forceinline__ void mma16816(float* c, const uint32_t* a, const uint32_t* b) {
    asm volatile(
        "mma.sync.aligned.m16n8k16.row.col.f32.bf16.bf16.f32 "
        "{%0,%1,%2,%3},{%4,%5,%6,%7},{%8,%9},{%0,%1,%2,%3};"
        : "+f"(c[0]), "+f"(c[1]), "+f"(c[2]), "+f"(c[3])
        : "r"(a[0]), "r"(a[1]), "r"(a[2]), "r"(a[3]), "r"(b[0]), "r"(b[1]));
}

// smem plan per buffer (32KB): A_hi 8K | A_lo 8K | B_hi 8K | B_lo 8K; 2 buffers
#define GB_BUF 32768
#define GB_AHI 0
#define GB_ALO 8192
#define GB_BHI 16384
#define GB_BLO 24576
#define GB_SMEM (2 * GB_BUF)

__device__ __forceinline__ void gemm_bf16s(
    const float* __restrict__ A,
    const __nv_bfloat16* __restrict__ Bh, const __nv_bfloat16* __restrict__ Bl,
    const float* __restrict__ bias, float* __restrict__ C,
    int M, int N, int K, int doRelu)
{
    extern __shared__ __align__(16) char dsm[];
    const uint32_t sb = (uint32_t)__cvta_generic_to_shared(dsm);

    const int tid = threadIdx.x;
    const int lane = tid & 31;
    const int warp = tid >> 5;
    const int warpM = (warp & 3) * 32;
    const int warpN = (warp >> 2) * 64;
    const int rowBase = blockIdx.y * 128;
    const int colBase = blockIdx.x * 128;

    const int am = tid >> 1;
    const int akoff = (tid & 1) * 16;
    const int bk = tid >> 3;
    const int bnoff = (tid & 7) * 16;
    const int gm = rowBase + am;
    const bool aValid = gm < M;

    float acc[2][8][4];
    #pragma unroll
    for (int mi = 0; mi < 2; mi++)
        #pragma unroll
        for (int j = 0; j < 8; j++)
            #pragma unroll
            for (int q = 0; q < 4; q++) acc[mi][j][q] = 0.f;

    const int niter = K >> 5;
    float4 ra[4];
    uint4 rbh[2], rbl[2];

    {
        if (aValid) {
            const float4* p = (const float4*)(A + (size_t)gm * K + akoff);
            ra[0] = p[0]; ra[1] = p[1]; ra[2] = p[2]; ra[3] = p[3];
        } else {
            ra[0] = ra[1] = ra[2] = ra[3] = make_float4(0.f, 0.f, 0.f, 0.f);
        }
        const uint4* ph = (const uint4*)(Bh + (size_t)bk * N + colBase + bnoff);
        const uint4* pl = (const uint4*)(Bl + (size_t)bk * N + colBase + bnoff);
        rbh[0] = ph[0]; rbh[1] = ph[1];
        rbl[0] = pl[0]; rbl[1] = pl[1];
    }
    {
        uint32_t h[4], l[4];
        #pragma unroll
        for (int cc = 0; cc < 2; cc++) {
            int c = (tid & 1) * 2 + cc;
            cvt_chunk(ra[cc * 2], ra[cc * 2 + 1], h, l);
            int p = c ^ ((am >> 1) & 3);
            int off = am * 64 + p * 16;
            *(uint4*)(dsm + GB_AHI + off) = make_uint4(h[0], h[1], h[2], h[3]);
            *(uint4*)(dsm + GB_ALO + off) = make_uint4(l[0], l[1], l[2], l[3]);
        }
        #pragma unroll
        for (int cc = 0; cc < 2; cc++) {
            int c = (tid & 7) * 2 + cc;
            int p = c ^ (bk & 7);
            int off = bk * 256 + p * 16;
            *(uint4*)(dsm + GB_BHI + off) = rbh[cc];
            *(uint4*)(dsm + GB_BLO + off) = rbl[cc];
        }
    }
    __syncthreads();

    for (int it = 0; it < niter; it++) {
        const uint32_t bufA_h = sb + (it & 1) * GB_BUF + GB_AHI;
        const uint32_t bufA_l = sb + (it & 1) * GB_BUF + GB_ALO;
        const uint32_t bufB_h = sb + (it & 1) * GB_BUF + GB_BHI;
        const uint32_t bufB_l = sb + (it & 1) * GB_BUF + GB_BLO;

        if (it + 1 < niter) {
            int kt = (it + 1) * 32;
            if (aValid) {
                const float4* p = (const float4*)(A + (size_t)gm * K + kt + akoff);
                ra[0] = p[0]; ra[1] = p[1]; ra[2] = p[2]; ra[3] = p[3];
            }
            const uint4* ph = (const uint4*)(Bh + (size_t)(kt + bk) * N + colBase + bnoff);
            const uint4* pl = (const uint4*)(Bl + (size_t)(kt + bk) * N + colBase + bnoff);
            rbh[0] = ph[0]; rbh[1] = ph[1];
            rbl[0] = pl[0]; rbl[1] = pl[1];
        }

        #pragma unroll
        for (int s = 0; s < 2; s++) {
            uint32_t Ah[2][4], Al[2][4];
            #pragma unroll
            for (int mi = 0; mi < 2; mi++) {
                int m0 = warpM + mi * 16 + (lane & 15);
                int c = 2 * s + (lane >> 4);
                int p = c ^ ((m0 >> 1) & 3);
                uint32_t off = (uint32_t)(m0 * 64 + p * 16);
                ldsm4(bufA_h + off, Ah[mi]);
                ldsm4(bufA_l + off, Al[mi]);
            }
            uint32_t Bhf[4][4], Blf[4][4];
            #pragma unroll
            for (int nb = 0; nb < 4; nb++) {
                int k = s * 16 + (lane & 15);
                int nc = (warpN >> 3) + nb * 2 + (lane >> 4);
                int p = nc ^ (k & 7);
                uint32_t off = (uint32_t)(k * 256 + p * 16);
                ldsm4t(bufB_h + off, Bhf[nb]);
                ldsm4t(bufB_l + off, Blf[nb]);
            }
            #pragma unroll
            for (int mi = 0; mi < 2; mi++)
                #pragma unroll
                for (int nb = 0; nb < 4; nb++)
                    #pragma unroll
                    for (int h = 0; h < 2; h++) {
                        float* c = acc[mi][nb * 2 + h];
                        mma16816(c, Ah[mi], &Bhf[nb][h * 2]);
                        mma16816(c, Ah[mi], &Blf[nb][h * 2]);
                        mma16816(c, Al[mi], &Bhf[nb][h * 2]);
                    }
        }

        if (it + 1 < niter) {
            char* nb = dsm + ((it + 1) & 1) * GB_BUF;
            uint32_t h[4], l[4];
            #pragma unroll
            for (int cc = 0; cc < 2; cc++) {
                int c = (tid & 1) * 2 + cc;
                cvt_chunk(ra[cc * 2], ra[cc * 2 + 1], h, l);
                int p = c ^ ((am >> 1) & 3);
                int off = am * 64 + p * 16;
                *(uint4*)(nb + GB_AHI + off) = make_uint4(h[0], h[1], h[2], h[3]);
                *(uint4*)(nb + GB_ALO + off) = make_uint4(l[0], l[1], l[2], l[3]);
            }
            #pragma unroll
            for (int cc = 0; cc < 2; cc++) {
                int c = (tid & 7) * 2 + cc;
                int p = c ^ (bk & 7);
                int off = bk * 256 + p * 16;
                *(uint4*)(nb + GB_BHI + off) = rbh[cc];
                *(uint4*)(nb + GB_BLO + off) = rbl[cc];
            }
        }
        __syncthreads();
    }

    #pragma unroll
    for (int mi = 0; mi < 2; mi++) {
        #pragma unroll
        for (int j = 0; j < 8; j++) {
            float* c = acc[mi][j];
            int gmr = rowBase + warpM + mi * 16 + (lane >> 2);
            int gn = colBase + warpN + j * 8 + (lane & 3) * 2;
            float b0 = 0.f, b1 = 0.f;
            if (bias) { b0 = bias[gn]; b1 = bias[gn + 1]; }
            float v0 = c[0] + b0, v1 = c[1] + b1, v2 = c[2] + b0, v3 = c[3] + b1;
            if (doRelu) {
                v0 = fmaxf(v0, 0.f); v1 = fmaxf(v1, 0.f);
                v2 = fmaxf(v2, 0.f); v3 = fmaxf(v3, 0.f);
            }
            if (gmr < M)     *(float2*)&C[(size_t)gmr * N + gn]       = make_float2(v0, v1);
            if (gmr + 8 < M) *(float2*)&C[(size_t)(gmr + 8) * N + gn] = make_float2(v2, v3);
        }
    }
}

__global__ void __launch_bounds__(256)
k_gemm_pre(const float* __restrict__ x, const float* __restrict__ b_pre)
{
    gemm_bf16s(x, g_WpH, g_WpL, b_pre, g_hpre, NNODES, HID, DIN, 1);
}

__global__ void __launch_bounds__(256)
k_gemm_h1()
{
    gemm_bf16s(g_hpre, g_W1H, g_W1L, nullptr, g_h1, NNODES, C1, HID, 0);
}

// ---------------- alpha for layer 1 ----------------
__global__ void k_alpha1(const float* __restrict__ a_src1, const float* __restrict__ a_dst1) {
    int node = blockIdx.x * 8 + (threadIdx.x >> 5);
    int lane = threadIdx.x & 31;
    const float* hrow = &g_h1[(size_t)node * C1];
    float s0 = 0.f, s1 = 0.f, d0 = 0.f, d1 = 0.f;
    #pragma unroll
    for (int k = 0; k < 8; k++) {
        int c = lane + 32 * k;
        float v = hrow[c];
        float as = a_src1[c], ad = a_dst1[c];
        if (k < 4) { s0 += v * as; d0 += v * ad; }
        else       { s1 += v * as; d1 += v * ad; }
    }
    #pragma unroll
    for (int o = 16; o; o >>= 1) {
        s0 += __shfl_xor_sync(0xffffffffu, s0, o);
        s1 += __shfl_xor_sync(0xffffffffu, s1, o);
        d0 += __shfl_xor_sync(0xffffffffu, d0, o);
        d1 += __shfl_xor_sync(0xffffffffu, d1, o);
    }
    if (lane == 0) {
        g_asrc1[node * 2 + 0] = s0; g_asrc1[node * 2 + 1] = s1;
        g_adst1[node * 2 + 0] = d0; g_adst1[node * 2 + 1] = d1;
    }
}

__device__ __forceinline__ float lrelu(float e) { return e > 0.f ? e : 0.2f * e; }

// ---------------- GAT1 aggregation: lane owns 8 contiguous cols ----------------
__global__ void k_agg1(const float* __restrict__ b1) {
    int node = blockIdx.x * 8 + (threadIdx.x >> 5);
    int lane = threadIdx.x & 31;
    if (lane == 0) g_cnt[node] = 0;   // restore zero-invariant for next call
    int beg = g_off[node], end = g_off[node + 1];
    float2 ad = *(const float2*)&g_adst1[node * 2];

    // pass 1: max per head
    float m0 = -1e30f, m1 = -1e30f;
    for (int j = beg + lane; j < end; j += 32) {
        int s = g_esrc[j];
        float2 as = *(const float2*)&g_asrc1[s * 2];
        m0 = fmaxf(m0, lrelu(as.x + ad.x));
        m1 = fmaxf(m1, lrelu(as.y + ad.y));
    }
    #pragma unroll
    for (int o = 16; o; o >>= 1) {
        m0 = fmaxf(m0, __shfl_xor_sync(0xffffffffu, m0, o));
        m1 = fmaxf(m1, __shfl_xor_sync(0xffffffffu, m1, o));
    }

    const int head = lane >> 4;          // cols [lane*8, lane*8+8) -> head = lane/16
    const float adh = head ? ad.y : ad.x;
    const float mh  = head ? m1 : m0;

    float4 a0 = make_float4(0.f, 0.f, 0.f, 0.f);
    float4 a1 = make_float4(0.f, 0.f, 0.f, 0.f);
    float ssum = 0.f;
    for (int j = beg; j < end; j++) {
        int s = g_esrc[j];
        float2 as = *(const float2*)&g_asrc1[s * 2];
        float p = expf(lrelu((head ? as.y : as.x) + adh) - mh);
        ssum += p;
        const float4* hr = (const float4*)&g_h1[(size_t)s * C1 + lane * 8];
        float4 v0 = hr[0], v1 = hr[1];
        a0.x += v0.x * p; a0.y += v0.y * p; a0.z += v0.z * p; a0.w += v0.w * p;
        a1.x += v1.x * p; a1.y += v1.y * p; a1.z += v1.z * p; a1.w += v1.w * p;
    }
    float inv = 1.f / (ssum + 1e-16f);
    int c = lane * 8;
    float4 bb0 = *(const float4*)&b1[c];
    float4 bb1 = *(const float4*)&b1[c + 4];
    float4 r0, r1;
    float o;
    o = a0.x * inv + bb0.x; r0.x = (o > 0.f) ? o : expm1f(o);
    o = a0.y * inv + bb0.y; r0.y = (o > 0.f) ? o : expm1f(o);
    o = a0.z * inv + bb0.z; r0.z = (o > 0.f) ? o : expm1f(o);
    o = a0.w * inv + bb0.w; r0.w = (o > 0.f) ? o : expm1f(o);
    o = a1.x * inv + bb1.x; r1.x = (o > 0.f) ? o : expm1f(o);
    o = a1.y * inv + bb1.y; r1.y = (o > 0.f) ? o : expm1f(o);
    o = a1.z * inv + bb1.z; r1.z = (o > 0.f) ? o : expm1f(o);
    o = a1.w * inv + bb1.w; r1.w = (o > 0.f) ? o : expm1f(o);
    *(float4*)&g_h1out[(size_t)node * C1 + c]     = r0;
    *(float4*)&g_h1out[(size_t)node * C1 + c + 4] = r1;
}

// ---------------- layer 2 transform + alpha ----------------
__global__ void k_gemm2(const float* __restrict__ W2, const float* __restrict__ a_src2,
                        const float* __restrict__ a_dst2) {
    __shared__ float sW[C1 * NC];
    __shared__ float sa[NC], sd[NC];
    int tid = threadIdx.x;
    *(float4*)&sW[tid * 4] = *(const float4*)&W2[tid * 4];
    if (tid < NC) { sa[tid] = a_src2[tid]; sd[tid] = a_dst2[tid]; }
    __syncthreads();

    int node = blockIdx.x * 8 + (tid >> 5);
    int lane = tid & 31;
    const float* hrow = &g_h1out[(size_t)node * C1];
    float a0 = 0.f, a1 = 0.f, a2 = 0.f, a3 = 0.f;
    #pragma unroll
    for (int k = 0; k < 8; k++) {
        int c = lane + 32 * k;
        float v = hrow[c];
        a0 += v * sW[c * 4 + 0];
        a1 += v * sW[c * 4 + 1];
        a2 += v * sW[c * 4 + 2];
        a3 += v * sW[c * 4 + 3];
    }
    #pragma unroll
    for (int o = 16; o; o >>= 1) {
        a0 += __shfl_xor_sync(0xffffffffu, a0, o);
        a1 += __shfl_xor_sync(0xffffffffu, a1, o);
        a2 += __shfl_xor_sync(0xffffffffu, a2, o);
        a3 += __shfl_xor_sync(0xffffffffu, a3, o);
    }
    if (lane == 0) {
        g_h2[node * 4 + 0] = a0; g_h2[node * 4 + 1] = a1;
        g_h2[node * 4 + 2] = a2; g_h2[node * 4 + 3] = a3;
        g_asrc2[node] = a0 * sa[0] + a1 * sa[1] + a2 * sa[2] + a3 * sa[3];
        g_adst2[node] = a0 * sd[0] + a1 * sd[1] + a2 * sd[2] + a3 * sd[3];
    }
}

// ---------------- GAT2 aggregation ----------------
__global__ void k_agg2(const float* __restrict__ b2, float* __restrict__ out) {
    int node = blockIdx.x * 8 + (threadIdx.x >> 5);
    int lane = threadIdx.x & 31;
    int beg = g_off[node], end = g_off[node + 1];
    float ad = g_adst2[node];

    float m = -1e30f;
    for (int j = beg + lane; j < end; j += 32)
        m = fmaxf(m, lrelu(g_asrc2[g_esrc[j]] + ad));
    #pragma unroll
    for (int o = 16; o; o >>= 1)
        m = fmaxf(m, __shfl_xor_sync(0xffffffffu, m, o));

    float ss = 0.f, c0 = 0.f, c1 = 0.f, c2 = 0.f, c3 = 0.f;
    for (int j = beg + lane; j < end; j += 32) {
        int s = g_esrc[j];
        float p = expf(lrelu(g_asrc2[s] + ad) - m);
        ss += p;
        float4 h = *(const float4*)&g_h2[s * 4];
        c0 += h.x * p; c1 += h.y * p; c2 += h.z * p; c3 += h.w * p;
    }
    #pragma unroll
    for (int o = 16; o; o >>= 1) {
        ss += __shfl_xor_sync(0xffffffffu, ss, o);
        c0 += __shfl_xor_sync(0xffffffffu, c0, o);
        c1 += __shfl_xor_sync(0xffffffffu, c1, o);
        c2 += __shfl_xor_sync(0xffffffffu, c2, o);
        c3 += __shfl_xor_sync(0xffffffffu, c3, o);
    }
    if (lane == 0) {
        float inv = 1.f / (ss + 1e-16f);
        out[node * 4 + 0] = c0 * inv + b2[0];
        out[node * 4 + 1] = c1 * inv + b2[1];
        out[node * 4 + 2] = c2 * inv + b2[2];
        out[node * 4 + 3] = c3 * inv + b2[3];
    }
}

// ---------------- launch ----------------
extern "C" void kernel_launch(void* const* d_in, const int* in_sizes, int n_in,
                              void* d_out, int out_size) {
    const float* x      = (const float*)d_in[0];
    const int*   ei     = (const int*)d_in[1];
    const float* W_pre  = (const float*)d_in[2];
    const float* b_pre  = (const float*)d_in[3];
    const float* W1     = (const float*)d_in[4];
    const float* a_src1 = (const float*)d_in[5];
    const float* a_dst1 = (const float*)d_in[6];
    const float* b1     = (const float*)d_in[7];
    const float* W2     = (const float*)d_in[8];
    const float* a_src2 = (const float*)d_in[9];
    const float* a_dst2 = (const float*)d_in[10];
    const float* b2     = (const float*)d_in[11];
    float* out = (float*)d_out;

    // one-time host resources (no device memory; identical GPU work every call)
    static cudaStream_t s1 = nullptr;
    static cudaEvent_t eFork = nullptr, eJoin = nullptr;
    if (s1 == nullptr) {
        cudaStreamCreateWithFlags(&s1, cudaStreamNonBlocking);
        cudaEventCreateWithFlags(&eFork, cudaEventDisableTiming);
        cudaEventCreateWithFlags(&eJoin, cudaEventDisableTiming);
    }
    cudaFuncSetAttribute(k_gemm_pre, cudaFuncAttributeMaxDynamicSharedMemorySize, GB_SMEM);
    cudaFuncSetAttribute(k_gemm_h1,  cudaFuncAttributeMaxDynamicSharedMemorySize, GB_SMEM);

    const int NB = (NNODES + 255) / 256;   // 196

    // ---- fork: CSR chain on s1, GEMM chain on main stream ----
    cudaEventRecord(eFork, 0);
    cudaStreamWaitEvent(s1, eFork, 0);

    k_count<<<(NEDGE + 255) / 256, 256, 0, s1>>>(ei);
    k_scanA<<<NB, 256, 0, s1>>>();
    k_scanB<<<1, 256, 0, s1>>>(NB);
    k_scanC<<<NB, 256, 0, s1>>>();
    k_scatter<<<(NTOT + 255) / 256, 256, 0, s1>>>(ei);
    cudaEventRecord(eJoin, s1);

    // main stream: weights + GEMMs + alpha
    k_prepW<<<(DIN * HID + HID * C1 + 255) / 256, 256>>>(W_pre, W1);
    {
        dim3 grid(1, (NNODES + 127) / 128);
        k_gemm_pre<<<grid, 256, GB_SMEM>>>(x, b_pre);
    }
    {
        dim3 grid(2, (NNODES + 127) / 128);
        k_gemm_h1<<<grid, 256, GB_SMEM>>>();
    }
    k_alpha1<<<NNODES / 8, 256>>>(a_src1, a_dst1);

    // ---- join: aggregation needs the CSR ----
    cudaStreamWaitEvent(0, eJoin, 0);
    k_agg1<<<NNODES / 8, 256>>>(b1);
    k_gemm2<<<NNODES / 8, 256>>>(W2, a_src2, a_dst2);
    k_agg2<<<NNODES / 8, 256>>>(b2, out);
}

// round 9
// speedup vs baseline: 2.5756x; 1.0728x over previous
#include <cuda_runtime.h>
#include <cuda_bf16.h>
#include <math.h>
#include <stdint.h>

#define NNODES 50000
#define NEDGE  800000
#define NTOT   (NEDGE + NNODES)
#define DIN    1024
#define HID    128
#define C1     256   // HEADS*HID
#define NC     4

// ---------------- scratch (device globals; no allocation allowed) ----------------
__device__ float g_hpre[(size_t)NNODES * HID];
__device__ __align__(16) __nv_bfloat16 g_h1b[(size_t)NNODES * C1];  // bf16 messages
__device__ float g_h1out[(size_t)NNODES * C1];
__device__ float g_asrc1[NNODES * 2];   // atomic-accumulated in gemm_h1 epilogue
__device__ float g_adst1[NNODES * 2];
__device__ float g_h2[NNODES * NC];
__device__ float g_asrc2[NNODES];
__device__ float g_adst2[NNODES];
__device__ int   g_cnt[NNODES];     // invariant: zero at kernel_launch entry
__device__ int   g_off[NNODES + 1];
__device__ int   g_esrc[NTOT];
__device__ int   g_bsum[256];
// pre-split bf16 weight planes ([K][N] row-major, same layout as fp32 weights)
__device__ __align__(16) __nv_bfloat16 g_WpH[DIN * HID];
__device__ __align__(16) __nv_bfloat16 g_WpL[DIN * HID];
__device__ __align__(16) __nv_bfloat16 g_W1H[HID * C1];
__device__ __align__(16) __nv_bfloat16 g_W1L[HID * C1];

__device__ __forceinline__ int clampN(int v) {
    return v < 0 ? 0 : (v >= NNODES ? NNODES - 1 : v);
}

// ---------------- CSR build ----------------
__global__ void k_count(const int* __restrict__ ei) {
    int e = blockIdx.x * blockDim.x + threadIdx.x;
    if (e < NEDGE) {
        int dst = clampN(ei[NEDGE + e]);
        atomicAdd(&g_cnt[dst], 1);
    }
}

__global__ void k_scanA() {
    __shared__ int wsum[8];
    int i = blockIdx.x * 256 + threadIdx.x;
    int lane = threadIdx.x & 31, w = threadIdx.x >> 5;
    int v = (i < NNODES) ? (g_cnt[i] + 1) : 0;   // +1 = self-loop
    if (i < NNODES) g_cnt[i] = 0;                // becomes scatter cursor
    int x = v;
    #pragma unroll
    for (int o = 1; o < 32; o <<= 1) {
        int t = __shfl_up_sync(0xffffffffu, x, o);
        if (lane >= o) x += t;
    }
    if (lane == 31) wsum[w] = x;
    __syncthreads();
    if (w == 0 && lane < 8) {
        int s = wsum[lane];
        #pragma unroll
        for (int o = 1; o < 8; o <<= 1) {
            int t = __shfl_up_sync(0xffu, s, o);
            if (lane >= o) s += t;
        }
        wsum[lane] = s;
    }
    __syncthreads();
    int pre = (w > 0) ? wsum[w - 1] : 0;
    if (i < NNODES) g_off[i] = pre + x - v;
    if (threadIdx.x == 255) g_bsum[blockIdx.x] = pre + x;
}

__global__ void k_scanB(int nblk) {
    __shared__ int wsum[8];
    int t = threadIdx.x;
    int lane = t & 31, w = t >> 5;
    int v = (t < nblk) ? g_bsum[t] : 0;
    int x = v;
    #pragma unroll
    for (int o = 1; o < 32; o <<= 1) {
        int q = __shfl_up_sync(0xffffffffu, x, o);
        if (lane >= o) x += q;
    }
    if (lane == 31) wsum[w] = x;
    __syncthreads();
    if (w == 0 && lane < 8) {
        int s = wsum[lane];
        #pragma unroll
        for (int o = 1; o < 8; o <<= 1) {
            int q = __shfl_up_sync(0xffu, s, o);
            if (lane >= o) s += q;
        }
        wsum[lane] = s;
    }
    __syncthreads();
    int pre = (w > 0) ? wsum[w - 1] : 0;
    if (t < nblk) g_bsum[t] = pre + x - v;
    if (t == 255) g_off[NNODES] = pre + x;
}

__global__ void k_scanC() {
    int i = blockIdx.x * 256 + threadIdx.x;
    if (i < NNODES) g_off[i] += g_bsum[blockIdx.x];
}

__global__ void k_scatter(const int* __restrict__ ei) {
    int e = blockIdx.x * blockDim.x + threadIdx.x;
    if (e >= NTOT) return;
    int src, dst;
    if (e < NEDGE) { src = clampN(ei[e]); dst = clampN(ei[NEDGE + e]); }
    else           { src = e - NEDGE; dst = src; }
    int pos = g_off[dst] + atomicAdd(&g_cnt[dst], 1);
    g_esrc[pos] = src;
}

// ================= bf16 split helpers =================
__device__ __forceinline__ uint32_t packbf(float v0, float v1) {
    uint32_t r;
    asm("cvt.rn.bf16x2.f32 %0, %1, %2;" : "=r"(r) : "f"(v1), "f"(v0));
    return r;
}
__device__ __forceinline__ float bflowf(uint32_t p)  { return __uint_as_float(p << 16); }
__device__ __forceinline__ float bfhighf(uint32_t p) { return __uint_as_float(p & 0xffff0000u); }

__device__ __forceinline__ void cvt_chunk(float4 x, float4 y, uint32_t* h, uint32_t* l) {
    h[0] = packbf(x.x, x.y); h[1] = packbf(x.z, x.w);
    h[2] = packbf(y.x, y.y); h[3] = packbf(y.z, y.w);
    l[0] = packbf(x.x - bflowf(h[0]), x.y - bfhighf(h[0]));
    l[1] = packbf(x.z - bflowf(h[1]), x.w - bfhighf(h[1]));
    l[2] = packbf(y.x - bflowf(h[2]), y.y - bfhighf(h[2]));
    l[3] = packbf(y.z - bflowf(h[3]), y.w - bfhighf(h[3]));
}

// weight split + zero alpha accumulators (every call, before gemm_h1)
#define PREP_N (DIN * HID + HID * C1 + 4 * NNODES)
__global__ void k_prepW(const float* __restrict__ Wp, const float* __restrict__ W1) {
    int i = blockIdx.x * blockDim.x + threadIdx.x;
    if (i < DIN * HID) {
        float v = Wp[i];
        __nv_bfloat16 h = __float2bfloat16(v);
        g_WpH[i] = h;
        g_WpL[i] = __float2bfloat16(v - __bfloat162float(h));
        return;
    }
    int j = i - DIN * HID;
    if (j < HID * C1) {
        float v = W1[j];
        __nv_bfloat16 h = __float2bfloat16(v);
        g_W1H[j] = h;
        g_W1L[j] = __float2bfloat16(v - __bfloat162float(h));
        return;
    }
    j -= HID * C1;
    if (j < 2 * NNODES) { g_asrc1[j] = 0.f; return; }
    j -= 2 * NNODES;
    if (j < 2 * NNODES) g_adst1[j] = 0.f;
}

// ================= mma.sync split-bf16 GEMM, double-buffered =================
__device__ __forceinline__ void ldsm4(uint32_t addr, uint32_t* r) {
    asm volatile("ldmatrix.sync.aligned.m8n8.x4.shared.b16 {%0,%1,%2,%3},[%4];"
        : "=r"(r[0]), "=r"(r[1]), "=r"(r[2]), "=r"(r[3]) : "r"(addr));
}
__device__ __forceinline__ void ldsm4t(uint32_t addr, uint32_t* r) {
    asm volatile("ldmatrix.sync.aligned.m8n8.x4.trans.shared.b16 {%0,%1,%2,%3},[%4];"
        : "=r"(r[0]), "=r"(r[1]), "=r"(r[2]), "=r"(r[3]) : "r"(addr));
}
__device__ __forceinline__ void mma16816(float* c, const uint32_t* a, const uint32_t* b) {
    asm volatile(
        "mma.sync.aligned.m16n8k16.row.col.f32.bf16.bf16.f32 "
        "{%0,%1,%2,%3},{%4,%5,%6,%7},{%8,%9},{%0,%1,%2,%3};"
        : "+f"(c[0]), "+f"(c[1]), "+f"(c[2]), "+f"(c[3])
        : "r"(a[0]), "r"(a[1]), "r"(a[2]), "r"(a[3]), "r"(b[0]), "r"(b[1]));
}

// smem plan per buffer (32KB): A_hi 8K | A_lo 8K | B_hi 8K | B_lo 8K; 2 buffers
#define GB_BUF 32768
#define GB_AHI 0
#define GB_ALO 8192
#define GB_BHI 16384
#define GB_BLO 24576
#define GB_SMEM (2 * GB_BUF)

// MODE 0: C = fp32, + bias + relu.
// MODE 1: write g_h1b (bf16) + atomic alpha partials into g_asrc1/g_adst1.
template <int MODE>
__device__ __forceinline__ void gemm_bf16s(
    const float* __restrict__ A,
    const __nv_bfloat16* __restrict__ Bh, const __nv_bfloat16* __restrict__ Bl,
    const float* __restrict__ bias, float* __restrict__ C,
    const float* __restrict__ asrc, const float* __restrict__ adst,
    int M, int N, int K)
{
    extern __shared__ __align__(16) char dsm[];
    const uint32_t sb = (uint32_t)__cvta_generic_to_shared(dsm);

    const int tid = threadIdx.x;
    const int lane = tid & 31;
    const int warp = tid >> 5;
    const int warpM = (warp & 3) * 32;
    const int warpN = (warp >> 2) * 64;
    const int rowBase = blockIdx.y * 128;
    const int colBase = blockIdx.x * 128;

    const int am = tid >> 1;
    const int akoff = (tid & 1) * 16;
    const int bk = tid >> 3;
    const int bnoff = (tid & 7) * 16;
    const int gm = rowBase + am;
    const bool aValid = gm < M;

    float acc[2][8][4];
    #pragma unroll
    for (int mi = 0; mi < 2; mi++)
        #pragma unroll
        for (int j = 0; j < 8; j++)
            #pragma unroll
            for (int q = 0; q < 4; q++) acc[mi][j][q] = 0.f;

    const int niter = K >> 5;
    float4 ra[4];
    uint4 rbh[2], rbl[2];

    {
        if (aValid) {
            const float4* p = (const float4*)(A + (size_t)gm * K + akoff);
            ra[0] = p[0]; ra[1] = p[1]; ra[2] = p[2]; ra[3] = p[3];
        } else {
            ra[0] = ra[1] = ra[2] = ra[3] = make_float4(0.f, 0.f, 0.f, 0.f);
        }
        const uint4* ph = (const uint4*)(Bh + (size_t)bk * N + colBase + bnoff);
        const uint4* pl = (const uint4*)(Bl + (size_t)bk * N + colBase + bnoff);
        rbh[0] = ph[0]; rbh[1] = ph[1];
        rbl[0] = pl[0]; rbl[1] = pl[1];
    }
    {
        uint32_t h[4], l[4];
        #pragma unroll
        for (int cc = 0; cc < 2; cc++) {
            int c = (tid & 1) * 2 + cc;
            cvt_chunk(ra[cc * 2], ra[cc * 2 + 1], h, l);
            int p = c ^ ((am >> 1) & 3);
            int off = am * 64 + p * 16;
            *(uint4*)(dsm + GB_AHI + off) = make_uint4(h[0], h[1], h[2], h[3]);
            *(uint4*)(dsm + GB_ALO + off) = make_uint4(l[0], l[1], l[2], l[3]);
        }
        #pragma unroll
        for (int cc = 0; cc < 2; cc++) {
            int c = (tid & 7) * 2 + cc;
            int p = c ^ (bk & 7);
            int off = bk * 256 + p * 16;
            *(uint4*)(dsm + GB_BHI + off) = rbh[cc];
            *(uint4*)(dsm + GB_BLO + off) = rbl[cc];
        }
    }
    __syncthreads();

    for (int it = 0; it < niter; it++) {
        const uint32_t bufA_h = sb + (it & 1) * GB_BUF + GB_AHI;
        const uint32_t bufA_l = sb + (it & 1) * GB_BUF + GB_ALO;
        const uint32_t bufB_h = sb + (it & 1) * GB_BUF + GB_BHI;
        const uint32_t bufB_l = sb + (it & 1) * GB_BUF + GB_BLO;

        if (it + 1 < niter) {
            int kt = (it + 1) * 32;
            if (aValid) {
                const float4* p = (const float4*)(A + (size_t)gm * K + kt + akoff);
                ra[0] = p[0]; ra[1] = p[1]; ra[2] = p[2]; ra[3] = p[3];
            }
            const uint4* ph = (const uint4*)(Bh + (size_t)(kt + bk) * N + colBase + bnoff);
            const uint4* pl = (const uint4*)(Bl + (size_t)(kt + bk) * N + colBase + bnoff);
            rbh[0] = ph[0]; rbh[1] = ph[1];
            rbl[0] = pl[0]; rbl[1] = pl[1];
        }

        #pragma unroll
        for (int s = 0; s < 2; s++) {
            uint32_t Ah[2][4], Al[2][4];
            #pragma unroll
            for (int mi = 0; mi < 2; mi++) {
                int m0 = warpM + mi * 16 + (lane & 15);
                int c = 2 * s + (lane >> 4);
                int p = c ^ ((m0 >> 1) & 3);
                uint32_t off = (uint32_t)(m0 * 64 + p * 16);
                ldsm4(bufA_h + off, Ah[mi]);
                ldsm4(bufA_l + off, Al[mi]);
            }
            uint32_t Bhf[4][4], Blf[4][4];
            #pragma unroll
            for (int nb = 0; nb < 4; nb++) {
                int k = s * 16 + (lane & 15);
                int nc = (warpN >> 3) + nb * 2 + (lane >> 4);
                int p = nc ^ (k & 7);
                uint32_t off = (uint32_t)(k * 256 + p * 16);
                ldsm4t(bufB_h + off, Bhf[nb]);
                ldsm4t(bufB_l + off, Blf[nb]);
            }
            #pragma unroll
            for (int mi = 0; mi < 2; mi++)
                #pragma unroll
                for (int nb = 0; nb < 4; nb++)
                    #pragma unroll
                    for (int h = 0; h < 2; h++) {
                        float* c = acc[mi][nb * 2 + h];
                        mma16816(c, Ah[mi], &Bhf[nb][h * 2]);
                        mma16816(c, Ah[mi], &Blf[nb][h * 2]);
                        mma16816(c, Al[mi], &Bhf[nb][h * 2]);
                    }
        }

        if (it + 1 < niter) {
            char* nb = dsm + ((it + 1) & 1) * GB_BUF;
            uint32_t h[4], l[4];
            #pragma unroll
            for (int cc = 0; cc < 2; cc++) {
                int c = (tid & 1) * 2 + cc;
                cvt_chunk(ra[cc * 2], ra[cc * 2 + 1], h, l);
                int p = c ^ ((am >> 1) & 3);
                int off = am * 64 + p * 16;
                *(uint4*)(nb + GB_AHI + off) = make_uint4(h[0], h[1], h[2], h[3]);
                *(uint4*)(nb + GB_ALO + off) = make_uint4(l[0], l[1], l[2], l[3]);
            }
            #pragma unroll
            for (int cc = 0; cc < 2; cc++) {
                int c = (tid & 7) * 2 + cc;
                int p = c ^ (bk & 7);
                int off = bk * 256 + p * 16;
                *(uint4*)(nb + GB_BHI + off) = rbh[cc];
                *(uint4*)(nb + GB_BLO + off) = rbl[cc];
            }
        }
        __syncthreads();
    }

    // ---- epilogue ----
    if (MODE == 0) {
        #pragma unroll
        for (int mi = 0; mi < 2; mi++) {
            #pragma unroll
            for (int j = 0; j < 8; j++) {
                float* c = acc[mi][j];
                int gmr = rowBase + warpM + mi * 16 + (lane >> 2);
                int gn = colBase + warpN + j * 8 + (lane & 3) * 2;
                float b0 = bias[gn], b1 = bias[gn + 1];
                float v0 = fmaxf(c[0] + b0, 0.f), v1 = fmaxf(c[1] + b1, 0.f);
                float v2 = fmaxf(c[2] + b0, 0.f), v3 = fmaxf(c[3] + b1, 0.f);
                if (gmr < M)     *(float2*)&C[(size_t)gmr * N + gn]       = make_float2(v0, v1);
                if (gmr + 8 < M) *(float2*)&C[(size_t)(gmr + 8) * N + gn] = make_float2(v2, v3);
            }
        }
    } else {
        // bf16 message write + fused alpha dot (atomic partials)
        const int head = (colBase + warpN) >> 7;
        #pragma unroll
        for (int mi = 0; mi < 2; mi++) {
            int gmr = rowBase + warpM + mi * 16 + (lane >> 2);
            float ps0 = 0.f, pd0 = 0.f, ps1 = 0.f, pd1 = 0.f;
            #pragma unroll
            for (int j = 0; j < 8; j++) {
                float* c = acc[mi][j];
                int gn = colBase + warpN + j * 8 + (lane & 3) * 2;
                float as0 = __ldg(&asrc[gn]), as1 = __ldg(&asrc[gn + 1]);
                float ad0 = __ldg(&adst[gn]), ad1 = __ldg(&adst[gn + 1]);
                ps0 += c[0] * as0 + c[1] * as1;
                pd0 += c[0] * ad0 + c[1] * ad1;
                ps1 += c[2] * as0 + c[3] * as1;
                pd1 += c[2] * ad0 + c[3] * ad1;
                if (gmr < M)
                    *(uint32_t*)&g_h1b[(size_t)gmr * C1 + gn] = packbf(c[0], c[1]);
                if (gmr + 8 < M)
                    *(uint32_t*)&g_h1b[(size_t)(gmr + 8) * C1 + gn] = packbf(c[2], c[3]);
            }
            #pragma unroll
            for (int o = 1; o < 4; o <<= 1) {
                ps0 += __shfl_xor_sync(0xffffffffu, ps0, o);
                pd0 += __shfl_xor_sync(0xffffffffu, pd0, o);
                ps1 += __shfl_xor_sync(0xffffffffu, ps1, o);
                pd1 += __shfl_xor_sync(0xffffffffu, pd1, o);
            }
            if ((lane & 3) == 0) {
                if (gmr < M) {
                    atomicAdd(&g_asrc1[gmr * 2 + head], ps0);
                    atomicAdd(&g_adst1[gmr * 2 + head], pd0);
                }
                if (gmr + 8 < M) {
                    atomicAdd(&g_asrc1[(gmr + 8) * 2 + head], ps1);
                    atomicAdd(&g_adst1[(gmr + 8) * 2 + head], pd1);
                }
            }
        }
    }
}

__global__ void __launch_bounds__(256)
k_gemm_pre(const float* __restrict__ x, const float* __restrict__ b_pre)
{
    gemm_bf16s<0>(x, g_WpH, g_WpL, b_pre, g_hpre, nullptr, nullptr, NNODES, HID, DIN);
}

__global__ void __launch_bounds__(256)
k_gemm_h1(const float* __restrict__ a_src1, const float* __restrict__ a_dst1)
{
    gemm_bf16s<1>(g_hpre, g_W1H, g_W1L, nullptr, nullptr, a_src1, a_dst1, NNODES, C1, HID);
}

__device__ __forceinline__ float lrelu(float e) { return e > 0.f ? e : 0.2f * e; }

// ---------------- GAT1 aggregation: bf16 messages, lane owns 8 cols ----------------
__global__ void k_agg1(const float* __restrict__ b1) {
    int node = blockIdx.x * 8 + (threadIdx.x >> 5);
    int lane = threadIdx.x & 31;
    if (lane == 0) g_cnt[node] = 0;   // restore zero-invariant for next call
    int beg = g_off[node], end = g_off[node + 1];
    float2 ad = *(const float2*)&g_adst1[node * 2];

    // pass 1: max per head
    float m0 = -1e30f, m1 = -1e30f;
    for (int j = beg + lane; j < end; j += 32) {
        int s = g_esrc[j];
        float2 as = *(const float2*)&g_asrc1[s * 2];
        m0 = fmaxf(m0, lrelu(as.x + ad.x));
        m1 = fmaxf(m1, lrelu(as.y + ad.y));
    }
    #pragma unroll
    for (int o = 16; o; o >>= 1) {
        m0 = fmaxf(m0, __shfl_xor_sync(0xffffffffu, m0, o));
        m1 = fmaxf(m1, __shfl_xor_sync(0xffffffffu, m1, o));
    }

    const int head = lane >> 4;
    const float adh = head ? ad.y : ad.x;
    const float mh  = head ? m1 : m0;

    float4 a0 = make_float4(0.f, 0.f, 0.f, 0.f);
    float4 a1 = make_float4(0.f, 0.f, 0.f, 0.f);
    float ssum = 0.f;
    for (int j = beg; j < end; j++) {
        int s = g_esrc[j];
        float2 as = *(const float2*)&g_asrc1[s * 2];
        float p = expf(lrelu((head ? as.y : as.x) + adh) - mh);
        ssum += p;
        uint4 hv = *(const uint4*)&g_h1b[(size_t)s * C1 + lane * 8];
        a0.x += bflowf(hv.x) * p;  a0.y += bfhighf(hv.x) * p;
        a0.z += bflowf(hv.y) * p;  a0.w += bfhighf(hv.y) * p;
        a1.x += bflowf(hv.z) * p;  a1.y += bfhighf(hv.z) * p;
        a1.z += bflowf(hv.w) * p;  a1.w += bfhighf(hv.w) * p;
    }
    float inv = 1.f / (ssum + 1e-16f);
    int c = lane * 8;
    float4 bb0 = *(const float4*)&b1[c];
    float4 bb1 = *(const float4*)&b1[c + 4];
    float4 r0, r1;
    float o;
    o = a0.x * inv + bb0.x; r0.x = (o > 0.f) ? o : expm1f(o);
    o = a0.y * inv + bb0.y; r0.y = (o > 0.f) ? o : expm1f(o);
    o = a0.z * inv + bb0.z; r0.z = (o > 0.f) ? o : expm1f(o);
    o = a0.w * inv + bb0.w; r0.w = (o > 0.f) ? o : expm1f(o);
    o = a1.x * inv + bb1.x; r1.x = (o > 0.f) ? o : expm1f(o);
    o = a1.y * inv + bb1.y; r1.y = (o > 0.f) ? o : expm1f(o);
    o = a1.z * inv + bb1.z; r1.z = (o > 0.f) ? o : expm1f(o);
    o = a1.w * inv + bb1.w; r1.w = (o > 0.f) ? o : expm1f(o);
    *(float4*)&g_h1out[(size_t)node * C1 + c]     = r0;
    *(float4*)&g_h1out[(size_t)node * C1 + c + 4] = r1;
}

// ---------------- layer 2 transform + alpha ----------------
__global__ void k_gemm2(const float* __restrict__ W2, const float* __restrict__ a_src2,
                        const float* __restrict__ a_dst2) {
    __shared__ float sW[C1 * NC];
    __shared__ float sa[NC], sd[NC];
    int tid = threadIdx.x;
    *(float4*)&sW[tid * 4] = *(const float4*)&W2[tid * 4];
    if (tid < NC) { sa[tid] = a_src2[tid]; sd[tid] = a_dst2[tid]; }
    __syncthreads();

    int node = blockIdx.x * 8 + (tid >> 5);
    int lane = tid & 31;
    const float* hrow = &g_h1out[(size_t)node * C1];
    float a0 = 0.f, a1 = 0.f, a2 = 0.f, a3 = 0.f;
    #pragma unroll
    for (int k = 0; k < 8; k++) {
        int c = lane + 32 * k;
        float v = hrow[c];
        a0 += v * sW[c * 4 + 0];
        a1 += v * sW[c * 4 + 1];
        a2 += v * sW[c * 4 + 2];
        a3 += v * sW[c * 4 + 3];
    }
    #pragma unroll
    for (int o = 16; o; o >>= 1) {
        a0 += __shfl_xor_sync(0xffffffffu, a0, o);
        a1 += __shfl_xor_sync(0xffffffffu, a1, o);
        a2 += __shfl_xor_sync(0xffffffffu, a2, o);
        a3 += __shfl_xor_sync(0xffffffffu, a3, o);
    }
    if (lane == 0) {
        g_h2[node * 4 + 0] = a0; g_h2[node * 4 + 1] = a1;
        g_h2[node * 4 + 2] = a2; g_h2[node * 4 + 3] = a3;
        g_asrc2[node] = a0 * sa[0] + a1 * sa[1] + a2 * sa[2] + a3 * sa[3];
        g_adst2[node] = a0 * sd[0] + a1 * sd[1] + a2 * sd[2] + a3 * sd[3];
    }
}

// ---------------- GAT2 aggregation ----------------
__global__ void k_agg2(const float* __restrict__ b2, float* __restrict__ out) {
    int node = blockIdx.x * 8 + (threadIdx.x >> 5);
    int lane = threadIdx.x & 31;
    int beg = g_off[node], end = g_off[node + 1];
    float ad = g_adst2[node];

    float m = -1e30f;
    for (int j = beg + lane; j < end; j += 32)
        m = fmaxf(m, lrelu(g_asrc2[g_esrc[j]] + ad));
    #pragma unroll
    for (int o = 16; o; o >>= 1)
        m = fmaxf(m, __shfl_xor_sync(0xffffffffu, m, o));

    float ss = 0.f, c0 = 0.f, c1 = 0.f, c2 = 0.f, c3 = 0.f;
    for (int j = beg + lane; j < end; j += 32) {
        int s = g_esrc[j];
        float p = expf(lrelu(g_asrc2[s] + ad) - m);
        ss += p;
        float4 h = *(const float4*)&g_h2[s * 4];
        c0 += h.x * p; c1 += h.y * p; c2 += h.z * p; c3 += h.w * p;
    }
    #pragma unroll
    for (int o = 16; o; o >>= 1) {
        ss += __shfl_xor_sync(0xffffffffu, ss, o);
        c0 += __shfl_xor_sync(0xffffffffu, c0, o);
        c1 += __shfl_xor_sync(0xffffffffu, c1, o);
        c2 += __shfl_xor_sync(0xffffffffu, c2, o);
        c3 += __shfl_xor_sync(0xffffffffu, c3, o);
    }
    if (lane == 0) {
        float inv = 1.f / (ss + 1e-16f);
        out[node * 4 + 0] = c0 * inv + b2[0];
        out[node * 4 + 1] = c1 * inv + b2[1];
        out[node * 4 + 2] = c2 * inv + b2[2];
        out[node * 4 + 3] = c3 * inv + b2[3];
    }
}

// ---------------- launch ----------------
extern "C" void kernel_launch(void* const* d_in, const int* in_sizes, int n_in,
                              void* d_out, int out_size) {
    const float* x      = (const float*)d_in[0];
    const int*   ei     = (const int*)d_in[1];
    const float* W_pre  = (const float*)d_in[2];
    const float* b_pre  = (const float*)d_in[3];
    const float* W1     = (const float*)d_in[4];
    const float* a_src1 = (const float*)d_in[5];
    const float* a_dst1 = (const float*)d_in[6];
    const float* b1     = (const float*)d_in[7];
    const float* W2     = (const float*)d_in[8];
    const float* a_src2 = (const float*)d_in[9];
    const float* a_dst2 = (const float*)d_in[10];
    const float* b2     = (const float*)d_in[11];
    float* out = (float*)d_out;

    static cudaStream_t s1 = nullptr;
    static cudaEvent_t eFork = nullptr, eJoin = nullptr;
    if (s1 == nullptr) {
        cudaStreamCreateWithFlags(&s1, cudaStreamNonBlocking);
        cudaEventCreateWithFlags(&eFork, cudaEventDisableTiming);
        cudaEventCreateWithFlags(&eJoin, cudaEventDisableTiming);
    }
    cudaFuncSetAttribute(k_gemm_pre, cudaFuncAttributeMaxDynamicSharedMemorySize, GB_SMEM);
    cudaFuncSetAttribute(k_gemm_h1,  cudaFuncAttributeMaxDynamicSharedMemorySize, GB_SMEM);

    const int NB = (NNODES + 255) / 256;   // 196

    // ---- fork: CSR chain on s1, compute chain on main stream ----
    cudaEventRecord(eFork, 0);
    cudaStreamWaitEvent(s1, eFork, 0);

    k_count<<<(NEDGE + 255) / 256, 256, 0, s1>>>(ei);
    k_scanA<<<NB, 256, 0, s1>>>();
    k_scanB<<<1, 256, 0, s1>>>(NB);
    k_scanC<<<NB, 256, 0, s1>>>();
    k_scatter<<<(NTOT + 255) / 256, 256, 0, s1>>>(ei);
    cudaEventRecord(eJoin, s1);

    // main stream: weights+zeroing, GEMMs (alpha fused into gemm_h1 epilogue)
    k_prepW<<<(PREP_N + 255) / 256, 256>>>(W_pre, W1);
    {
        dim3 grid(1, (NNODES + 127) / 128);
        k_gemm_pre<<<grid, 256, GB_SMEM>>>(x, b_pre);
    }
    {
        dim3 grid(2, (NNODES + 127) / 128);
        k_gemm_h1<<<grid, 256, GB_SMEM>>>(a_src1, a_dst1);
    }

    // ---- join: aggregation needs the CSR ----
    cudaStreamWaitEvent(0, eJoin, 0);
    k_agg1<<<NNODES / 8, 256>>>(b1);
    k_gemm2<<<NNODES / 8, 256>>>(W2, a_src2, a_dst2);
    k_agg2<<<NNODES / 8, 256>>>(b2, out);
}

// round 13
// speedup vs baseline: 2.8691x; 1.1139x over previous
#include <cuda_runtime.h>
#include <cuda_bf16.h>
#include <math.h>
#include <stdint.h>

#define NNODES 50000
#define NEDGE  800000
#define NTOT   (NEDGE + NNODES)
#define DIN    1024
#define HID    128
#define C1     256   // HEADS*HID
#define NC     4

// ---------------- scratch (device globals; no allocation allowed) ----------------
__device__ float g_hpre[(size_t)NNODES * HID];
__device__ __align__(16) __nv_bfloat16 g_h1b[(size_t)NNODES * C1];  // bf16 messages
__device__ float g_h1out[(size_t)NNODES * C1];
__device__ float g_asrc1[NNODES * 2];   // written (plain stores) by gemm_h1 epilogue
__device__ float g_adst1[NNODES * 2];
__device__ float g_h2[NNODES * NC];
__device__ float g_asrc2[NNODES];
__device__ float g_adst2[NNODES];
__device__ int   g_cnt[NNODES];     // invariant: zero at kernel_launch entry
__device__ int   g_off[NNODES + 1];
__device__ int   g_esrc[NTOT];
__device__ int   g_bsum[256];
// pre-swizzled bf16 weight planes, tile layout: chunk q=(t*CB+cb)*512 + r*16 + d
#define WP_CHUNKS 16384   // (DIN/32)*1*512
#define W1_CHUNKS 4096    // (HID/32)*2*512
__device__ uint4 g_WpHs[WP_CHUNKS], g_WpLs[WP_CHUNKS];
__device__ uint4 g_W1Hs[W1_CHUNKS], g_W1Ls[W1_CHUNKS];

__device__ __forceinline__ int clampN(int v) {
    return v < 0 ? 0 : (v >= NNODES ? NNODES - 1 : v);
}

// ---------------- CSR build ----------------
__global__ void k_count(const int* __restrict__ ei) {
    int e = blockIdx.x * blockDim.x + threadIdx.x;
    if (e < NEDGE) {
        int dst = clampN(ei[NEDGE + e]);
        atomicAdd(&g_cnt[dst], 1);
    }
}

__global__ void k_scanA() {
    __shared__ int wsum[8];
    int i = blockIdx.x * 256 + threadIdx.x;
    int lane = threadIdx.x & 31, w = threadIdx.x >> 5;
    int v = (i < NNODES) ? (g_cnt[i] + 1) : 0;   // +1 = self-loop
    if (i < NNODES) g_cnt[i] = 0;                // becomes scatter cursor
    int x = v;
    #pragma unroll
    for (int o = 1; o < 32; o <<= 1) {
        int t = __shfl_up_sync(0xffffffffu, x, o);
        if (lane >= o) x += t;
    }
    if (lane == 31) wsum[w] = x;
    __syncthreads();
    if (w == 0 && lane < 8) {
        int s = wsum[lane];
        #pragma unroll
        for (int o = 1; o < 8; o <<= 1) {
            int t = __shfl_up_sync(0xffu, s, o);
            if (lane >= o) s += t;
        }
        wsum[lane] = s;
    }
    __syncthreads();
    int pre = (w > 0) ? wsum[w - 1] : 0;
    if (i < NNODES) g_off[i] = pre + x - v;
    if (threadIdx.x == 255) g_bsum[blockIdx.x] = pre + x;
}

__global__ void k_scanB(int nblk) {
    __shared__ int wsum[8];
    int t = threadIdx.x;
    int lane = t & 31, w = t >> 5;
    int v = (t < nblk) ? g_bsum[t] : 0;
    int x = v;
    #pragma unroll
    for (int o = 1; o < 32; o <<= 1) {
        int q = __shfl_up_sync(0xffffffffu, x, o);
        if (lane >= o) x += q;
    }
    if (lane == 31) wsum[w] = x;
    __syncthreads();
    if (w == 0 && lane < 8) {
        int s = wsum[lane];
        #pragma unroll
        for (int o = 1; o < 8; o <<= 1) {
            int q = __shfl_up_sync(0xffu, s, o);
            if (lane >= o) s += q;
        }
        wsum[lane] = s;
    }
    __syncthreads();
    int pre = (w > 0) ? wsum[w - 1] : 0;
    if (t < nblk) g_bsum[t] = pre + x - v;
    if (t == 255) g_off[NNODES] = pre + x;
}

__global__ void k_scanC() {
    int i = blockIdx.x * 256 + threadIdx.x;
    if (i < NNODES) g_off[i] += g_bsum[blockIdx.x];
}

__global__ void k_scatter(const int* __restrict__ ei) {
    int e = blockIdx.x * blockDim.x + threadIdx.x;
    if (e >= NTOT) return;
    int src, dst;
    if (e < NEDGE) { src = clampN(ei[e]); dst = clampN(ei[NEDGE + e]); }
    else           { src = e - NEDGE; dst = src; }
    int pos = g_off[dst] + atomicAdd(&g_cnt[dst], 1);
    g_esrc[pos] = src;
}

// ================= bf16 split helpers =================
__device__ __forceinline__ uint32_t packbf(float v0, float v1) {
    uint32_t r;
    asm("cvt.rn.bf16x2.f32 %0, %1, %2;" : "=r"(r) : "f"(v1), "f"(v0));
    return r;
}
__device__ __forceinline__ float bflowf(uint32_t p)  { return __uint_as_float(p << 16); }
__device__ __forceinline__ float bfhighf(uint32_t p) { return __uint_as_float(p & 0xffff0000u); }

__device__ __forceinline__ void cvt_chunk(float4 x, float4 y, uint32_t* h, uint32_t* l) {
    h[0] = packbf(x.x, x.y); h[1] = packbf(x.z, x.w);
    h[2] = packbf(y.x, y.y); h[3] = packbf(y.z, y.w);
    l[0] = packbf(x.x - bflowf(h[0]), x.y - bfhighf(h[0]));
    l[1] = packbf(x.z - bflowf(h[1]), x.w - bfhighf(h[1]));
    l[2] = packbf(y.x - bflowf(h[2]), y.y - bfhighf(h[2]));
    l[3] = packbf(y.z - bflowf(h[3]), y.w - bfhighf(h[3]));
}

// weight split + pre-swizzle into tile layout (once per run)
// dest chunk q -> (tile tcb = q>>9, r = (q>>4)&31, d = q&15); src chunk c = (d&8)|((d^r)&7)
__global__ void k_prepW(const float* __restrict__ Wp, const float* __restrict__ W1) {
    int q = blockIdx.x * blockDim.x + threadIdx.x;
    const float* src;
    uint4 *dh, *dl;
    int idx;
    if (q < WP_CHUNKS) {
        int t = q >> 9, rr = q & 511, r = rr >> 4, d = rr & 15;
        int c = (d & 8) | ((d ^ r) & 7);
        src = Wp + (size_t)(t * 32 + r) * HID + c * 8;
        dh = g_WpHs; dl = g_WpLs; idx = q;
    } else {
        int j = q - WP_CHUNKS;
        if (j >= W1_CHUNKS) return;
        int tcb = j >> 9, rr = j & 511, r = rr >> 4, d = rr & 15;
        int t = tcb >> 1, cb = tcb & 1;
        int c = (d & 8) | ((d ^ r) & 7);
        src = W1 + (size_t)(t * 32 + r) * C1 + cb * 128 + c * 8;
        dh = g_W1Hs; dl = g_W1Ls; idx = j;
    }
    float4 f0 = *(const float4*)src;
    float4 f1 = *(const float4*)(src + 4);
    uint32_t h[4], l[4];
    cvt_chunk(f0, f1, h, l);
    dh[idx] = make_uint4(h[0], h[1], h[2], h[3]);
    dl[idx] = make_uint4(l[0], l[1], l[2], l[3]);
}

// ================= mma.sync split-bf16 GEMM, double-buffered, cp.async B ======
__device__ __forceinline__ void ldsm4(uint32_t addr, uint32_t* r) {
    asm volatile("ldmatrix.sync.aligned.m8n8.x4.shared.b16 {%0,%1,%2,%3},[%4];"
        : "=r"(r[0]), "=r"(r[1]), "=r"(r[2]), "=r"(r[3]) : "r"(addr));
}
__device__ __forceinline__ void ldsm4t(uint32_t addr, uint32_t* r) {
    asm volatile("ldmatrix.sync.aligned.m8n8.x4.trans.shared.b16 {%0,%1,%2,%3},[%4];"
        : "=r"(r[0]), "=r"(r[1]), "=r"(r[2]), "=r"(r[3]) : "r"(addr));
}
__device__ __forceinline__ void mma16816(float* c, const uint32_t* a, const uint32_t* b) {
    asm volatile(
        "mma.sync.aligned.m16n8k16.row.col.f32.bf16.bf16.f32 "
        "{%0,%1,%2,%3},{%4,%5,%6,%7},{%8,%9},{%0,%1,%2,%3};"
        : "+f"(c[0]), "+f"(c[1]), "+f"(c[2]), "+f"(c[3])
        : "r"(a[0]), "r"(a[1]), "r"(a[2]), "r"(a[3]), "r"(b[0]), "r"(b[1]));
}
__device__ __forceinline__ void cpa16(uint32_t saddr, const void* g) {
    asm volatile("cp.async.cg.shared.global [%0], [%1], 16;" :: "r"(saddr), "l"(g));
}
__device__ __forceinline__ void cpa_commit() {
    asm volatile("cp.async.commit_group;" ::: "memory");
}
__device__ __forceinline__ void cpa_wait0() {
    asm volatile("cp.async.wait_group 0;" ::: "memory");
}

// smem plan per buffer (32KB): A_hi 8K | A_lo 8K | B_hi 8K | B_lo 8K; 2 buffers
#define GB_BUF 32768
#define GB_AHI 0
#define GB_ALO 8192
#define GB_BHI 16384
#define GB_BLO 24576
#define GB_SMEM (2 * GB_BUF)

// MODE 0: C = fp32, + bias + relu.
// MODE 1: write g_h1b (bf16) + alpha partials via smem two-warp reduction.
template <int MODE>
__device__ __forceinline__ void gemm_bf16s(
    const float* __restrict__ A,
    const uint4* __restrict__ BswH, const uint4* __restrict__ BswL, int CB,
    const float* __restrict__ bias, float* __restrict__ C,
    const float* __restrict__ asrc, const float* __restrict__ adst,
    int M, int N, int K)
{
    extern __shared__ __align__(16) char dsm[];
    const uint32_t sb = (uint32_t)__cvta_generic_to_shared(dsm);

    const int tid = threadIdx.x;
    const int lane = tid & 31;
    const int warp = tid >> 5;
    const int warpM = (warp & 3) * 32;
    const int warpN = (warp >> 2) * 64;
    const int rowBase = blockIdx.y * 128;
    const int colBase = blockIdx.x * 128;
    const int cb = blockIdx.x;

    const int am = tid >> 1;
    const int akoff = (tid & 1) * 16;
    const int gm = rowBase + am;
    const bool aValid = gm < M;

    float acc[2][8][4];
    #pragma unroll
    for (int mi = 0; mi < 2; mi++)
        #pragma unroll
        for (int j = 0; j < 8; j++)
            #pragma unroll
            for (int q = 0; q < 4; q++) acc[mi][j][q] = 0.f;

    const int niter = K >> 5;
    float4 ra[4];

    // ---- prologue: tile 0 ----
    {
        if (aValid) {
            const float4* p = (const float4*)(A + (size_t)gm * K + akoff);
            ra[0] = p[0]; ra[1] = p[1]; ra[2] = p[2]; ra[3] = p[3];
        } else {
            ra[0] = ra[1] = ra[2] = ra[3] = make_float4(0.f, 0.f, 0.f, 0.f);
        }
        size_t bbase = (size_t)cb * 512;
        cpa16(sb + GB_BHI + tid * 16,        BswH + bbase + tid);
        cpa16(sb + GB_BHI + 4096 + tid * 16, BswH + bbase + tid + 256);
        cpa16(sb + GB_BLO + tid * 16,        BswL + bbase + tid);
        cpa16(sb + GB_BLO + 4096 + tid * 16, BswL + bbase + tid + 256);
        cpa_commit();
        uint32_t h[4], l[4];
        #pragma unroll
        for (int cc = 0; cc < 2; cc++) {
            int c = (tid & 1) * 2 + cc;
            cvt_chunk(ra[cc * 2], ra[cc * 2 + 1], h, l);
            int p = c ^ ((am >> 1) & 3);
            int off = am * 64 + p * 16;
            *(uint4*)(dsm + GB_AHI + off) = make_uint4(h[0], h[1], h[2], h[3]);
            *(uint4*)(dsm + GB_ALO + off) = make_uint4(l[0], l[1], l[2], l[3]);
        }
        cpa_wait0();
    }
    __syncthreads();

    for (int it = 0; it < niter; it++) {
        const uint32_t bufA_h = sb + (it & 1) * GB_BUF + GB_AHI;
        const uint32_t bufA_l = sb + (it & 1) * GB_BUF + GB_ALO;
        const uint32_t bufB_h = sb + (it & 1) * GB_BUF + GB_BHI;
        const uint32_t bufB_l = sb + (it & 1) * GB_BUF + GB_BLO;
        const uint32_t nxt = sb + ((it + 1) & 1) * GB_BUF;

        if (it + 1 < niter) {
            int kt = (it + 1) * 32;
            if (aValid) {
                const float4* p = (const float4*)(A + (size_t)gm * K + kt + akoff);
                ra[0] = p[0]; ra[1] = p[1]; ra[2] = p[2]; ra[3] = p[3];
            }
            size_t bbase = (size_t)((it + 1) * CB + cb) * 512;
            cpa16(nxt + GB_BHI + tid * 16,        BswH + bbase + tid);
            cpa16(nxt + GB_BHI + 4096 + tid * 16, BswH + bbase + tid + 256);
            cpa16(nxt + GB_BLO + tid * 16,        BswL + bbase + tid);
            cpa16(nxt + GB_BLO + 4096 + tid * 16, BswL + bbase + tid + 256);
            cpa_commit();
        }

        // mma over current buffer
        #pragma unroll
        for (int s = 0; s < 2; s++) {
            uint32_t Ah[2][4], Al[2][4];
            #pragma unroll
            for (int mi = 0; mi < 2; mi++) {
                int m0 = warpM + mi * 16 + (lane & 15);
                int c = 2 * s + (lane >> 4);
                int p = c ^ ((m0 >> 1) & 3);
                uint32_t off = (uint32_t)(m0 * 64 + p * 16);
                ldsm4(bufA_h + off, Ah[mi]);
                ldsm4(bufA_l + off, Al[mi]);
            }
            uint32_t Bhf[4][4], Blf[4][4];
            #pragma unroll
            for (int nb = 0; nb < 4; nb++) {
                int k = s * 16 + (lane & 15);
                int nc = (warpN >> 3) + nb * 2 + (lane >> 4);
                int p = nc ^ (k & 7);
                uint32_t off = (uint32_t)(k * 256 + p * 16);
                ldsm4t(bufB_h + off, Bhf[nb]);
                ldsm4t(bufB_l + off, Blf[nb]);
            }
            #pragma unroll
            for (int mi = 0; mi < 2; mi++)
                #pragma unroll
                for (int nb = 0; nb < 4; nb++)
                    #pragma unroll
                    for (int h = 0; h < 2; h++) {
                        float* c = acc[mi][nb * 2 + h];
                        mma16816(c, Ah[mi], &Bhf[nb][h * 2]);
                        mma16816(c, Ah[mi], &Blf[nb][h * 2]);
                        mma16816(c, Al[mi], &Bhf[nb][h * 2]);
                    }
        }

        if (it + 1 < niter) {
            char* nb = dsm + ((it + 1) & 1) * GB_BUF;
            uint32_t h[4], l[4];
            #pragma unroll
            for (int cc = 0; cc < 2; cc++) {
                int c = (tid & 1) * 2 + cc;
                cvt_chunk(ra[cc * 2], ra[cc * 2 + 1], h, l);
                int p = c ^ ((am >> 1) & 3);
                int off = am * 64 + p * 16;
                *(uint4*)(nb + GB_AHI + off) = make_uint4(h[0], h[1], h[2], h[3]);
                *(uint4*)(nb + GB_ALO + off) = make_uint4(l[0], l[1], l[2], l[3]);
            }
            cpa_wait0();
        }
        __syncthreads();
    }

    // ---- epilogue ----
    if (MODE == 0) {
        #pragma unroll
        for (int mi = 0; mi < 2; mi++) {
            #pragma unroll
            for (int j = 0; j < 8; j++) {
                float* c = acc[mi][j];
                int gmr = rowBase + warpM + mi * 16 + (lane >> 2);
                int gn = colBase + warpN + j * 8 + (lane & 3) * 2;
                float b0 = bias[gn], b1 = bias[gn + 1];
                float v0 = fmaxf(c[0] + b0, 0.f), v1 = fmaxf(c[1] + b1, 0.f);
                float v2 = fmaxf(c[2] + b0, 0.f), v3 = fmaxf(c[3] + b1, 0.f);
                if (gmr < M)     *(float2*)&C[(size_t)gmr * N + gn]       = make_float2(v0, v1);
                if (gmr + 8 < M) *(float2*)&C[(size_t)(gmr + 8) * N + gn] = make_float2(v2, v3);
            }
        }
    } else {
        // bf16 message write + fused alpha dot; two-warp smem reduction, no atomics
        const int head = colBase >> 7;
        float psA[2], pdA[2], psB[2], pdB[2];
        #pragma unroll
        for (int mi = 0; mi < 2; mi++) {
            int gmr = rowBase + warpM + mi * 16 + (lane >> 2);
            float ps0 = 0.f, pd0 = 0.f, ps1 = 0.f, pd1 = 0.f;
            #pragma unroll
            for (int j = 0; j < 8; j++) {
                float* c = acc[mi][j];
                int gn = colBase + warpN + j * 8 + (lane & 3) * 2;
                float as0 = __ldg(&asrc[gn]), as1 = __ldg(&asrc[gn + 1]);
                float ad0 = __ldg(&adst[gn]), ad1 = __ldg(&adst[gn + 1]);
                ps0 += c[0] * as0 + c[1] * as1;
                pd0 += c[0] * ad0 + c[1] * ad1;
                ps1 += c[2] * as0 + c[3] * as1;
                pd1 += c[2] * ad0 + c[3] * ad1;
                if (gmr < M)
                    *(uint32_t*)&g_h1b[(size_t)gmr * C1 + gn] = packbf(c[0], c[1]);
                if (gmr + 8 < M)
                    *(uint32_t*)&g_h1b[(size_t)(gmr + 8) * C1 + gn] = packbf(c[2], c[3]);
            }
            #pragma unroll
            for (int o = 1; o < 4; o <<= 1) {
                ps0 += __shfl_xor_sync(0xffffffffu, ps0, o);
                pd0 += __shfl_xor_sync(0xffffffffu, pd0, o);
                ps1 += __shfl_xor_sync(0xffffffffu, ps1, o);
                pd1 += __shfl_xor_sync(0xffffffffu, pd1, o);
            }
            psA[mi] = ps0; pdA[mi] = pd0; psB[mi] = ps1; pdB[mi] = pd1;
        }
        float2* sred = (float2*)dsm;   // 128 rows x float2 = 1KB (main loop done)
        if (warp < 4 && (lane & 3) == 0) {
            #pragma unroll
            for (int mi = 0; mi < 2; mi++) {
                int rloc = warpM + mi * 16 + (lane >> 2);
                sred[rloc]     = make_float2(psA[mi], pdA[mi]);
                sred[rloc + 8] = make_float2(psB[mi], pdB[mi]);
            }
        }
        __syncthreads();
        if (warp >= 4 && (lane & 3) == 0) {
            #pragma unroll
            for (int mi = 0; mi < 2; mi++) {
                int rloc = warpM + mi * 16 + (lane >> 2);
                float2 o = sred[rloc];
                int row = rowBase + rloc;
                if (row < M) {
                    g_asrc1[row * 2 + head] = o.x + psA[mi];
                    g_adst1[row * 2 + head] = o.y + pdA[mi];
                }
                o = sred[rloc + 8];
                row += 8;
                if (row < M) {
                    g_asrc1[row * 2 + head] = o.x + psB[mi];
                    g_adst1[row * 2 + head] = o.y + pdB[mi];
                }
            }
        }
    }
}

__global__ void __launch_bounds__(256, 2)
k_gemm_pre(const float* __restrict__ x, const float* __restrict__ b_pre)
{
    gemm_bf16s<0>(x, g_WpHs, g_WpLs, 1, b_pre, g_hpre, nullptr, nullptr, NNODES, HID, DIN);
}

__global__ void __launch_bounds__(256, 2)
k_gemm_h1(const float* __restrict__ a_src1, const float* __restrict__ a_dst1)
{
    gemm_bf16s<1>(g_hpre, g_W1Hs, g_W1Ls, 2, nullptr, nullptr, a_src1, a_dst1, NNODES, C1, HID);
}

__device__ __forceinline__ float lrelu(float e) { return e > 0.f ? e : 0.2f * e; }

// ---------------- GAT1 aggregation: bf16 messages, lane owns 8 cols ----------------
__global__ void k_agg1(const float* __restrict__ b1) {
    int node = blockIdx.x * 8 + (threadIdx.x >> 5);
    int lane = threadIdx.x & 31;
    if (lane == 0) g_cnt[node] = 0;   // restore zero-invariant for next call
    int beg = g_off[node], end = g_off[node + 1];
    float2 ad = *(const float2*)&g_adst1[node * 2];

    float m0 = -1e30f, m1 = -1e30f;
    for (int j = beg + lane; j < end; j += 32) {
        int s = g_esrc[j];
        float2 as = *(const float2*)&g_asrc1[s * 2];
        m0 = fmaxf(m0, lrelu(as.x + ad.x));
        m1 = fmaxf(m1, lrelu(as.y + ad.y));
    }
    #pragma unroll
    for (int o = 16; o; o >>= 1) {
        m0 = fmaxf(m0, __shfl_xor_sync(0xffffffffu, m0, o));
        m1 = fmaxf(m1, __shfl_xor_sync(0xffffffffu, m1, o));
    }

    const int head = lane >> 4;
    const float adh = head ? ad.y : ad.x;
    const float mh  = head ? m1 : m0;

    float4 a0 = make_float4(0.f, 0.f, 0.f, 0.f);
    float4 a1 = make_float4(0.f, 0.f, 0.f, 0.f);
    float ssum = 0.f;
    for (int j = beg; j < end; j++) {
        int s = g_esrc[j];
        float2 as = *(const float2*)&g_asrc1[s * 2];
        float p = expf(lrelu((head ? as.y : as.x) + adh) - mh);
        ssum += p;
        uint4 hv = *(const uint4*)&g_h1b[(size_t)s * C1 + lane * 8];
        a0.x += bflowf(hv.x) * p;  a0.y += bfhighf(hv.x) * p;
        a0.z += bflowf(hv.y) * p;  a0.w += bfhighf(hv.y) * p;
        a1.x += bflowf(hv.z) * p;  a1.y += bfhighf(hv.z) * p;
        a1.z += bflowf(hv.w) * p;  a1.w += bfhighf(hv.w) * p;
    }
    float inv = 1.f / (ssum + 1e-16f);
    int c = lane * 8;
    float4 bb0 = *(const float4*)&b1[c];
    float4 bb1 = *(const float4*)&b1[c + 4];
    float4 r0, r1;
    float o;
    o = a0.x * inv + bb0.x; r0.x = (o > 0.f) ? o : expm1f(o);
    o = a0.y * inv + bb0.y; r0.y = (o > 0.f) ? o : expm1f(o);
    o = a0.z * inv + bb0.z; r0.z = (o > 0.f) ? o : expm1f(o);
    o = a0.w * inv + bb0.w; r0.w = (o > 0.f) ? o : expm1f(o);
    o = a1.x * inv + bb1.x; r1.x = (o > 0.f) ? o : expm1f(o);
    o = a1.y * inv + bb1.y; r1.y = (o > 0.f) ? o : expm1f(o);
    o = a1.z * inv + bb1.z; r1.z = (o > 0.f) ? o : expm1f(o);
    o = a1.w * inv + bb1.w; r1.w = (o > 0.f) ? o : expm1f(o);
    *(float4*)&g_h1out[(size_t)node * C1 + c]     = r0;
    *(float4*)&g_h1out[(size_t)node * C1 + c + 4] = r1;
}

// ---------------- layer 2 transform + alpha ----------------
__global__ void k_gemm2(const float* __restrict__ W2, const float* __restrict__ a_src2,
                        const float* __restrict__ a_dst2) {
    __shared__ float sW[C1 * NC];
    __shared__ float sa[NC], sd[NC];
    int tid = threadIdx.x;
    *(float4*)&sW[tid * 4] = *(const float4*)&W2[tid * 4];
    if (tid < NC) { sa[tid] = a_src2[tid]; sd[tid] = a_dst2[tid]; }
    __syncthreads();

    int node = blockIdx.x * 8 + (tid >> 5);
    int lane = tid & 31;
    const float* hrow = &g_h1out[(size_t)node * C1];
    float a0 = 0.f, a1 = 0.f, a2 = 0.f, a3 = 0.f;
    #pragma unroll
    for (int k = 0; k < 8; k++) {
        int c = lane + 32 * k;
        float v = hrow[c];
        a0 += v * sW[c * 4 + 0];
        a1 += v * sW[c * 4 + 1];
        a2 += v * sW[c * 4 + 2];
        a3 += v * sW[c * 4 + 3];
    }
    #pragma unroll
    for (int o = 16; o; o >>= 1) {
        a0 += __shfl_xor_sync(0xffffffffu, a0, o);
        a1 += __shfl_xor_sync(0xffffffffu, a1, o);
        a2 += __shfl_xor_sync(0xffffffffu, a2, o);
        a3 += __shfl_xor_sync(0xffffffffu, a3, o);
    }
    if (lane == 0) {
        g_h2[node * 4 + 0] = a0; g_h2[node * 4 + 1] = a1;
        g_h2[node * 4 + 2] = a2; g_h2[node * 4 + 3] = a3;
        g_asrc2[node] = a0 * sa[0] + a1 * sa[1] + a2 * sa[2] + a3 * sa[3];
        g_adst2[node] = a0 * sd[0] + a1 * sd[1] + a2 * sd[2] + a3 * sd[3];
    }
}

// ---------------- GAT2 aggregation ----------------
__global__ void k_agg2(const float* __restrict__ b2, float* __restrict__ out) {
    int node = blockIdx.x * 8 + (threadIdx.x >> 5);
    int lane = threadIdx.x & 31;
    int beg = g_off[node], end = g_off[node + 1];
    float ad = g_adst2[node];

    float m = -1e30f;
    for (int j = beg + lane; j < end; j += 32)
        m = fmaxf(m, lrelu(g_asrc2[g_esrc[j]] + ad));
    #pragma unroll
    for (int o = 16; o; o >>= 1)
        m = fmaxf(m, __shfl_xor_sync(0xffffffffu, m, o));

    float ss = 0.f, c0 = 0.f, c1 = 0.f, c2 = 0.f, c3 = 0.f;
    for (int j = beg + lane; j < end; j += 32) {
        int s = g_esrc[j];
        float p = expf(lrelu(g_asrc2[s] + ad) - m);
        ss += p;
        float4 h = *(const float4*)&g_h2[s * 4];
        c0 += h.x * p; c1 += h.y * p; c2 += h.z * p; c3 += h.w * p;
    }
    #pragma unroll
    for (int o = 16; o; o >>= 1) {
        ss += __shfl_xor_sync(0xffffffffu, ss, o);
        c0 += __shfl_xor_sync(0xffffffffu, c0, o);
        c1 += __shfl_xor_sync(0xffffffffu, c1, o);
        c2 += __shfl_xor_sync(0xffffffffu, c2, o);
        c3 += __shfl_xor_sync(0xffffffffu, c3, o);
    }
    if (lane == 0) {
        float inv = 1.f / (ss + 1e-16f);
        out[node * 4 + 0] = c0 * inv + b2[0];
        out[node * 4 + 1] = c1 * inv + b2[1];
        out[node * 4 + 2] = c2 * inv + b2[2];
        out[node * 4 + 3] = c3 * inv + b2[3];
    }
}

// ---------------- launch ----------------
extern "C" void kernel_launch(void* const* d_in, const int* in_sizes, int n_in,
                              void* d_out, int out_size) {
    const float* x      = (const float*)d_in[0];
    const int*   ei     = (const int*)d_in[1];
    const float* W_pre  = (const float*)d_in[2];
    const float* b_pre  = (const float*)d_in[3];
    const float* W1     = (const float*)d_in[4];
    const float* a_src1 = (const float*)d_in[5];
    const float* a_dst1 = (const float*)d_in[6];
    const float* b1     = (const float*)d_in[7];
    const float* W2     = (const float*)d_in[8];
    const float* a_src2 = (const float*)d_in[9];
    const float* a_dst2 = (const float*)d_in[10];
    const float* b2     = (const float*)d_in[11];
    float* out = (float*)d_out;

    static cudaStream_t s1 = nullptr;
    static cudaEvent_t eFork = nullptr, eJoin = nullptr;
    if (s1 == nullptr) {
        cudaStreamCreateWithFlags(&s1, cudaStreamNonBlocking);
        cudaEventCreateWithFlags(&eFork, cudaEventDisableTiming);
        cudaEventCreateWithFlags(&eJoin, cudaEventDisableTiming);
    }
    cudaFuncSetAttribute(k_gemm_pre, cudaFuncAttributeMaxDynamicSharedMemorySize, GB_SMEM);
    cudaFuncSetAttribute(k_gemm_h1,  cudaFuncAttributeMaxDynamicSharedMemorySize, GB_SMEM);

    const int NB = (NNODES + 255) / 256;   // 196

    // ---- fork: CSR chain on s1, compute chain on main stream ----
    cudaEventRecord(eFork, 0);
    cudaStreamWaitEvent(s1, eFork, 0);

    k_count<<<(NEDGE + 255) / 256, 256, 0, s1>>>(ei);
    k_scanA<<<NB, 256, 0, s1>>>();
    k_scanB<<<1, 256, 0, s1>>>(NB);
    k_scanC<<<NB, 256, 0, s1>>>();
    k_scatter<<<(NTOT + 255) / 256, 256, 0, s1>>>(ei);
    cudaEventRecord(eJoin, s1);

    // main stream: weights prep, GEMMs (alpha fused into gemm_h1 epilogue)
    k_prepW<<<(WP_CHUNKS + W1_CHUNKS + 255) / 256, 256>>>(W_pre, W1);
    {
        dim3 grid(1, (NNODES + 127) / 128);
        k_gemm_pre<<<grid, 256, GB_SMEM>>>(x, b_pre);
    }
    {
        dim3 grid(2, (NNODES + 127) / 128);
        k_gemm_h1<<<grid, 256, GB_SMEM>>>(a_src1, a_dst1);
    }

    // ---- join: aggregation needs the CSR ----
    cudaStreamWaitEvent(0, eJoin, 0);
    k_agg1<<<NNODES / 8, 256>>>(b1);
    k_gemm2<<<NNODES / 8, 256>>>(W2, a_src2, a_dst2);
    k_agg2<<<NNODES / 8, 256>>>(b2, out);
}

// round 14
// speedup vs baseline: 3.2103x; 1.1189x over previous
#include <cuda_runtime.h>
#include <cuda_bf16.h>
#include <cuda_fp16.h>
#include <math.h>
#include <stdint.h>

#define NNODES 50000
#define NEDGE  800000
#define NTOT   (NEDGE + NNODES)
#define DIN    1024
#define HID    128
#define C1     256   // HEADS*HID
#define NC     4

// ---------------- scratch (device globals; no allocation allowed) ----------------
__device__ float g_hpre[(size_t)NNODES * HID];
__device__ __align__(16) __nv_bfloat16 g_h1b[(size_t)NNODES * C1];  // bf16 messages
__device__ float g_h1out[(size_t)NNODES * C1];
__device__ float g_asrc1[NNODES * 2];   // written (plain stores) by gemm_h1 epilogue
__device__ float g_adst1[NNODES * 2];
__device__ float g_h2[NNODES * NC];
__device__ float g_asrc2[NNODES];
__device__ float g_adst2[NNODES];
__device__ int   g_cnt[NNODES];     // invariant: zero at kernel_launch entry
__device__ int   g_off[NNODES + 1];
__device__ int   g_esrc[NTOT];
__device__ int   g_bsum[256];
// pre-swizzled FP16 weight planes, tile layout: chunk q=(t*CB+cb)*512 + r*16 + d
#define WP_CHUNKS 16384   // (DIN/32)*1*512
#define W1_CHUNKS 4096    // (HID/32)*2*512
__device__ uint4 g_WpHs[WP_CHUNKS], g_WpLs[WP_CHUNKS];
__device__ uint4 g_W1Hs[W1_CHUNKS], g_W1Ls[W1_CHUNKS];

__device__ __forceinline__ int clampN(int v) {
    return v < 0 ? 0 : (v >= NNODES ? NNODES - 1 : v);
}

// ---------------- CSR build ----------------
__global__ void k_count(const int* __restrict__ ei) {
    int e = blockIdx.x * blockDim.x + threadIdx.x;
    if (e < NEDGE) {
        int dst = clampN(ei[NEDGE + e]);
        atomicAdd(&g_cnt[dst], 1);
    }
}

__global__ void k_scanA() {
    __shared__ int wsum[8];
    int i = blockIdx.x * 256 + threadIdx.x;
    int lane = threadIdx.x & 31, w = threadIdx.x >> 5;
    int v = (i < NNODES) ? (g_cnt[i] + 1) : 0;   // +1 = self-loop
    if (i < NNODES) g_cnt[i] = 0;                // becomes scatter cursor
    int x = v;
    #pragma unroll
    for (int o = 1; o < 32; o <<= 1) {
        int t = __shfl_up_sync(0xffffffffu, x, o);
        if (lane >= o) x += t;
    }
    if (lane == 31) wsum[w] = x;
    __syncthreads();
    if (w == 0 && lane < 8) {
        int s = wsum[lane];
        #pragma unroll
        for (int o = 1; o < 8; o <<= 1) {
            int t = __shfl_up_sync(0xffu, s, o);
            if (lane >= o) s += t;
        }
        wsum[lane] = s;
    }
    __syncthreads();
    int pre = (w > 0) ? wsum[w - 1] : 0;
    if (i < NNODES) g_off[i] = pre + x - v;
    if (threadIdx.x == 255) g_bsum[blockIdx.x] = pre + x;
}

__global__ void k_scanB(int nblk) {
    __shared__ int wsum[8];
    int t = threadIdx.x;
    int lane = t & 31, w = t >> 5;
    int v = (t < nblk) ? g_bsum[t] : 0;
    int x = v;
    #pragma unroll
    for (int o = 1; o < 32; o <<= 1) {
        int q = __shfl_up_sync(0xffffffffu, x, o);
        if (lane >= o) x += q;
    }
    if (lane == 31) wsum[w] = x;
    __syncthreads();
    if (w == 0 && lane < 8) {
        int s = wsum[lane];
        #pragma unroll
        for (int o = 1; o < 8; o <<= 1) {
            int q = __shfl_up_sync(0xffu, s, o);
            if (lane >= o) s += q;
        }
        wsum[lane] = s;
    }
    __syncthreads();
    int pre = (w > 0) ? wsum[w - 1] : 0;
    if (t < nblk) g_bsum[t] = pre + x - v;
    if (t == 255) g_off[NNODES] = pre + x;
}

__global__ void k_scanC() {
    int i = blockIdx.x * 256 + threadIdx.x;
    if (i < NNODES) g_off[i] += g_bsum[blockIdx.x];
}

__global__ void k_scatter(const int* __restrict__ ei) {
    int e = blockIdx.x * blockDim.x + threadIdx.x;
    if (e >= NTOT) return;
    int src, dst;
    if (e < NEDGE) { src = clampN(ei[e]); dst = clampN(ei[NEDGE + e]); }
    else           { src = e - NEDGE; dst = src; }
    int pos = g_off[dst] + atomicAdd(&g_cnt[dst], 1);
    g_esrc[pos] = src;
}

// ================= pack helpers =================
__device__ __forceinline__ uint32_t packbf(float v0, float v1) {
    uint32_t r;
    asm("cvt.rn.bf16x2.f32 %0, %1, %2;" : "=r"(r) : "f"(v1), "f"(v0));
    return r;
}
__device__ __forceinline__ float bflowf(uint32_t p)  { return __uint_as_float(p << 16); }
__device__ __forceinline__ float bfhighf(uint32_t p) { return __uint_as_float(p & 0xffff0000u); }

__device__ __forceinline__ uint32_t packhf(float v0, float v1) {
    uint32_t r;
    asm("cvt.rn.f16x2.f32 %0, %1, %2;" : "=r"(r) : "f"(v1), "f"(v0));
    return r;
}

// weight split (fp16 hi + fp16 lo; lo captures residual -> B effectively exact)
// + pre-swizzle into tile layout (once per run)
// dest chunk q -> (tile tcb = q>>9, r = (q>>4)&31, d = q&15); src chunk c = (d&8)|((d^r)&7)
__global__ void k_prepW(const float* __restrict__ Wp, const float* __restrict__ W1) {
    int q = blockIdx.x * blockDim.x + threadIdx.x;
    const float* src;
    uint4 *dh, *dl;
    int idx;
    if (q < WP_CHUNKS) {
        int t = q >> 9, rr = q & 511, r = rr >> 4, d = rr & 15;
        int c = (d & 8) | ((d ^ r) & 7);
        src = Wp + (size_t)(t * 32 + r) * HID + c * 8;
        dh = g_WpHs; dl = g_WpLs; idx = q;
    } else {
        int j = q - WP_CHUNKS;
        if (j >= W1_CHUNKS) return;
        int tcb = j >> 9, rr = j & 511, r = rr >> 4, d = rr & 15;
        int t = tcb >> 1, cb = tcb & 1;
        int c = (d & 8) | ((d ^ r) & 7);
        src = W1 + (size_t)(t * 32 + r) * C1 + cb * 128 + c * 8;
        dh = g_W1Hs; dl = g_W1Ls; idx = j;
    }
    float v[8], hi[8], lo[8];
    *(float4*)&v[0] = *(const float4*)src;
    *(float4*)&v[4] = *(const float4*)(src + 4);
    #pragma unroll
    for (int i = 0; i < 8; i++) {
        hi[i] = __half2float(__float2half_rn(v[i]));
        lo[i] = v[i] - hi[i];
    }
    dh[idx] = make_uint4(packhf(hi[0], hi[1]), packhf(hi[2], hi[3]),
                         packhf(hi[4], hi[5]), packhf(hi[6], hi[7]));
    dl[idx] = make_uint4(packhf(lo[0], lo[1]), packhf(lo[2], lo[3]),
                         packhf(lo[4], lo[5]), packhf(lo[6], lo[7]));
}

// ================= mma.sync fp16 2-term GEMM, double-buffered, cp.async B =====
__device__ __forceinline__ void ldsm4(uint32_t addr, uint32_t* r) {
    asm volatile("ldmatrix.sync.aligned.m8n8.x4.shared.b16 {%0,%1,%2,%3},[%4];"
        : "=r"(r[0]), "=r"(r[1]), "=r"(r[2]), "=r"(r[3]) : "r"(addr));
}
__device__ __forceinline__ void ldsm4t(uint32_t addr, uint32_t* r) {
    asm volatile("ldmatrix.sync.aligned.m8n8.x4.trans.shared.b16 {%0,%1,%2,%3},[%4];"
        : "=r"(r[0]), "=r"(r[1]), "=r"(r[2]), "=r"(r[3]) : "r"(addr));
}
__device__ __forceinline__ void mma16816h(float* c, const uint32_t* a, const uint32_t* b) {
    asm volatile(
        "mma.sync.aligned.m16n8k16.row.col.f32.f16.f16.f32 "
        "{%0,%1,%2,%3},{%4,%5,%6,%7},{%8,%9},{%0,%1,%2,%3};"
        : "+f"(c[0]), "+f"(c[1]), "+f"(c[2]), "+f"(c[3])
        : "r"(a[0]), "r"(a[1]), "r"(a[2]), "r"(a[3]), "r"(b[0]), "r"(b[1]));
}
__device__ __forceinline__ void cpa16(uint32_t saddr, const void* g) {
    asm volatile("cp.async.cg.shared.global [%0], [%1], 16;" :: "r"(saddr), "l"(g));
}
__device__ __forceinline__ void cpa_commit() {
    asm volatile("cp.async.commit_group;" ::: "memory");
}
__device__ __forceinline__ void cpa_wait0() {
    asm volatile("cp.async.wait_group 0;" ::: "memory");
}

// smem per buffer (24KB): A 8K | B_hi 8K | B_lo 8K; 2 buffers = 48KB
#define GB_BUF 24576
#define GB_A   0
#define GB_BHI 8192
#define GB_BLO 16384
#define GB_SMEM (2 * GB_BUF)

// MODE 0: C = fp32, + bias + relu.
// MODE 1: write g_h1b (bf16) + alpha partials via smem two-warp reduction.
template <int MODE>
__device__ __forceinline__ void gemm_hf16(
    const float* __restrict__ A,
    const uint4* __restrict__ BswH, const uint4* __restrict__ BswL, int CB,
    const float* __restrict__ bias, float* __restrict__ C,
    const float* __restrict__ asrc, const float* __restrict__ adst,
    int M, int N, int K)
{
    extern __shared__ __align__(16) char dsm[];
    const uint32_t sb = (uint32_t)__cvta_generic_to_shared(dsm);

    const int tid = threadIdx.x;
    const int lane = tid & 31;
    const int warp = tid >> 5;
    const int warpM = (warp & 3) * 32;
    const int warpN = (warp >> 2) * 64;
    const int rowBase = blockIdx.y * 128;
    const int colBase = blockIdx.x * 128;
    const int cb = blockIdx.x;

    const int am = tid >> 1;
    const int akoff = (tid & 1) * 16;
    const int gm = rowBase + am;
    const bool aValid = gm < M;

    float acc[2][8][4];
    #pragma unroll
    for (int mi = 0; mi < 2; mi++)
        #pragma unroll
        for (int j = 0; j < 8; j++)
            #pragma unroll
            for (int q = 0; q < 4; q++) acc[mi][j][q] = 0.f;

    const int niter = K >> 5;
    float4 ra[4];

    // ---- prologue: tile 0 ----
    {
        if (aValid) {
            const float4* p = (const float4*)(A + (size_t)gm * K + akoff);
            ra[0] = p[0]; ra[1] = p[1]; ra[2] = p[2]; ra[3] = p[3];
        } else {
            ra[0] = ra[1] = ra[2] = ra[3] = make_float4(0.f, 0.f, 0.f, 0.f);
        }
        size_t bbase = (size_t)cb * 512;
        cpa16(sb + GB_BHI + tid * 16,        BswH + bbase + tid);
        cpa16(sb + GB_BHI + 4096 + tid * 16, BswH + bbase + tid + 256);
        cpa16(sb + GB_BLO + tid * 16,        BswL + bbase + tid);
        cpa16(sb + GB_BLO + 4096 + tid * 16, BswL + bbase + tid + 256);
        cpa_commit();
        #pragma unroll
        for (int cc = 0; cc < 2; cc++) {
            int c = (tid & 1) * 2 + cc;
            float4 f0 = ra[cc * 2], f1 = ra[cc * 2 + 1];
            int p = c ^ ((am >> 1) & 3);
            *(uint4*)(dsm + GB_A + am * 64 + p * 16) =
                make_uint4(packhf(f0.x, f0.y), packhf(f0.z, f0.w),
                           packhf(f1.x, f1.y), packhf(f1.z, f1.w));
        }
        cpa_wait0();
    }
    __syncthreads();

    for (int it = 0; it < niter; it++) {
        const uint32_t bufA   = sb + (it & 1) * GB_BUF + GB_A;
        const uint32_t bufB_h = sb + (it & 1) * GB_BUF + GB_BHI;
        const uint32_t bufB_l = sb + (it & 1) * GB_BUF + GB_BLO;
        const uint32_t nxt = sb + ((it + 1) & 1) * GB_BUF;

        if (it + 1 < niter) {
            int kt = (it + 1) * 32;
            if (aValid) {
                const float4* p = (const float4*)(A + (size_t)gm * K + kt + akoff);
                ra[0] = p[0]; ra[1] = p[1]; ra[2] = p[2]; ra[3] = p[3];
            }
            size_t bbase = (size_t)((it + 1) * CB + cb) * 512;
            cpa16(nxt + GB_BHI + tid * 16,        BswH + bbase + tid);
            cpa16(nxt + GB_BHI + 4096 + tid * 16, BswH + bbase + tid + 256);
            cpa16(nxt + GB_BLO + tid * 16,        BswL + bbase + tid);
            cpa16(nxt + GB_BLO + 4096 + tid * 16, BswL + bbase + tid + 256);
            cpa_commit();
        }

        // mma over current buffer: Ah*(Bh + Bl)
        #pragma unroll
        for (int s = 0; s < 2; s++) {
            uint32_t Ah[2][4];
            #pragma unroll
            for (int mi = 0; mi < 2; mi++) {
                int m0 = warpM + mi * 16 + (lane & 15);
                int c = 2 * s + (lane >> 4);
                int p = c ^ ((m0 >> 1) & 3);
                ldsm4(bufA + (uint32_t)(m0 * 64 + p * 16), Ah[mi]);
            }
            uint32_t Bhf[4][4], Blf[4][4];
            #pragma unroll
            for (int nb = 0; nb < 4; nb++) {
                int k = s * 16 + (lane & 15);
                int nc = (warpN >> 3) + nb * 2 + (lane >> 4);
                int p = nc ^ (k & 7);
                uint32_t off = (uint32_t)(k * 256 + p * 16);
                ldsm4t(bufB_h + off, Bhf[nb]);
                ldsm4t(bufB_l + off, Blf[nb]);
            }
            #pragma unroll
            for (int mi = 0; mi < 2; mi++)
                #pragma unroll
                for (int nb = 0; nb < 4; nb++)
                    #pragma unroll
                    for (int h = 0; h < 2; h++) {
                        float* c = acc[mi][nb * 2 + h];
                        mma16816h(c, Ah[mi], &Bhf[nb][h * 2]);
                        mma16816h(c, Ah[mi], &Blf[nb][h * 2]);
                    }
        }

        if (it + 1 < niter) {
            char* nb = dsm + ((it + 1) & 1) * GB_BUF;
            #pragma unroll
            for (int cc = 0; cc < 2; cc++) {
                int c = (tid & 1) * 2 + cc;
                float4 f0 = ra[cc * 2], f1 = ra[cc * 2 + 1];
                int p = c ^ ((am >> 1) & 3);
                *(uint4*)(nb + GB_A + am * 64 + p * 16) =
                    make_uint4(packhf(f0.x, f0.y), packhf(f0.z, f0.w),
                               packhf(f1.x, f1.y), packhf(f1.z, f1.w));
            }
            cpa_wait0();
        }
        __syncthreads();
    }

    // ---- epilogue ----
    if (MODE == 0) {
        #pragma unroll
        for (int mi = 0; mi < 2; mi++) {
            #pragma unroll
            for (int j = 0; j < 8; j++) {
                float* c = acc[mi][j];
                int gmr = rowBase + warpM + mi * 16 + (lane >> 2);
                int gn = colBase + warpN + j * 8 + (lane & 3) * 2;
                float b0 = bias[gn], b1 = bias[gn + 1];
                float v0 = fmaxf(c[0] + b0, 0.f), v1 = fmaxf(c[1] + b1, 0.f);
                float v2 = fmaxf(c[2] + b0, 0.f), v3 = fmaxf(c[3] + b1, 0.f);
                if (gmr < M)     *(float2*)&C[(size_t)gmr * N + gn]       = make_float2(v0, v1);
                if (gmr + 8 < M) *(float2*)&C[(size_t)(gmr + 8) * N + gn] = make_float2(v2, v3);
            }
        }
    } else {
        // bf16 message write + fused alpha dot; two-warp smem reduction, no atomics
        const int head = colBase >> 7;
        float psA[2], pdA[2], psB[2], pdB[2];
        #pragma unroll
        for (int mi = 0; mi < 2; mi++) {
            int gmr = rowBase + warpM + mi * 16 + (lane >> 2);
            float ps0 = 0.f, pd0 = 0.f, ps1 = 0.f, pd1 = 0.f;
            #pragma unroll
            for (int j = 0; j < 8; j++) {
                float* c = acc[mi][j];
                int gn = colBase + warpN + j * 8 + (lane & 3) * 2;
                float as0 = __ldg(&asrc[gn]), as1 = __ldg(&asrc[gn + 1]);
                float ad0 = __ldg(&adst[gn]), ad1 = __ldg(&adst[gn + 1]);
                ps0 += c[0] * as0 + c[1] * as1;
                pd0 += c[0] * ad0 + c[1] * ad1;
                ps1 += c[2] * as0 + c[3] * as1;
                pd1 += c[2] * ad0 + c[3] * ad1;
                if (gmr < M)
                    *(uint32_t*)&g_h1b[(size_t)gmr * C1 + gn] = packbf(c[0], c[1]);
                if (gmr + 8 < M)
                    *(uint32_t*)&g_h1b[(size_t)(gmr + 8) * C1 + gn] = packbf(c[2], c[3]);
            }
            #pragma unroll
            for (int o = 1; o < 4; o <<= 1) {
                ps0 += __shfl_xor_sync(0xffffffffu, ps0, o);
                pd0 += __shfl_xor_sync(0xffffffffu, pd0, o);
                ps1 += __shfl_xor_sync(0xffffffffu, ps1, o);
                pd1 += __shfl_xor_sync(0xffffffffu, pd1, o);
            }
            psA[mi] = ps0; pdA[mi] = pd0; psB[mi] = ps1; pdB[mi] = pd1;
        }
        float2* sred = (float2*)dsm;   // 128 rows x float2 = 1KB (main loop done)
        if (warp < 4 && (lane & 3) == 0) {
            #pragma unroll
            for (int mi = 0; mi < 2; mi++) {
                int rloc = warpM + mi * 16 + (lane >> 2);
                sred[rloc]     = make_float2(psA[mi], pdA[mi]);
                sred[rloc + 8] = make_float2(psB[mi], pdB[mi]);
            }
        }
        __syncthreads();
        if (warp >= 4 && (lane & 3) == 0) {
            #pragma unroll
            for (int mi = 0; mi < 2; mi++) {
                int rloc = warpM + mi * 16 + (lane >> 2);
                float2 o = sred[rloc];
                int row = rowBase + rloc;
                if (row < M) {
                    g_asrc1[row * 2 + head] = o.x + psA[mi];
                    g_adst1[row * 2 + head] = o.y + pdA[mi];
                }
                o = sred[rloc + 8];
                row += 8;
                if (row < M) {
                    g_asrc1[row * 2 + head] = o.x + psB[mi];
                    g_adst1[row * 2 + head] = o.y + pdB[mi];
                }
            }
        }
    }
}

__global__ void __launch_bounds__(256, 2)
k_gemm_pre(const float* __restrict__ x, const float* __restrict__ b_pre)
{
    gemm_hf16<0>(x, g_WpHs, g_WpLs, 1, b_pre, g_hpre, nullptr, nullptr, NNODES, HID, DIN);
}

__global__ void __launch_bounds__(256, 2)
k_gemm_h1(const float* __restrict__ a_src1, const float* __restrict__ a_dst1)
{
    gemm_hf16<1>(g_hpre, g_W1Hs, g_W1Ls, 2, nullptr, nullptr, a_src1, a_dst1, NNODES, C1, HID);
}

__device__ __forceinline__ float lrelu(float e) { return e > 0.f ? e : 0.2f * e; }

// ---------------- GAT1 aggregation: bf16 messages, lane owns 8 cols ----------------
__global__ void k_agg1(const float* __restrict__ b1) {
    int node = blockIdx.x * 8 + (threadIdx.x >> 5);
    int lane = threadIdx.x & 31;
    if (lane == 0) g_cnt[node] = 0;   // restore zero-invariant for next call
    int beg = g_off[node], end = g_off[node + 1];
    float2 ad = *(const float2*)&g_adst1[node * 2];

    float m0 = -1e30f, m1 = -1e30f;
    for (int j = beg + lane; j < end; j += 32) {
        int s = g_esrc[j];
        float2 as = *(const float2*)&g_asrc1[s * 2];
        m0 = fmaxf(m0, lrelu(as.x + ad.x));
        m1 = fmaxf(m1, lrelu(as.y + ad.y));
    }
    #pragma unroll
    for (int o = 16; o; o >>= 1) {
        m0 = fmaxf(m0, __shfl_xor_sync(0xffffffffu, m0, o));
        m1 = fmaxf(m1, __shfl_xor_sync(0xffffffffu, m1, o));
    }

    const int head = lane >> 4;
    const float adh = head ? ad.y : ad.x;
    const float mh  = head ? m1 : m0;

    float4 a0 = make_float4(0.f, 0.f, 0.f, 0.f);
    float4 a1 = make_float4(0.f, 0.f, 0.f, 0.f);
    float ssum = 0.f;
    for (int j = beg; j < end; j++) {
        int s = g_esrc[j];
        float2 as = *(const float2*)&g_asrc1[s * 2];
        float p = expf(lrelu((head ? as.y : as.x) + adh) - mh);
        ssum += p;
        uint4 hv = *(const uint4*)&g_h1b[(size_t)s * C1 + lane * 8];
        a0.x += bflowf(hv.x) * p;  a0.y += bfhighf(hv.x) * p;
        a0.z += bflowf(hv.y) * p;  a0.w += bfhighf(hv.y) * p;
        a1.x += bflowf(hv.z) * p;  a1.y += bfhighf(hv.z) * p;
        a1.z += bflowf(hv.w) * p;  a1.w += bfhighf(hv.w) * p;
    }
    float inv = 1.f / (ssum + 1e-16f);
    int c = lane * 8;
    float4 bb0 = *(const float4*)&b1[c];
    float4 bb1 = *(const float4*)&b1[c + 4];
    float4 r0, r1;
    float o;
    o = a0.x * inv + bb0.x; r0.x = (o > 0.f) ? o : expm1f(o);
    o = a0.y * inv + bb0.y; r0.y = (o > 0.f) ? o : expm1f(o);
    o = a0.z * inv + bb0.z; r0.z = (o > 0.f) ? o : expm1f(o);
    o = a0.w * inv + bb0.w; r0.w = (o > 0.f) ? o : expm1f(o);
    o = a1.x * inv + bb1.x; r1.x = (o > 0.f) ? o : expm1f(o);
    o = a1.y * inv + bb1.y; r1.y = (o > 0.f) ? o : expm1f(o);
    o = a1.z * inv + bb1.z; r1.z = (o > 0.f) ? o : expm1f(o);
    o = a1.w * inv + bb1.w; r1.w = (o > 0.f) ? o : expm1f(o);
    *(float4*)&g_h1out[(size_t)node * C1 + c]     = r0;
    *(float4*)&g_h1out[(size_t)node * C1 + c + 4] = r1;
}

// ---------------- layer 2 transform + alpha ----------------
__global__ void k_gemm2(const float* __restrict__ W2, const float* __restrict__ a_src2,
                        const float* __restrict__ a_dst2) {
    __shared__ float sW[C1 * NC];
    __shared__ float sa[NC], sd[NC];
    int tid = threadIdx.x;
    *(float4*)&sW[tid * 4] = *(const float4*)&W2[tid * 4];
    if (tid < NC) { sa[tid] = a_src2[tid]; sd[tid] = a_dst2[tid]; }
    __syncthreads();

    int node = blockIdx.x * 8 + (tid >> 5);
    int lane = tid & 31;
    const float* hrow = &g_h1out[(size_t)node * C1];
    float a0 = 0.f, a1 = 0.f, a2 = 0.f, a3 = 0.f;
    #pragma unroll
    for (int k = 0; k < 8; k++) {
        int c = lane + 32 * k;
        float v = hrow[c];
        a0 += v * sW[c * 4 + 0];
        a1 += v * sW[c * 4 + 1];
        a2 += v * sW[c * 4 + 2];
        a3 += v * sW[c * 4 + 3];
    }
    #pragma unroll
    for (int o = 16; o; o >>= 1) {
        a0 += __shfl_xor_sync(0xffffffffu, a0, o);
        a1 += __shfl_xor_sync(0xffffffffu, a1, o);
        a2 += __shfl_xor_sync(0xffffffffu, a2, o);
        a3 += __shfl_xor_sync(0xffffffffu, a3, o);
    }
    if (lane == 0) {
        g_h2[node * 4 + 0] = a0; g_h2[node * 4 + 1] = a1;
        g_h2[node * 4 + 2] = a2; g_h2[node * 4 + 3] = a3;
        g_asrc2[node] = a0 * sa[0] + a1 * sa[1] + a2 * sa[2] + a3 * sa[3];
        g_adst2[node] = a0 * sd[0] + a1 * sd[1] + a2 * sd[2] + a3 * sd[3];
    }
}

// ---------------- GAT2 aggregation ----------------
__global__ void k_agg2(const float* __restrict__ b2, float* __restrict__ out) {
    int node = blockIdx.x * 8 + (threadIdx.x >> 5);
    int lane = threadIdx.x & 31;
    int beg = g_off[node], end = g_off[node + 1];
    float ad = g_adst2[node];

    float m = -1e30f;
    for (int j = beg + lane; j < end; j += 32)
        m = fmaxf(m, lrelu(g_asrc2[g_esrc[j]] + ad));
    #pragma unroll
    for (int o = 16; o; o >>= 1)
        m = fmaxf(m, __shfl_xor_sync(0xffffffffu, m, o));

    float ss = 0.f, c0 = 0.f, c1 = 0.f, c2 = 0.f, c3 = 0.f;
    for (int j = beg + lane; j < end; j += 32) {
        int s = g_esrc[j];
        float p = expf(lrelu(g_asrc2[s] + ad) - m);
        ss += p;
        float4 h = *(const float4*)&g_h2[s * 4];
        c0 += h.x * p; c1 += h.y * p; c2 += h.z * p; c3 += h.w * p;
    }
    #pragma unroll
    for (int o = 16; o; o >>= 1) {
        ss += __shfl_xor_sync(0xffffffffu, ss, o);
        c0 += __shfl_xor_sync(0xffffffffu, c0, o);
        c1 += __shfl_xor_sync(0xffffffffu, c1, o);
        c2 += __shfl_xor_sync(0xffffffffu, c2, o);
        c3 += __shfl_xor_sync(0xffffffffu, c3, o);
    }
    if (lane == 0) {
        float inv = 1.f / (ss + 1e-16f);
        out[node * 4 + 0] = c0 * inv + b2[0];
        out[node * 4 + 1] = c1 * inv + b2[1];
        out[node * 4 + 2] = c2 * inv + b2[2];
        out[node * 4 + 3] = c3 * inv + b2[3];
    }
}

// ---------------- launch ----------------
extern "C" void kernel_launch(void* const* d_in, const int* in_sizes, int n_in,
                              void* d_out, int out_size) {
    const float* x      = (const float*)d_in[0];
    const int*   ei     = (const int*)d_in[1];
    const float* W_pre  = (const float*)d_in[2];
    const float* b_pre  = (const float*)d_in[3];
    const float* W1     = (const float*)d_in[4];
    const float* a_src1 = (const float*)d_in[5];
    const float* a_dst1 = (const float*)d_in[6];
    const float* b1     = (const float*)d_in[7];
    const float* W2     = (const float*)d_in[8];
    const float* a_src2 = (const float*)d_in[9];
    const float* a_dst2 = (const float*)d_in[10];
    const float* b2     = (const float*)d_in[11];
    float* out = (float*)d_out;

    static cudaStream_t s1 = nullptr;
    static cudaEvent_t eFork = nullptr, eJoin = nullptr;
    if (s1 == nullptr) {
        cudaStreamCreateWithFlags(&s1, cudaStreamNonBlocking);
        cudaEventCreateWithFlags(&eFork, cudaEventDisableTiming);
        cudaEventCreateWithFlags(&eJoin, cudaEventDisableTiming);
    }
    cudaFuncSetAttribute(k_gemm_pre, cudaFuncAttributeMaxDynamicSharedMemorySize, GB_SMEM);
    cudaFuncSetAttribute(k_gemm_h1,  cudaFuncAttributeMaxDynamicSharedMemorySize, GB_SMEM);

    const int NB = (NNODES + 255) / 256;   // 196

    // ---- fork: CSR chain on s1, compute chain on main stream ----
    cudaEventRecord(eFork, 0);
    cudaStreamWaitEvent(s1, eFork, 0);

    k_count<<<(NEDGE + 255) / 256, 256, 0, s1>>>(ei);
    k_scanA<<<NB, 256, 0, s1>>>();
    k_scanB<<<1, 256, 0, s1>>>(NB);
    k_scanC<<<NB, 256, 0, s1>>>();
    k_scatter<<<(NTOT + 255) / 256, 256, 0, s1>>>(ei);
    cudaEventRecord(eJoin, s1);

    // main stream: weights prep, GEMMs (alpha fused into gemm_h1 epilogue)
    k_prepW<<<(WP_CHUNKS + W1_CHUNKS + 255) / 256, 256>>>(W_pre, W1);
    {
        dim3 grid(1, (NNODES + 127) / 128);
        k_gemm_pre<<<grid, 256, GB_SMEM>>>(x, b_pre);
    }
    {
        dim3 grid(2, (NNODES + 127) / 128);
        k_gemm_h1<<<grid, 256, GB_SMEM>>>(a_src1, a_dst1);
    }

    // ---- join: aggregation needs the CSR ----
    cudaStreamWaitEvent(0, eJoin, 0);
    k_agg1<<<NNODES / 8, 256>>>(b1);
    k_gemm2<<<NNODES / 8, 256>>>(W2, a_src2, a_dst2);
    k_agg2<<<NNODES / 8, 256>>>(b2, out);
}

// round 17
// speedup vs baseline: 3.3740x; 1.0510x over previous
#include <cuda_runtime.h>
#include <cuda_bf16.h>
#include <cuda_fp16.h>
#include <math.h>
#include <stdint.h>

#define NNODES 50000
#define NEDGE  800000
#define NTOT   (NEDGE + NNODES)
#define DIN    1024
#define HID    128
#define C1     256   // HEADS*HID
#define NC     4

// ---------------- scratch (device globals; no allocation allowed) ----------------
__device__ float g_hpre[(size_t)NNODES * HID];
__device__ __align__(16) __nv_bfloat16 g_h1b[(size_t)NNODES * C1];  // bf16 messages
__device__ float g_h1out[(size_t)NNODES * C1];
__device__ float g_asrc1[NNODES * 2];   // written (plain stores) by gemm_h1 epilogue
__device__ float g_adst1[NNODES * 2];
__device__ float g_h2[NNODES * NC];
__device__ float g_asrc2[NNODES];
__device__ float g_adst2[NNODES];
__device__ int   g_cnt[NNODES];     // invariant: zero at kernel_launch entry
__device__ int   g_off[NNODES + 1];
__device__ int   g_esrc[NTOT];
__device__ int   g_bsum[256];
// pre-swizzled FP16 weight plane, tile layout: chunk q=(t*CB+cb)*512 + r*16 + d
#define WP_CHUNKS 16384   // (DIN/32)*1*512
#define W1_CHUNKS 4096    // (HID/32)*2*512
__device__ uint4 g_WpHs[WP_CHUNKS];
__device__ uint4 g_W1Hs[W1_CHUNKS];

__device__ __forceinline__ int clampN(int v) {
    return v < 0 ? 0 : (v >= NNODES ? NNODES - 1 : v);
}

// ---------------- CSR build ----------------
__global__ void k_count(const int* __restrict__ ei) {
    int e = blockIdx.x * blockDim.x + threadIdx.x;
    if (e < NEDGE) {
        int dst = clampN(ei[NEDGE + e]);
        atomicAdd(&g_cnt[dst], 1);
    }
}

__global__ void k_scanA() {
    __shared__ int wsum[8];
    int i = blockIdx.x * 256 + threadIdx.x;
    int lane = threadIdx.x & 31, w = threadIdx.x >> 5;
    int v = (i < NNODES) ? (g_cnt[i] + 1) : 0;   // +1 = self-loop
    if (i < NNODES) g_cnt[i] = 0;                // becomes scatter cursor
    int x = v;
    #pragma unroll
    for (int o = 1; o < 32; o <<= 1) {
        int t = __shfl_up_sync(0xffffffffu, x, o);
        if (lane >= o) x += t;
    }
    if (lane == 31) wsum[w] = x;
    __syncthreads();
    if (w == 0 && lane < 8) {
        int s = wsum[lane];
        #pragma unroll
        for (int o = 1; o < 8; o <<= 1) {
            int t = __shfl_up_sync(0xffu, s, o);
            if (lane >= o) s += t;
        }
        wsum[lane] = s;
    }
    __syncthreads();
    int pre = (w > 0) ? wsum[w - 1] : 0;
    if (i < NNODES) g_off[i] = pre + x - v;
    if (threadIdx.x == 255) g_bsum[blockIdx.x] = pre + x;
}

__global__ void k_scanB(int nblk) {
    __shared__ int wsum[8];
    int t = threadIdx.x;
    int lane = t & 31, w = t >> 5;
    int v = (t < nblk) ? g_bsum[t] : 0;
    int x = v;
    #pragma unroll
    for (int o = 1; o < 32; o <<= 1) {
        int q = __shfl_up_sync(0xffffffffu, x, o);
        if (lane >= o) x += q;
    }
    if (lane == 31) wsum[w] = x;
    __syncthreads();
    if (w == 0 && lane < 8) {
        int s = wsum[lane];
        #pragma unroll
        for (int o = 1; o < 8; o <<= 1) {
            int q = __shfl_up_sync(0xffu, s, o);
            if (lane >= o) s += q;
        }
        wsum[lane] = s;
    }
    __syncthreads();
    int pre = (w > 0) ? wsum[w - 1] : 0;
    if (t < nblk) g_bsum[t] = pre + x - v;
    if (t == 255) g_off[NNODES] = pre + x;
}

__global__ void k_scanC() {
    int i = blockIdx.x * 256 + threadIdx.x;
    if (i < NNODES) g_off[i] += g_bsum[blockIdx.x];
}

__global__ void k_scatter(const int* __restrict__ ei) {
    int e = blockIdx.x * blockDim.x + threadIdx.x;
    if (e >= NTOT) return;
    int src, dst;
    if (e < NEDGE) { src = clampN(ei[e]); dst = clampN(ei[NEDGE + e]); }
    else           { src = e - NEDGE; dst = src; }
    int pos = g_off[dst] + atomicAdd(&g_cnt[dst], 1);
    g_esrc[pos] = src;
}

// ================= pack helpers =================
__device__ __forceinline__ uint32_t packbf(float v0, float v1) {
    uint32_t r;
    asm("cvt.rn.bf16x2.f32 %0, %1, %2;" : "=r"(r) : "f"(v1), "f"(v0));
    return r;
}
__device__ __forceinline__ float bflowf(uint32_t p)  { return __uint_as_float(p << 16); }
__device__ __forceinline__ float bfhighf(uint32_t p) { return __uint_as_float(p & 0xffff0000u); }

__device__ __forceinline__ uint32_t packhf(float v0, float v1) {
    uint32_t r;
    asm("cvt.rn.f16x2.f32 %0, %1, %2;" : "=r"(r) : "f"(v1), "f"(v0));
    return r;
}

// weight fp16 conversion + pre-swizzle into tile layout (once per run)
// dest chunk q -> (tile tcb = q>>9, r = (q>>4)&31, d = q&15); src chunk c = (d&8)|((d^r)&7)
__global__ void k_prepW(const float* __restrict__ Wp, const float* __restrict__ W1) {
    int q = blockIdx.x * blockDim.x + threadIdx.x;
    const float* src;
    uint4* dh;
    int idx;
    if (q < WP_CHUNKS) {
        int t = q >> 9, rr = q & 511, r = rr >> 4, d = rr & 15;
        int c = (d & 8) | ((d ^ r) & 7);
        src = Wp + (size_t)(t * 32 + r) * HID + c * 8;
        dh = g_WpHs; idx = q;
    } else {
        int j = q - WP_CHUNKS;
        if (j >= W1_CHUNKS) return;
        int tcb = j >> 9, rr = j & 511, r = rr >> 4, d = rr & 15;
        int t = tcb >> 1, cb = tcb & 1;
        int c = (d & 8) | ((d ^ r) & 7);
        src = W1 + (size_t)(t * 32 + r) * C1 + cb * 128 + c * 8;
        dh = g_W1Hs; idx = j;
    }
    float4 f0 = *(const float4*)src;
    float4 f1 = *(const float4*)(src + 4);
    dh[idx] = make_uint4(packhf(f0.x, f0.y), packhf(f0.z, f0.w),
                         packhf(f1.x, f1.y), packhf(f1.z, f1.w));
}

// ================= mma.sync fp16 1-term GEMM, double-buffered, cp.async B =====
__device__ __forceinline__ void ldsm4(uint32_t addr, uint32_t* r) {
    asm volatile("ldmatrix.sync.aligned.m8n8.x4.shared.b16 {%0,%1,%2,%3},[%4];"
        : "=r"(r[0]), "=r"(r[1]), "=r"(r[2]), "=r"(r[3]) : "r"(addr));
}
__device__ __forceinline__ void ldsm4t(uint32_t addr, uint32_t* r) {
    asm volatile("ldmatrix.sync.aligned.m8n8.x4.trans.shared.b16 {%0,%1,%2,%3},[%4];"
        : "=r"(r[0]), "=r"(r[1]), "=r"(r[2]), "=r"(r[3]) : "r"(addr));
}
__device__ __forceinline__ void mma16816h(float* c, const uint32_t* a, const uint32_t* b) {
    asm volatile(
        "mma.sync.aligned.m16n8k16.row.col.f32.f16.f16.f32 "
        "{%0,%1,%2,%3},{%4,%5,%6,%7},{%8,%9},{%0,%1,%2,%3};"
        : "+f"(c[0]), "+f"(c[1]), "+f"(c[2]), "+f"(c[3])
        : "r"(a[0]), "r"(a[1]), "r"(a[2]), "r"(a[3]), "r"(b[0]), "r"(b[1]));
}
__device__ __forceinline__ void cpa16(uint32_t saddr, const void* g) {
    asm volatile("cp.async.cg.shared.global [%0], [%1], 16;" :: "r"(saddr), "l"(g));
}
__device__ __forceinline__ void cpa_commit() {
    asm volatile("cp.async.commit_group;" ::: "memory");
}
__device__ __forceinline__ void cpa_wait0() {
    asm volatile("cp.async.wait_group 0;" ::: "memory");
}

// smem per buffer (16KB): A 8K | B 8K; 2 buffers = 32KB
#define GB_BUF 16384
#define GB_A   0
#define GB_BHI 8192
#define GB_SMEM (2 * GB_BUF)

// MODE 0: C = fp32, + bias + relu.
// MODE 1: write g_h1b (bf16) + alpha partials via smem two-warp reduction.
template <int MODE>
__device__ __forceinline__ void gemm_hf16(
    const float* __restrict__ A,
    const uint4* __restrict__ BswH, int CB,
    const float* __restrict__ bias, float* __restrict__ C,
    const float* __restrict__ asrc, const float* __restrict__ adst,
    int M, int N, int K)
{
    extern __shared__ __align__(16) char dsm[];
    const uint32_t sb = (uint32_t)__cvta_generic_to_shared(dsm);

    const int tid = threadIdx.x;
    const int lane = tid & 31;
    const int warp = tid >> 5;
    const int warpM = (warp & 3) * 32;
    const int warpN = (warp >> 2) * 64;
    const int rowBase = blockIdx.y * 128;
    const int colBase = blockIdx.x * 128;
    const int cb = blockIdx.x;

    const int am = tid >> 1;
    const int akoff = (tid & 1) * 16;
    const int gm = rowBase + am;
    const bool aValid = gm < M;

    float acc[2][8][4];
    #pragma unroll
    for (int mi = 0; mi < 2; mi++)
        #pragma unroll
        for (int j = 0; j < 8; j++)
            #pragma unroll
            for (int q = 0; q < 4; q++) acc[mi][j][q] = 0.f;

    const int niter = K >> 5;
    float4 ra[4];

    // ---- prologue: tile 0 ----
    {
        if (aValid) {
            const float4* p = (const float4*)(A + (size_t)gm * K + akoff);
            ra[0] = p[0]; ra[1] = p[1]; ra[2] = p[2]; ra[3] = p[3];
        } else {
            ra[0] = ra[1] = ra[2] = ra[3] = make_float4(0.f, 0.f, 0.f, 0.f);
        }
        size_t bbase = (size_t)cb * 512;
        cpa16(sb + GB_BHI + tid * 16,        BswH + bbase + tid);
        cpa16(sb + GB_BHI + 4096 + tid * 16, BswH + bbase + tid + 256);
        cpa_commit();
        #pragma unroll
        for (int cc = 0; cc < 2; cc++) {
            int c = (tid & 1) * 2 + cc;
            float4 f0 = ra[cc * 2], f1 = ra[cc * 2 + 1];
            int p = c ^ ((am >> 1) & 3);
            *(uint4*)(dsm + GB_A + am * 64 + p * 16) =
                make_uint4(packhf(f0.x, f0.y), packhf(f0.z, f0.w),
                           packhf(f1.x, f1.y), packhf(f1.z, f1.w));
        }
        cpa_wait0();
    }
    __syncthreads();

    for (int it = 0; it < niter; it++) {
        const uint32_t bufA   = sb + (it & 1) * GB_BUF + GB_A;
        const uint32_t bufB_h = sb + (it & 1) * GB_BUF + GB_BHI;
        const uint32_t nxt = sb + ((it + 1) & 1) * GB_BUF;

        if (it + 1 < niter) {
            int kt = (it + 1) * 32;
            if (aValid) {
                const float4* p = (const float4*)(A + (size_t)gm * K + kt + akoff);
                ra[0] = p[0]; ra[1] = p[1]; ra[2] = p[2]; ra[3] = p[3];
            }
            size_t bbase = (size_t)((it + 1) * CB + cb) * 512;
            cpa16(nxt + GB_BHI + tid * 16,        BswH + bbase + tid);
            cpa16(nxt + GB_BHI + 4096 + tid * 16, BswH + bbase + tid + 256);
            cpa_commit();
        }

        // mma over current buffer: A * Bh
        #pragma unroll
        for (int s = 0; s < 2; s++) {
            uint32_t Ah[2][4];
            #pragma unroll
            for (int mi = 0; mi < 2; mi++) {
                int m0 = warpM + mi * 16 + (lane & 15);
                int c = 2 * s + (lane >> 4);
                int p = c ^ ((m0 >> 1) & 3);
                ldsm4(bufA + (uint32_t)(m0 * 64 + p * 16), Ah[mi]);
            }
            uint32_t Bhf[4][4];
            #pragma unroll
            for (int nb = 0; nb < 4; nb++) {
                int k = s * 16 + (lane & 15);
                int nc = (warpN >> 3) + nb * 2 + (lane >> 4);
                int p = nc ^ (k & 7);
                ldsm4t(bufB_h + (uint32_t)(k * 256 + p * 16), Bhf[nb]);
            }
            #pragma unroll
            for (int mi = 0; mi < 2; mi++)
                #pragma unroll
                for (int nb = 0; nb < 4; nb++)
                    #pragma unroll
                    for (int h = 0; h < 2; h++)
                        mma16816h(acc[mi][nb * 2 + h], Ah[mi], &Bhf[nb][h * 2]);
        }

        if (it + 1 < niter) {
            char* nb = dsm + ((it + 1) & 1) * GB_BUF;
            #pragma unroll
            for (int cc = 0; cc < 2; cc++) {
                int c = (tid & 1) * 2 + cc;
                float4 f0 = ra[cc * 2], f1 = ra[cc * 2 + 1];
                int p = c ^ ((am >> 1) & 3);
                *(uint4*)(nb + GB_A + am * 64 + p * 16) =
                    make_uint4(packhf(f0.x, f0.y), packhf(f0.z, f0.w),
                               packhf(f1.x, f1.y), packhf(f1.z, f1.w));
            }
            cpa_wait0();
        }
        __syncthreads();
    }

    // ---- epilogue ----
    if (MODE == 0) {
        #pragma unroll
        for (int mi = 0; mi < 2; mi++) {
            #pragma unroll
            for (int j = 0; j < 8; j++) {
                float* c = acc[mi][j];
                int gmr = rowBase + warpM + mi * 16 + (lane >> 2);
                int gn = colBase + warpN + j * 8 + (lane & 3) * 2;
                float b0 = bias[gn], b1 = bias[gn + 1];
                float v0 = fmaxf(c[0] + b0, 0.f), v1 = fmaxf(c[1] + b1, 0.f);
                float v2 = fmaxf(c[2] + b0, 0.f), v3 = fmaxf(c[3] + b1, 0.f);
                if (gmr < M)     *(float2*)&C[(size_t)gmr * N + gn]       = make_float2(v0, v1);
                if (gmr + 8 < M) *(float2*)&C[(size_t)(gmr + 8) * N + gn] = make_float2(v2, v3);
            }
        }
    } else {
        // bf16 message write + fused alpha dot; two-warp smem reduction, no atomics
        const int head = colBase >> 7;
        float psA[2], pdA[2], psB[2], pdB[2];
        #pragma unroll
        for (int mi = 0; mi < 2; mi++) {
            int gmr = rowBase + warpM + mi * 16 + (lane >> 2);
            float ps0 = 0.f, pd0 = 0.f, ps1 = 0.f, pd1 = 0.f;
            #pragma unroll
            for (int j = 0; j < 8; j++) {
                float* c = acc[mi][j];
                int gn = colBase + warpN + j * 8 + (lane & 3) * 2;
                float as0 = __ldg(&asrc[gn]), as1 = __ldg(&asrc[gn + 1]);
                float ad0 = __ldg(&adst[gn]), ad1 = __ldg(&adst[gn + 1]);
                ps0 += c[0] * as0 + c[1] * as1;
                pd0 += c[0] * ad0 + c[1] * ad1;
                ps1 += c[2] * as0 + c[3] * as1;
                pd1 += c[2] * ad0 + c[3] * ad1;
                if (gmr < M)
                    *(uint32_t*)&g_h1b[(size_t)gmr * C1 + gn] = packbf(c[0], c[1]);
                if (gmr + 8 < M)
                    *(uint32_t*)&g_h1b[(size_t)(gmr + 8) * C1 + gn] = packbf(c[2], c[3]);
            }
            #pragma unroll
            for (int o = 1; o < 4; o <<= 1) {
                ps0 += __shfl_xor_sync(0xffffffffu, ps0, o);
                pd0 += __shfl_xor_sync(0xffffffffu, pd0, o);
                ps1 += __shfl_xor_sync(0xffffffffu, ps1, o);
                pd1 += __shfl_xor_sync(0xffffffffu, pd1, o);
            }
            psA[mi] = ps0; pdA[mi] = pd0; psB[mi] = ps1; pdB[mi] = pd1;
        }
        float2* sred = (float2*)dsm;   // 128 rows x float2 = 1KB (main loop done)
        if (warp < 4 && (lane & 3) == 0) {
            #pragma unroll
            for (int mi = 0; mi < 2; mi++) {
                int rloc = warpM + mi * 16 + (lane >> 2);
                sred[rloc]     = make_float2(psA[mi], pdA[mi]);
                sred[rloc + 8] = make_float2(psB[mi], pdB[mi]);
            }
        }
        __syncthreads();
        if (warp >= 4 && (lane & 3) == 0) {
            #pragma unroll
            for (int mi = 0; mi < 2; mi++) {
                int rloc = warpM + mi * 16 + (lane >> 2);
                float2 o = sred[rloc];
                int row = rowBase + rloc;
                if (row < M) {
                    g_asrc1[row * 2 + head] = o.x + psA[mi];
                    g_adst1[row * 2 + head] = o.y + pdA[mi];
                }
                o = sred[rloc + 8];
                row += 8;
                if (row < M) {
                    g_asrc1[row * 2 + head] = o.x + psB[mi];
                    g_adst1[row * 2 + head] = o.y + pdB[mi];
                }
            }
        }
    }
}

__global__ void __launch_bounds__(256, 2)
k_gemm_pre(const float* __restrict__ x, const float* __restrict__ b_pre)
{
    gemm_hf16<0>(x, g_WpHs, 1, b_pre, g_hpre, nullptr, nullptr, NNODES, HID, DIN);
}

__global__ void __launch_bounds__(256, 2)
k_gemm_h1(const float* __restrict__ a_src1, const float* __restrict__ a_dst1)
{
    gemm_hf16<1>(g_hpre, g_W1Hs, 2, nullptr, nullptr, a_src1, a_dst1, NNODES, C1, HID);
}

__device__ __forceinline__ float lrelu(float e) { return e > 0.f ? e : 0.2f * e; }

// ---------------- GAT1 aggregation: bf16 messages, lane owns 8 cols ----------------
__global__ void k_agg1(const float* __restrict__ b1) {
    int node = blockIdx.x * 8 + (threadIdx.x >> 5);
    int lane = threadIdx.x & 31;
    if (lane == 0) g_cnt[node] = 0;   // restore zero-invariant for next call
    int beg = g_off[node], end = g_off[node + 1];
    float2 ad = *(const float2*)&g_adst1[node * 2];

    float m0 = -1e30f, m1 = -1e30f;
    for (int j = beg + lane; j < end; j += 32) {
        int s = g_esrc[j];
        float2 as = *(const float2*)&g_asrc1[s * 2];
        m0 = fmaxf(m0, lrelu(as.x + ad.x));
        m1 = fmaxf(m1, lrelu(as.y + ad.y));
    }
    #pragma unroll
    for (int o = 16; o; o >>= 1) {
        m0 = fmaxf(m0, __shfl_xor_sync(0xffffffffu, m0, o));
        m1 = fmaxf(m1, __shfl_xor_sync(0xffffffffu, m1, o));
    }

    const int head = lane >> 4;
    const float adh = head ? ad.y : ad.x;
    const float mh  = head ? m1 : m0;

    float4 a0 = make_float4(0.f, 0.f, 0.f, 0.f);
    float4 a1 = make_float4(0.f, 0.f, 0.f, 0.f);
    float ssum = 0.f;
    for (int j = beg; j < end; j++) {
        int s = g_esrc[j];
        float2 as = *(const float2*)&g_asrc1[s * 2];
        float p = expf(lrelu((head ? as.y : as.x) + adh) - mh);
        ssum += p;
        uint4 hv = *(const uint4*)&g_h1b[(size_t)s * C1 + lane * 8];
        a0.x += bflowf(hv.x) * p;  a0.y += bfhighf(hv.x) * p;
        a0.z += bflowf(hv.y) * p;  a0.w += bfhighf(hv.y) * p;
        a1.x += bflowf(hv.z) * p;  a1.y += bfhighf(hv.z) * p;
        a1.z += bflowf(hv.w) * p;  a1.w += bfhighf(hv.w) * p;
    }
    float inv = 1.f / (ssum + 1e-16f);
    int c = lane * 8;
    float4 bb0 = *(const float4*)&b1[c];
    float4 bb1 = *(const float4*)&b1[c + 4];
    float4 r0, r1;
    float o;
    o = a0.x * inv + bb0.x; r0.x = (o > 0.f) ? o : expm1f(o);
    o = a0.y * inv + bb0.y; r0.y = (o > 0.f) ? o : expm1f(o);
    o = a0.z * inv + bb0.z; r0.z = (o > 0.f) ? o : expm1f(o);
    o = a0.w * inv + bb0.w; r0.w = (o > 0.f) ? o : expm1f(o);
    o = a1.x * inv + bb1.x; r1.x = (o > 0.f) ? o : expm1f(o);
    o = a1.y * inv + bb1.y; r1.y = (o > 0.f) ? o : expm1f(o);
    o = a1.z * inv + bb1.z; r1.z = (o > 0.f) ? o : expm1f(o);
    o = a1.w * inv + bb1.w; r1.w = (o > 0.f) ? o : expm1f(o);
    *(float4*)&g_h1out[(size_t)node * C1 + c]     = r0;
    *(float4*)&g_h1out[(size_t)node * C1 + c + 4] = r1;
}

// ---------------- layer 2 transform + alpha ----------------
__global__ void k_gemm2(const float* __restrict__ W2, const float* __restrict__ a_src2,
                        const float* __restrict__ a_dst2) {
    __shared__ float sW[C1 * NC];
    __shared__ float sa[NC], sd[NC];
    int tid = threadIdx.x;
    *(float4*)&sW[tid * 4] = *(const float4*)&W2[tid * 4];
    if (tid < NC) { sa[tid] = a_src2[tid]; sd[tid] = a_dst2[tid]; }
    __syncthreads();

    int node = blockIdx.x * 8 + (tid >> 5);
    int lane = tid & 31;
    const float* hrow = &g_h1out[(size_t)node * C1];
    float a0 = 0.f, a1 = 0.f, a2 = 0.f, a3 = 0.f;
    #pragma unroll
    for (int k = 0; k < 8; k++) {
        int c = lane + 32 * k;
        float v = hrow[c];
        a0 += v * sW[c * 4 + 0];
        a1 += v * sW[c * 4 + 1];
        a2 += v * sW[c * 4 + 2];
        a3 += v * sW[c * 4 + 3];
    }
    #pragma unroll
    for (int o = 16; o; o >>= 1) {
        a0 += __shfl_xor_sync(0xffffffffu, a0, o);
        a1 += __shfl_xor_sync(0xffffffffu, a1, o);
        a2 += __shfl_xor_sync(0xffffffffu, a2, o);
        a3 += __shfl_xor_sync(0xffffffffu, a3, o);
    }
    if (lane == 0) {
        g_h2[node * 4 + 0] = a0; g_h2[node * 4 + 1] = a1;
        g_h2[node * 4 + 2] = a2; g_h2[node * 4 + 3] = a3;
        g_asrc2[node] = a0 * sa[0] + a1 * sa[1] + a2 * sa[2] + a3 * sa[3];
        g_adst2[node] = a0 * sd[0] + a1 * sd[1] + a2 * sd[2] + a3 * sd[3];
    }
}

// ---------------- GAT2 aggregation ----------------
__global__ void k_agg2(const float* __restrict__ b2, float* __restrict__ out) {
    int node = blockIdx.x * 8 + (threadIdx.x >> 5);
    int lane = threadIdx.x & 31;
    int beg = g_off[node], end = g_off[node + 1];
    float ad = g_adst2[node];

    float m = -1e30f;
    for (int j = beg + lane; j < end; j += 32)
        m = fmaxf(m, lrelu(g_asrc2[g_esrc[j]] + ad));
    #pragma unroll
    for (int o = 16; o; o >>= 1)
        m = fmaxf(m, __shfl_xor_sync(0xffffffffu, m, o));

    float ss = 0.f, c0 = 0.f, c1 = 0.f, c2 = 0.f, c3 = 0.f;
    for (int j = beg + lane; j < end; j += 32) {
        int s = g_esrc[j];
        float p = expf(lrelu(g_asrc2[s] + ad) - m);
        ss += p;
        float4 h = *(const float4*)&g_h2[s * 4];
        c0 += h.x * p; c1 += h.y * p; c2 += h.z * p; c3 += h.w * p;
    }
    #pragma unroll
    for (int o = 16; o; o >>= 1) {
        ss += __shfl_xor_sync(0xffffffffu, ss, o);
        c0 += __shfl_xor_sync(0xffffffffu, c0, o);
        c1 += __shfl_xor_sync(0xffffffffu, c1, o);
        c2 += __shfl_xor_sync(0xffffffffu, c2, o);
        c3 += __shfl_xor_sync(0xffffffffu, c3, o);
    }
    if (lane == 0) {
        float inv = 1.f / (ss + 1e-16f);
        out[node * 4 + 0] = c0 * inv + b2[0];
        out[node * 4 + 1] = c1 * inv + b2[1];
        out[node * 4 + 2] = c2 * inv + b2[2];
        out[node * 4 + 3] = c3 * inv + b2[3];
    }
}

// ---------------- launch ----------------
extern "C" void kernel_launch(void* const* d_in, const int* in_sizes, int n_in,
                              void* d_out, int out_size) {
    const float* x      = (const float*)d_in[0];
    const int*   ei     = (const int*)d_in[1];
    const float* W_pre  = (const float*)d_in[2];
    const float* b_pre  = (const float*)d_in[3];
    const float* W1     = (const float*)d_in[4];
    const float* a_src1 = (const float*)d_in[5];
    const float* a_dst1 = (const float*)d_in[6];
    const float* b1     = (const float*)d_in[7];
    const float* W2     = (const float*)d_in[8];
    const float* a_src2 = (const float*)d_in[9];
    const float* a_dst2 = (const float*)d_in[10];
    const float* b2     = (const float*)d_in[11];
    float* out = (float*)d_out;

    static cudaStream_t s1 = nullptr;
    static cudaEvent_t eFork = nullptr, eJoin = nullptr;
    if (s1 == nullptr) {
        cudaStreamCreateWithFlags(&s1, cudaStreamNonBlocking);
        cudaEventCreateWithFlags(&eFork, cudaEventDisableTiming);
        cudaEventCreateWithFlags(&eJoin, cudaEventDisableTiming);
    }
    cudaFuncSetAttribute(k_gemm_pre, cudaFuncAttributeMaxDynamicSharedMemorySize, GB_SMEM);
    cudaFuncSetAttribute(k_gemm_h1,  cudaFuncAttributeMaxDynamicSharedMemorySize, GB_SMEM);

    const int NB = (NNODES + 255) / 256;   // 196

    // ---- fork: CSR chain on s1, compute chain on main stream ----
    cudaEventRecord(eFork, 0);
    cudaStreamWaitEvent(s1, eFork, 0);

    k_count<<<(NEDGE + 255) / 256, 256, 0, s1>>>(ei);
    k_scanA<<<NB, 256, 0, s1>>>();
    k_scanB<<<1, 256, 0, s1>>>(NB);
    k_scanC<<<NB, 256, 0, s1>>>();
    k_scatter<<<(NTOT + 255) / 256, 256, 0, s1>>>(ei);
    cudaEventRecord(eJoin, s1);

    // main stream: weights prep, GEMMs (alpha fused into gemm_h1 epilogue)
    k_prepW<<<(WP_CHUNKS + W1_CHUNKS + 255) / 256, 256>>>(W_pre, W1);
    {
        dim3 grid(1, (NNODES + 127) / 128);
        k_gemm_pre<<<grid, 256, GB_SMEM>>>(x, b_pre);
    }
    {
        dim3 grid(2, (NNODES + 127) / 128);
        k_gemm_h1<<<grid, 256, GB_SMEM>>>(a_src1, a_dst1);
    }

    // ---- join: aggregation needs the CSR ----
    cudaStreamWaitEvent(0, eJoin, 0);
    k_agg1<<<NNODES / 8, 256>>>(b1);
    k_gemm2<<<NNODES / 8, 256>>>(W2, a_src2, a_dst2);
    k_agg2<<<NNODES / 8, 256>>>(b2, out);
}